// round 1
// baseline (speedup 1.0000x reference)
#include <cuda_runtime.h>
#include <math.h>

#define N_RES 320
#define CZ 128
#define NH 4
#define HD 32
#define NN (N_RES*N_RES)   /* 102400 */

// ---------------- scratch (static device globals; no allocation) ----------------
__device__ float g_pair_ln[(size_t)NN*CZ];   // 52.4 MB
__device__ float g_qkvg[(size_t)NN*512];     // 209.7 MB : [row][kind*128 + h*32 + d], kind=q,k,v,g
__device__ float g_nb[(size_t)NH*NN];        // 1.6 MB   : [h][q*320+k]
__device__ float g_wa[(size_t)NN*CZ];        // 52.4 MB  : weighted_avg [row][h*32+d]

// ---------------- K1: LayerNorm(pair) + LayerNorm(affine) + nonbatched bias ----
__global__ void k1_ln_nb(const float* __restrict__ pair, const float* __restrict__ affine,
                         const float* __restrict__ pls, const float* __restrict__ plo,
                         const float* __restrict__ als, const float* __restrict__ alo,
                         const float* __restrict__ f2d) {
  int row = blockIdx.x;
  int t = threadIdx.x, w = t >> 5, l = t & 31;
  __shared__ float sh[16];
  size_t base = (size_t)row * CZ + t;

  float x = pair[base];
  float s = x, s2 = x * x;
  #pragma unroll
  for (int o = 16; o; o >>= 1) { s += __shfl_xor_sync(~0u, s, o); s2 += __shfl_xor_sync(~0u, s2, o); }
  if (l == 0) { sh[w] = s; sh[4 + w] = s2; }
  __syncthreads();
  float sum  = sh[0] + sh[1] + sh[2] + sh[3];
  float sum2 = sh[4] + sh[5] + sh[6] + sh[7];
  float mean = sum * (1.f / CZ);
  float var  = sum2 * (1.f / CZ) - mean * mean;
  float ln = (x - mean) * rsqrtf(var + 1e-5f) * pls[t] + plo[t];
  g_pair_ln[base] = ln;

  float a = affine[base];
  s = a; s2 = a * a;
  #pragma unroll
  for (int o = 16; o; o >>= 1) { s += __shfl_xor_sync(~0u, s, o); s2 += __shfl_xor_sync(~0u, s2, o); }
  __syncthreads();
  if (l == 0) { sh[w] = s; sh[4 + w] = s2; }
  __syncthreads();
  sum  = sh[0] + sh[1] + sh[2] + sh[3];
  sum2 = sh[4] + sh[5] + sh[6] + sh[7];
  mean = sum * (1.f / CZ);
  var  = sum2 * (1.f / CZ) - mean * mean;
  float aln = (a - mean) * rsqrtf(var + 1e-5f) * als[t] + alo[t];

  // nonbatched_bias[h, row] = sum_c aln[c] * f2d[c,h]
  float p0 = aln * f2d[t * 4 + 0];
  float p1 = aln * f2d[t * 4 + 1];
  float p2 = aln * f2d[t * 4 + 2];
  float p3 = aln * f2d[t * 4 + 3];
  #pragma unroll
  for (int o = 16; o; o >>= 1) {
    p0 += __shfl_xor_sync(~0u, p0, o);
    p1 += __shfl_xor_sync(~0u, p1, o);
    p2 += __shfl_xor_sync(~0u, p2, o);
    p3 += __shfl_xor_sync(~0u, p3, o);
  }
  __syncthreads();
  if (l == 0) { sh[w*4+0] = p0; sh[w*4+1] = p1; sh[w*4+2] = p2; sh[w*4+3] = p3; }
  __syncthreads();
  if (t < 4) {
    g_nb[(size_t)t * NN + row] = sh[0*4+t] + sh[1*4+t] + sh[2*4+t] + sh[3*4+t];
  }
}

// ---------------- K2: QKVG projection GEMM [102400x128] x [128x512] -------------
// grid (800, 4); blockIdx.y selects which weight matrix (q,k,v,g); 128x128 tile, 8x8/thread.
__global__ __launch_bounds__(256) void k2_qkvg(const float* __restrict__ qw, const float* __restrict__ kw,
                                               const float* __restrict__ vw, const float* __restrict__ gw) {
  __shared__ float As[16][132];
  __shared__ float Ws[16][132];
  int tid = threadIdx.x;
  int tx = tid & 15, ty = tid >> 4;
  int rowBase = blockIdx.x * 128;
  const float* W = (blockIdx.y == 0) ? qw : (blockIdx.y == 1) ? kw : (blockIdx.y == 2) ? vw : gw;

  float acc[8][8];
  #pragma unroll
  for (int i = 0; i < 8; i++)
    #pragma unroll
    for (int j = 0; j < 8; j++) acc[i][j] = 0.f;

  for (int kc = 0; kc < 128; kc += 16) {
    #pragma unroll
    for (int i = 0; i < 8; i++) {
      int e = tid + i * 256;
      int m = e >> 4, kk = e & 15;
      As[kk][m] = g_pair_ln[(size_t)(rowBase + m) * CZ + kc + kk];
    }
    #pragma unroll
    for (int i = 0; i < 8; i++) {
      int e = tid + i * 256;
      int kk = e >> 7, j = e & 127;
      Ws[kk][j] = W[(kc + kk) * CZ + j];
    }
    __syncthreads();
    #pragma unroll
    for (int kk = 0; kk < 16; kk++) {
      float4 a0 = *(const float4*)&As[kk][ty * 4];
      float4 a1 = *(const float4*)&As[kk][64 + ty * 4];
      float4 b0 = *(const float4*)&Ws[kk][tx * 4];
      float4 b1 = *(const float4*)&Ws[kk][64 + tx * 4];
      float av[8] = {a0.x, a0.y, a0.z, a0.w, a1.x, a1.y, a1.z, a1.w};
      float bv[8] = {b0.x, b0.y, b0.z, b0.w, b1.x, b1.y, b1.z, b1.w};
      #pragma unroll
      for (int i = 0; i < 8; i++)
        #pragma unroll
        for (int j = 0; j < 8; j++) acc[i][j] += av[i] * bv[j];
    }
    __syncthreads();
  }
  int colBase = blockIdx.y * 128;
  #pragma unroll
  for (int i = 0; i < 8; i++) {
    int m = rowBase + ((i < 4) ? (ty * 4 + i) : (64 + ty * 4 + (i - 4)));
    float4 c0 = make_float4(acc[i][0], acc[i][1], acc[i][2], acc[i][3]);
    float4 c1 = make_float4(acc[i][4], acc[i][5], acc[i][6], acc[i][7]);
    *(float4*)&g_qkvg[(size_t)m * 512 + colBase + tx * 4] = c0;
    *(float4*)&g_qkvg[(size_t)m * 512 + colBase + 64 + tx * 4] = c1;
  }
}

// ---------------- K3: attention per (b,h) ---------------------------------------
// grid (4, 320); 256 threads; dynamic smem: K(320x33) V(320x32) q(8x4x32) w(8x4x320) bias(320)
__global__ __launch_bounds__(256) void k3_attn(const float* __restrict__ mask) {
  extern __shared__ float sm[];
  float* Ks     = sm;                     // 320*33 = 10560
  float* Vs     = Ks + 320 * 33;          // 320*32 = 10240
  float* qs     = Vs + 320 * 32;          // 8*4*32 = 1024
  float* ws     = qs + 8 * 4 * 32;        // 8*4*320 = 10240
  float* bias_s = ws + 8 * 4 * 320;       // 320

  int h = blockIdx.x, b = blockIdx.y;
  int t = threadIdx.x, w = t >> 5, l = t & 31;

  for (int e = t; e < 320 * 32; e += 256) {
    int k = e >> 5, c = e & 31;
    size_t rbase = (size_t)(b * 320 + k) * 512 + h * 32;
    Ks[k * 33 + c] = g_qkvg[rbase + 128 + c];
    Vs[e]          = g_qkvg[rbase + 256 + c];
  }
  for (int e = t; e < 320; e += 256) bias_s[e] = 1e9f * (mask[b * 320 + e] - 1.f);
  __syncthreads();

  const float scl = 0.17677669529663687f;  // 32^-0.5
  for (int it = 0; it < 10; it++) {
    int q0 = it * 32 + w * 4;
    #pragma unroll
    for (int r = 0; r < 4; r++)
      qs[(w * 4 + r) * 32 + l] = g_qkvg[(size_t)(b * 320 + q0 + r) * 512 + h * 32 + l];
    __syncwarp();

    float lg[4][10];
    #pragma unroll
    for (int r = 0; r < 4; r++)
      #pragma unroll
      for (int tt = 0; tt < 10; tt++) lg[r][tt] = 0.f;

    for (int c = 0; c < 32; c++) {
      float qv0 = qs[(w * 4 + 0) * 32 + c];
      float qv1 = qs[(w * 4 + 1) * 32 + c];
      float qv2 = qs[(w * 4 + 2) * 32 + c];
      float qv3 = qs[(w * 4 + 3) * 32 + c];
      #pragma unroll
      for (int tt = 0; tt < 10; tt++) {
        float kv = Ks[(tt * 32 + l) * 33 + c];
        lg[0][tt] += qv0 * kv;
        lg[1][tt] += qv1 * kv;
        lg[2][tt] += qv2 * kv;
        lg[3][tt] += qv3 * kv;
      }
    }

    #pragma unroll
    for (int r = 0; r < 4; r++) {
      int qrow = q0 + r;
      const float* nbrow = g_nb + (size_t)h * NN + (size_t)qrow * 320;
      float lv[10];
      float mx = -3.0e38f;
      #pragma unroll
      for (int tt = 0; tt < 10; tt++) {
        int k = tt * 32 + l;
        lv[tt] = lg[r][tt] * scl + bias_s[k] + __ldg(nbrow + k);
        mx = fmaxf(mx, lv[tt]);
      }
      #pragma unroll
      for (int o = 16; o; o >>= 1) mx = fmaxf(mx, __shfl_xor_sync(~0u, mx, o));
      float ssum = 0.f;
      #pragma unroll
      for (int tt = 0; tt < 10; tt++) { lv[tt] = __expf(lv[tt] - mx); ssum += lv[tt]; }
      #pragma unroll
      for (int o = 16; o; o >>= 1) ssum += __shfl_xor_sync(~0u, ssum, o);
      float inv = 1.f / ssum;
      #pragma unroll
      for (int tt = 0; tt < 10; tt++) ws[(w * 4 + r) * 320 + tt * 32 + l] = lv[tt] * inv;
    }
    __syncwarp();

    float a0 = 0.f, a1 = 0.f, a2 = 0.f, a3 = 0.f;
    const float* wr = ws + (w * 4) * 320;
    #pragma unroll 4
    for (int k = 0; k < 320; k++) {
      float v = Vs[k * 32 + l];
      a0 += wr[k] * v;
      a1 += wr[320 + k] * v;
      a2 += wr[640 + k] * v;
      a3 += wr[960 + k] * v;
    }
    size_t ob = (size_t)(b * 320 + q0) * CZ + h * 32 + l;
    g_wa[ob]       = a0;
    g_wa[ob + 128] = a1;
    g_wa[ob + 256] = a2;
    g_wa[ob + 384] = a3;
  }
}

// ---------------- K4: gate + output GEMM [102400x128] x [128x128] ---------------
__global__ __launch_bounds__(256) void k4_out(const float* __restrict__ ow, float* __restrict__ out) {
  __shared__ float As[16][132];
  __shared__ float Ws[16][132];
  int tid = threadIdx.x;
  int tx = tid & 15, ty = tid >> 4;
  int rowBase = blockIdx.x * 128;

  float acc[8][8];
  #pragma unroll
  for (int i = 0; i < 8; i++)
    #pragma unroll
    for (int j = 0; j < 8; j++) acc[i][j] = 0.f;

  for (int kc = 0; kc < 128; kc += 16) {
    #pragma unroll
    for (int i = 0; i < 8; i++) {
      int e = tid + i * 256;
      int m = e >> 4, kk = e & 15;
      int row = rowBase + m;
      float a = g_wa[(size_t)row * CZ + kc + kk];
      float g = g_qkvg[(size_t)row * 512 + 384 + kc + kk];
      As[kk][m] = a * (1.f / (1.f + __expf(-g)));
    }
    #pragma unroll
    for (int i = 0; i < 8; i++) {
      int e = tid + i * 256;
      int kk = e >> 7, j = e & 127;
      Ws[kk][j] = ow[(kc + kk) * CZ + j];
    }
    __syncthreads();
    #pragma unroll
    for (int kk = 0; kk < 16; kk++) {
      float4 a0 = *(const float4*)&As[kk][ty * 4];
      float4 a1 = *(const float4*)&As[kk][64 + ty * 4];
      float4 b0 = *(const float4*)&Ws[kk][tx * 4];
      float4 b1 = *(const float4*)&Ws[kk][64 + tx * 4];
      float av[8] = {a0.x, a0.y, a0.z, a0.w, a1.x, a1.y, a1.z, a1.w};
      float bv[8] = {b0.x, b0.y, b0.z, b0.w, b1.x, b1.y, b1.z, b1.w};
      #pragma unroll
      for (int i = 0; i < 8; i++)
        #pragma unroll
        for (int j = 0; j < 8; j++) acc[i][j] += av[i] * bv[j];
    }
    __syncthreads();
  }
  #pragma unroll
  for (int i = 0; i < 8; i++) {
    int m = rowBase + ((i < 4) ? (ty * 4 + i) : (64 + ty * 4 + (i - 4)));
    float4 c0 = make_float4(acc[i][0], acc[i][1], acc[i][2], acc[i][3]);
    float4 c1 = make_float4(acc[i][4], acc[i][5], acc[i][6], acc[i][7]);
    *(float4*)&out[(size_t)m * CZ + tx * 4] = c0;
    *(float4*)&out[(size_t)m * CZ + 64 + tx * 4] = c1;
  }
}

// ---------------- launch --------------------------------------------------------
extern "C" void kernel_launch(void* const* d_in, const int* in_sizes, int n_in,
                              void* d_out, int out_size) {
  const float* pair    = (const float*)d_in[0];
  const float* affine  = (const float*)d_in[1];
  const float* mask    = (const float*)d_in[2];
  const float* pls     = (const float*)d_in[3];
  const float* plo     = (const float*)d_in[4];
  const float* als     = (const float*)d_in[5];
  const float* alo     = (const float*)d_in[6];
  const float* f2d     = (const float*)d_in[7];
  const float* qw      = (const float*)d_in[8];
  const float* kw      = (const float*)d_in[9];
  const float* vw      = (const float*)d_in[10];
  const float* gw      = (const float*)d_in[11];
  const float* ow      = (const float*)d_in[12];
  float* out = (float*)d_out;

  const int k3_smem = (320 * 33 + 320 * 32 + 8 * 4 * 32 + 8 * 4 * 320 + 320) * 4;  // 129536 B
  cudaFuncSetAttribute(k3_attn, cudaFuncAttributeMaxDynamicSharedMemorySize, k3_smem);

  k1_ln_nb<<<NN, 128>>>(pair, affine, pls, plo, als, alo, f2d);
  k2_qkvg<<<dim3(NN / 128, 4), 256>>>(qw, kw, vw, gw);
  k3_attn<<<dim3(NH, N_RES), 256, k3_smem>>>(mask);
  k4_out<<<NN / 128, 256>>>(ow, out);
}

// round 4
// speedup vs baseline: 1.3591x; 1.3591x over previous
#include <cuda_runtime.h>
#include <cstdint>
#include <math.h>

#define N_RES 320
#define CZ 128
#define NH 4
#define HD 32
#define NN (N_RES*N_RES)   /* 102400 */

// ---------------- scratch (static device globals; no allocation) ----------------
__device__ float g_pair_ln[(size_t)NN*CZ];   // 52.4 MB
__device__ float g_qkvg[(size_t)NN*512];     // 209.7 MB : [row][kind*128 + h*32 + d]
__device__ float g_nb[(size_t)NH*NN];        // 1.6 MB   : [h][q*320+k]
__device__ float g_wa[(size_t)NN*CZ];        // 52.4 MB  : weighted_avg [row][h*32+d]

__device__ __forceinline__ uint32_t f2tf32(float x) {
  uint32_t r; asm("cvt.rna.tf32.f32 %0, %1;" : "=r"(r) : "f"(x)); return r;
}
__device__ __forceinline__ void mma_tf32(float* c, const uint32_t* a, const uint32_t* b) {
  asm volatile("mma.sync.aligned.m16n8k8.row.col.f32.tf32.tf32.f32 "
               "{%0,%1,%2,%3}, {%4,%5,%6,%7}, {%8,%9}, {%0,%1,%2,%3};"
               : "+f"(c[0]), "+f"(c[1]), "+f"(c[2]), "+f"(c[3])
               : "r"(a[0]), "r"(a[1]), "r"(a[2]), "r"(a[3]), "r"(b[0]), "r"(b[1]));
}

#define LDA 132   /* padded stride (floats) for 128-wide smem tiles */

// ---------------- K1: LayerNorm(pair) + LayerNorm(affine) + nonbatched bias ----
__global__ void k1_ln_nb(const float* __restrict__ pair, const float* __restrict__ affine,
                         const float* __restrict__ pls, const float* __restrict__ plo,
                         const float* __restrict__ als, const float* __restrict__ alo,
                         const float* __restrict__ f2d) {
  int row = blockIdx.x;
  int t = threadIdx.x, w = t >> 5, l = t & 31;
  __shared__ float sh[16];
  size_t base = (size_t)row * CZ + t;

  float x = pair[base];
  float s = x, s2 = x * x;
  #pragma unroll
  for (int o = 16; o; o >>= 1) { s += __shfl_xor_sync(~0u, s, o); s2 += __shfl_xor_sync(~0u, s2, o); }
  if (l == 0) { sh[w] = s; sh[4 + w] = s2; }
  __syncthreads();
  float sum  = sh[0] + sh[1] + sh[2] + sh[3];
  float sum2 = sh[4] + sh[5] + sh[6] + sh[7];
  float mean = sum * (1.f / CZ);
  float var  = sum2 * (1.f / CZ) - mean * mean;
  float ln = (x - mean) * rsqrtf(var + 1e-5f) * pls[t] + plo[t];
  g_pair_ln[base] = ln;

  float a = affine[base];
  s = a; s2 = a * a;
  #pragma unroll
  for (int o = 16; o; o >>= 1) { s += __shfl_xor_sync(~0u, s, o); s2 += __shfl_xor_sync(~0u, s2, o); }
  __syncthreads();
  if (l == 0) { sh[w] = s; sh[4 + w] = s2; }
  __syncthreads();
  sum  = sh[0] + sh[1] + sh[2] + sh[3];
  sum2 = sh[4] + sh[5] + sh[6] + sh[7];
  mean = sum * (1.f / CZ);
  var  = sum2 * (1.f / CZ) - mean * mean;
  float aln = (a - mean) * rsqrtf(var + 1e-5f) * als[t] + alo[t];

  float p0 = aln * f2d[t * 4 + 0];
  float p1 = aln * f2d[t * 4 + 1];
  float p2 = aln * f2d[t * 4 + 2];
  float p3 = aln * f2d[t * 4 + 3];
  #pragma unroll
  for (int o = 16; o; o >>= 1) {
    p0 += __shfl_xor_sync(~0u, p0, o);
    p1 += __shfl_xor_sync(~0u, p1, o);
    p2 += __shfl_xor_sync(~0u, p2, o);
    p3 += __shfl_xor_sync(~0u, p3, o);
  }
  __syncthreads();
  if (l == 0) { sh[w*4+0] = p0; sh[w*4+1] = p1; sh[w*4+2] = p2; sh[w*4+3] = p3; }
  __syncthreads();
  if (t < 4) {
    g_nb[(size_t)t * NN + row] = sh[0*4+t] + sh[1*4+t] + sh[2*4+t] + sh[3*4+t];
  }
}

// ---------------- K2: QKVG projection via mma.sync tf32 -------------------------
// grid (4, 800): x = weight kind (q,k,v,g), y = 128-row tile. Whole K=128 in smem.
__global__ __launch_bounds__(256) void k2_mma(const float* __restrict__ qw, const float* __restrict__ kw,
                                              const float* __restrict__ vw, const float* __restrict__ gw) {
  extern __shared__ uint32_t sm2[];
  uint32_t* As = sm2;               // [128][LDA]
  uint32_t* Bs = sm2 + 128 * LDA;   // [128][LDA]

  int tid = threadIdx.x, wid = tid >> 5, lane = tid & 31;
  int wm = wid >> 2, wn = wid & 3;            // warp 2x4
  int qr = lane >> 2, qc = lane & 3;
  int rowBase = blockIdx.y * 128;
  const float* W = (blockIdx.x == 0) ? qw : (blockIdx.x == 1) ? kw : (blockIdx.x == 2) ? vw : gw;

  // load A (pair_ln) and B (weights), convert to tf32
  #pragma unroll
  for (int i = 0; i < 16; i++) {
    int idx = tid + i * 256;          // 4096 float4
    int r = idx >> 5, f = idx & 31;
    float4 v = ((const float4*)(g_pair_ln + (size_t)(rowBase + r) * CZ))[f];
    uint32_t* d = As + r * LDA + f * 4;
    d[0] = f2tf32(v.x); d[1] = f2tf32(v.y); d[2] = f2tf32(v.z); d[3] = f2tf32(v.w);
  }
  #pragma unroll
  for (int i = 0; i < 16; i++) {
    int idx = tid + i * 256;
    int k = idx >> 5, f = idx & 31;
    float4 v = ((const float4*)(W + (size_t)k * 128))[f];
    uint32_t* d = Bs + k * LDA + f * 4;
    d[0] = f2tf32(v.x); d[1] = f2tf32(v.y); d[2] = f2tf32(v.z); d[3] = f2tf32(v.w);
  }
  __syncthreads();

  float acc[4][4][4];
  #pragma unroll
  for (int i = 0; i < 4; i++)
    #pragma unroll
    for (int j = 0; j < 4; j++)
      #pragma unroll
      for (int e = 0; e < 4; e++) acc[i][j][e] = 0.f;

  #pragma unroll 2
  for (int kk = 0; kk < 16; kk++) {
    int k0 = kk * 8;
    uint32_t af[4][4], bf[4][2];
    #pragma unroll
    for (int i = 0; i < 4; i++) {
      int row = wm * 64 + i * 16 + qr;
      af[i][0] = As[row * LDA + k0 + qc];
      af[i][1] = As[(row + 8) * LDA + k0 + qc];
      af[i][2] = As[row * LDA + k0 + qc + 4];
      af[i][3] = As[(row + 8) * LDA + k0 + qc + 4];
    }
    #pragma unroll
    for (int j = 0; j < 4; j++) {
      int col = wn * 32 + j * 8 + qr;
      bf[j][0] = Bs[(k0 + qc) * LDA + col];
      bf[j][1] = Bs[(k0 + qc + 4) * LDA + col];
    }
    #pragma unroll
    for (int i = 0; i < 4; i++)
      #pragma unroll
      for (int j = 0; j < 4; j++)
        mma_tf32(acc[i][j], af[i], bf[j]);
  }

  // epilogue: direct float2 stores (full 32B sectors per mma n-row)
  int colBase = blockIdx.x * 128;
  #pragma unroll
  for (int i = 0; i < 4; i++) {
    int row0 = rowBase + wm * 64 + i * 16 + qr;
    #pragma unroll
    for (int j = 0; j < 4; j++) {
      int col = colBase + wn * 32 + j * 8 + qc * 2;
      *(float2*)(g_qkvg + (size_t)row0 * 512 + col)       = make_float2(acc[i][j][0], acc[i][j][1]);
      *(float2*)(g_qkvg + (size_t)(row0 + 8) * 512 + col) = make_float2(acc[i][j][2], acc[i][j][3]);
    }
  }
}

// ---------------- K3: attention per (b,h) ---------------------------------------
__global__ __launch_bounds__(256) void k3_attn(const float* __restrict__ mask) {
  extern __shared__ float sm[];
  float* Ks     = sm;                     // 320*33
  float* Vs     = Ks + 320 * 33;          // 320*32
  float* qs     = Vs + 320 * 32;          // 8*4*32
  float* ws     = qs + 8 * 4 * 32;        // 8*4*320
  float* bias_s = ws + 8 * 4 * 320;       // 320

  int h = blockIdx.x, b = blockIdx.y;
  int t = threadIdx.x, w = t >> 5, l = t & 31;

  for (int e = t; e < 320 * 32; e += 256) {
    int k = e >> 5, c = e & 31;
    size_t rbase = (size_t)(b * 320 + k) * 512 + h * 32;
    Ks[k * 33 + c] = g_qkvg[rbase + 128 + c];
    Vs[e]          = g_qkvg[rbase + 256 + c];
  }
  for (int e = t; e < 320; e += 256) bias_s[e] = 1e9f * (mask[b * 320 + e] - 1.f);
  __syncthreads();

  const float scl = 0.17677669529663687f;
  for (int it = 0; it < 10; it++) {
    int q0 = it * 32 + w * 4;
    #pragma unroll
    for (int r = 0; r < 4; r++)
      qs[(w * 4 + r) * 32 + l] = g_qkvg[(size_t)(b * 320 + q0 + r) * 512 + h * 32 + l];
    __syncwarp();

    float lg[4][10];
    #pragma unroll
    for (int r = 0; r < 4; r++)
      #pragma unroll
      for (int tt = 0; tt < 10; tt++) lg[r][tt] = 0.f;

    for (int c = 0; c < 32; c++) {
      float qv0 = qs[(w * 4 + 0) * 32 + c];
      float qv1 = qs[(w * 4 + 1) * 32 + c];
      float qv2 = qs[(w * 4 + 2) * 32 + c];
      float qv3 = qs[(w * 4 + 3) * 32 + c];
      #pragma unroll
      for (int tt = 0; tt < 10; tt++) {
        float kv = Ks[(tt * 32 + l) * 33 + c];
        lg[0][tt] += qv0 * kv;
        lg[1][tt] += qv1 * kv;
        lg[2][tt] += qv2 * kv;
        lg[3][tt] += qv3 * kv;
      }
    }

    #pragma unroll
    for (int r = 0; r < 4; r++) {
      int qrow = q0 + r;
      const float* nbrow = g_nb + (size_t)h * NN + (size_t)qrow * 320;
      float lv[10];
      float mx = -3.0e38f;
      #pragma unroll
      for (int tt = 0; tt < 10; tt++) {
        int k = tt * 32 + l;
        lv[tt] = lg[r][tt] * scl + bias_s[k] + __ldg(nbrow + k);
        mx = fmaxf(mx, lv[tt]);
      }
      #pragma unroll
      for (int o = 16; o; o >>= 1) mx = fmaxf(mx, __shfl_xor_sync(~0u, mx, o));
      float ssum = 0.f;
      #pragma unroll
      for (int tt = 0; tt < 10; tt++) { lv[tt] = __expf(lv[tt] - mx); ssum += lv[tt]; }
      #pragma unroll
      for (int o = 16; o; o >>= 1) ssum += __shfl_xor_sync(~0u, ssum, o);
      float inv = 1.f / ssum;
      #pragma unroll
      for (int tt = 0; tt < 10; tt++) ws[(w * 4 + r) * 320 + tt * 32 + l] = lv[tt] * inv;
    }
    __syncwarp();

    float a0 = 0.f, a1 = 0.f, a2 = 0.f, a3 = 0.f;
    const float* wr = ws + (w * 4) * 320;
    #pragma unroll 4
    for (int k = 0; k < 320; k++) {
      float v = Vs[k * 32 + l];
      a0 += wr[k] * v;
      a1 += wr[320 + k] * v;
      a2 += wr[640 + k] * v;
      a3 += wr[960 + k] * v;
    }
    size_t ob = (size_t)(b * 320 + q0) * CZ + h * 32 + l;
    g_wa[ob]       = a0;
    g_wa[ob + 128] = a1;
    g_wa[ob + 256] = a2;
    g_wa[ob + 384] = a3;
  }
}

// ---------------- K4: gate*sigmoid fused + output proj via mma.sync tf32 --------
__global__ __launch_bounds__(256) void k4_mma(const float* __restrict__ ow, float* __restrict__ out) {
  extern __shared__ uint32_t sm4[];
  uint32_t* As = sm4;
  uint32_t* Bs = sm4 + 128 * LDA;

  int tid = threadIdx.x, wid = tid >> 5, lane = tid & 31;
  int wm = wid >> 2, wn = wid & 3;
  int qr = lane >> 2, qc = lane & 3;
  int rowBase = blockIdx.x * 128;

  #pragma unroll
  for (int i = 0; i < 16; i++) {
    int idx = tid + i * 256;
    int r = idx >> 5, f = idx & 31;
    int row = rowBase + r;
    float4 a  = ((const float4*)(g_wa + (size_t)row * CZ))[f];
    float4 gt = ((const float4*)(g_qkvg + (size_t)row * 512 + 384))[f];
    a.x *= 1.f / (1.f + __expf(-gt.x));
    a.y *= 1.f / (1.f + __expf(-gt.y));
    a.z *= 1.f / (1.f + __expf(-gt.z));
    a.w *= 1.f / (1.f + __expf(-gt.w));
    uint32_t* d = As + r * LDA + f * 4;
    d[0] = f2tf32(a.x); d[1] = f2tf32(a.y); d[2] = f2tf32(a.z); d[3] = f2tf32(a.w);
  }
  #pragma unroll
  for (int i = 0; i < 16; i++) {
    int idx = tid + i * 256;
    int k = idx >> 5, f = idx & 31;
    float4 v = ((const float4*)(ow + (size_t)k * 128))[f];
    uint32_t* d = Bs + k * LDA + f * 4;
    d[0] = f2tf32(v.x); d[1] = f2tf32(v.y); d[2] = f2tf32(v.z); d[3] = f2tf32(v.w);
  }
  __syncthreads();

  float acc[4][4][4];
  #pragma unroll
  for (int i = 0; i < 4; i++)
    #pragma unroll
    for (int j = 0; j < 4; j++)
      #pragma unroll
      for (int e = 0; e < 4; e++) acc[i][j][e] = 0.f;

  #pragma unroll 2
  for (int kk = 0; kk < 16; kk++) {
    int k0 = kk * 8;
    uint32_t af[4][4], bf[4][2];
    #pragma unroll
    for (int i = 0; i < 4; i++) {
      int row = wm * 64 + i * 16 + qr;
      af[i][0] = As[row * LDA + k0 + qc];
      af[i][1] = As[(row + 8) * LDA + k0 + qc];
      af[i][2] = As[row * LDA + k0 + qc + 4];
      af[i][3] = As[(row + 8) * LDA + k0 + qc + 4];
    }
    #pragma unroll
    for (int j = 0; j < 4; j++) {
      int col = wn * 32 + j * 8 + qr;
      bf[j][0] = Bs[(k0 + qc) * LDA + col];
      bf[j][1] = Bs[(k0 + qc + 4) * LDA + col];
    }
    #pragma unroll
    for (int i = 0; i < 4; i++)
      #pragma unroll
      for (int j = 0; j < 4; j++)
        mma_tf32(acc[i][j], af[i], bf[j]);
  }

  #pragma unroll
  for (int i = 0; i < 4; i++) {
    int row0 = rowBase + wm * 64 + i * 16 + qr;
    #pragma unroll
    for (int j = 0; j < 4; j++) {
      int col = wn * 32 + j * 8 + qc * 2;
      *(float2*)(out + (size_t)row0 * CZ + col)       = make_float2(acc[i][j][0], acc[i][j][1]);
      *(float2*)(out + (size_t)(row0 + 8) * CZ + col) = make_float2(acc[i][j][2], acc[i][j][3]);
    }
  }
}

// ---------------- launch --------------------------------------------------------
extern "C" void kernel_launch(void* const* d_in, const int* in_sizes, int n_in,
                              void* d_out, int out_size) {
  const float* pair    = (const float*)d_in[0];
  const float* affine  = (const float*)d_in[1];
  const float* mask    = (const float*)d_in[2];
  const float* pls     = (const float*)d_in[3];
  const float* plo     = (const float*)d_in[4];
  const float* als     = (const float*)d_in[5];
  const float* alo     = (const float*)d_in[6];
  const float* f2d     = (const float*)d_in[7];
  const float* qw      = (const float*)d_in[8];
  const float* kw      = (const float*)d_in[9];
  const float* vw      = (const float*)d_in[10];
  const float* gw      = (const float*)d_in[11];
  const float* ow      = (const float*)d_in[12];
  float* out = (float*)d_out;

  const int gemm_smem = 2 * 128 * LDA * 4;  // 135168 B
  const int k3_smem = (320 * 33 + 320 * 32 + 8 * 4 * 32 + 8 * 4 * 320 + 320) * 4;
  cudaFuncSetAttribute(k3_attn, cudaFuncAttributeMaxDynamicSharedMemorySize, k3_smem);
  cudaFuncSetAttribute(k2_mma, cudaFuncAttributeMaxDynamicSharedMemorySize, gemm_smem);
  cudaFuncSetAttribute(k4_mma, cudaFuncAttributeMaxDynamicSharedMemorySize, gemm_smem);

  k1_ln_nb<<<NN, 128>>>(pair, affine, pls, plo, als, alo, f2d);
  k2_mma<<<dim3(4, NN / 128), 256, gemm_smem>>>(qw, kw, vw, gw);
  k3_attn<<<dim3(NH, N_RES), 256, k3_smem>>>(mask);
  k4_mma<<<NN / 128, 256, gemm_smem>>>(ow, out);
}

// round 5
// speedup vs baseline: 1.6471x; 1.2119x over previous
#include <cuda_runtime.h>
#include <cstdint>
#include <math.h>

#define N_RES 320
#define CZ 128
#define NH 4
#define HD 32
#define NN (N_RES*N_RES)   /* 102400 */

// ---------------- scratch (static device globals; no allocation) ----------------
__device__ float g_qkvg[(size_t)NN*512];     // 209.7 MB : [row][kind*128 + h*32 + d]
__device__ float g_nb[(size_t)NH*NN];        // 1.6 MB   : [h][q*320+k]
__device__ float g_wa[(size_t)NN*CZ];        // 52.4 MB  : weighted_avg [row][h*32+d]

__device__ __forceinline__ uint32_t f2tf32(float x) {
  uint32_t r; asm("cvt.rna.tf32.f32 %0, %1;" : "=r"(r) : "f"(x)); return r;
}
__device__ __forceinline__ void mma_tf32(float* c, const uint32_t* a, const uint32_t* b) {
  asm volatile("mma.sync.aligned.m16n8k8.row.col.f32.tf32.tf32.f32 "
               "{%0,%1,%2,%3}, {%4,%5,%6,%7}, {%8,%9}, {%0,%1,%2,%3};"
               : "+f"(c[0]), "+f"(c[1]), "+f"(c[2]), "+f"(c[3])
               : "r"(a[0]), "r"(a[1]), "r"(a[2]), "r"(a[3]), "r"(b[0]), "r"(b[1]));
}

#define LDA 132   /* padded stride (floats) for 128-wide smem tiles */

// ---------------- K1: LayerNorm(affine) + nonbatched bias only ------------------
__global__ void k1_nb(const float* __restrict__ affine,
                      const float* __restrict__ als, const float* __restrict__ alo,
                      const float* __restrict__ f2d) {
  int row = blockIdx.x;
  int t = threadIdx.x, w = t >> 5, l = t & 31;
  __shared__ float sh[16];
  size_t base = (size_t)row * CZ + t;

  float a = affine[base];
  float s = a, s2 = a * a;
  #pragma unroll
  for (int o = 16; o; o >>= 1) { s += __shfl_xor_sync(~0u, s, o); s2 += __shfl_xor_sync(~0u, s2, o); }
  if (l == 0) { sh[w] = s; sh[4 + w] = s2; }
  __syncthreads();
  float sum  = sh[0] + sh[1] + sh[2] + sh[3];
  float sum2 = sh[4] + sh[5] + sh[6] + sh[7];
  float mean = sum * (1.f / CZ);
  float var  = sum2 * (1.f / CZ) - mean * mean;
  float aln = (a - mean) * rsqrtf(var + 1e-5f) * als[t] + alo[t];

  float p0 = aln * f2d[t * 4 + 0];
  float p1 = aln * f2d[t * 4 + 1];
  float p2 = aln * f2d[t * 4 + 2];
  float p3 = aln * f2d[t * 4 + 3];
  #pragma unroll
  for (int o = 16; o; o >>= 1) {
    p0 += __shfl_xor_sync(~0u, p0, o);
    p1 += __shfl_xor_sync(~0u, p1, o);
    p2 += __shfl_xor_sync(~0u, p2, o);
    p3 += __shfl_xor_sync(~0u, p3, o);
  }
  __syncthreads();
  if (l == 0) { sh[w*4+0] = p0; sh[w*4+1] = p1; sh[w*4+2] = p2; sh[w*4+3] = p3; }
  __syncthreads();
  if (t < 4) {
    g_nb[(size_t)t * NN + row] = sh[0*4+t] + sh[1*4+t] + sh[2*4+t] + sh[3*4+t];
  }
}

// ---------------- K2: fused pair-LN + QKVG projection (mma tf32) ----------------
// grid (4, 1600): x = kind, y = 64-row tile. 128 threads, 2 CTAs/SM.
__global__ __launch_bounds__(128) void k2_mma(const float* __restrict__ pair,
                                              const float* __restrict__ pls, const float* __restrict__ plo,
                                              const float* __restrict__ qw, const float* __restrict__ kw,
                                              const float* __restrict__ vw, const float* __restrict__ gw) {
  extern __shared__ uint32_t sm2[];
  uint32_t* As = sm2;               // [64][LDA]  (fp32 staged, then tf32 in place)
  uint32_t* Bs = sm2 + 64 * LDA;    // [128][LDA]
  float* Asf = (float*)As;

  int tid = threadIdx.x, wid = tid >> 5, lane = tid & 31;
  int wn = wid;                               // 4 warps along N
  int qr = lane >> 2, qc = lane & 3;
  int rowBase = blockIdx.y * 64;
  const float* W = (blockIdx.x == 0) ? qw : (blockIdx.x == 1) ? kw : (blockIdx.x == 2) ? vw : gw;

  // stage A rows as fp32 (coalesced)
  #pragma unroll
  for (int i = 0; i < 16; i++) {
    int idx = tid + i * 128;                  // 2048 float4
    int r = idx >> 5, f = idx & 31;
    float4 v = ((const float4*)(pair + (size_t)(rowBase + r) * CZ))[f];
    float* d = Asf + r * LDA + f * 4;
    d[0] = v.x; d[1] = v.y; d[2] = v.z; d[3] = v.w;
  }
  // B load + tf32
  #pragma unroll
  for (int i = 0; i < 32; i++) {
    int idx = tid + i * 128;
    int k = idx >> 5, f = idx & 31;
    float4 v = ((const float4*)(W + (size_t)k * 128))[f];
    uint32_t* d = Bs + k * LDA + f * 4;
    d[0] = f2tf32(v.x); d[1] = f2tf32(v.y); d[2] = f2tf32(v.z); d[3] = f2tf32(v.w);
  }
  __syncthreads();

  // in-place LayerNorm per row (warp-per-row), write tf32 bits
  float plsv[4], plov[4];
  #pragma unroll
  for (int m = 0; m < 4; m++) { plsv[m] = pls[lane + 32 * m]; plov[m] = plo[lane + 32 * m]; }
  for (int r = wid; r < 64; r += 4) {
    float x[4];
    float s = 0.f, s2 = 0.f;
    #pragma unroll
    for (int m = 0; m < 4; m++) {
      x[m] = Asf[r * LDA + lane + 32 * m];
      s += x[m]; s2 += x[m] * x[m];
    }
    #pragma unroll
    for (int o = 16; o; o >>= 1) { s += __shfl_xor_sync(~0u, s, o); s2 += __shfl_xor_sync(~0u, s2, o); }
    float mean = s * (1.f / CZ);
    float var  = s2 * (1.f / CZ) - mean * mean;
    float rstd = rsqrtf(var + 1e-5f);
    #pragma unroll
    for (int m = 0; m < 4; m++)
      As[r * LDA + lane + 32 * m] = f2tf32((x[m] - mean) * rstd * plsv[m] + plov[m]);
  }
  __syncthreads();

  float acc[4][4][4];
  #pragma unroll
  for (int i = 0; i < 4; i++)
    #pragma unroll
    for (int j = 0; j < 4; j++)
      #pragma unroll
      for (int e = 0; e < 4; e++) acc[i][j][e] = 0.f;

  #pragma unroll 2
  for (int kk = 0; kk < 16; kk++) {
    int k0 = kk * 8;
    uint32_t af[4][4], bf[4][2];
    #pragma unroll
    for (int i = 0; i < 4; i++) {
      int row = i * 16 + qr;
      af[i][0] = As[row * LDA + k0 + qc];
      af[i][1] = As[(row + 8) * LDA + k0 + qc];
      af[i][2] = As[row * LDA + k0 + qc + 4];
      af[i][3] = As[(row + 8) * LDA + k0 + qc + 4];
    }
    #pragma unroll
    for (int j = 0; j < 4; j++) {
      int col = wn * 32 + j * 8 + qr;
      bf[j][0] = Bs[(k0 + qc) * LDA + col];
      bf[j][1] = Bs[(k0 + qc + 4) * LDA + col];
    }
    #pragma unroll
    for (int i = 0; i < 4; i++)
      #pragma unroll
      for (int j = 0; j < 4; j++)
        mma_tf32(acc[i][j], af[i], bf[j]);
  }

  int colBase = blockIdx.x * 128;
  #pragma unroll
  for (int i = 0; i < 4; i++) {
    int row0 = rowBase + i * 16 + qr;
    #pragma unroll
    for (int j = 0; j < 4; j++) {
      int col = colBase + wn * 32 + j * 8 + qc * 2;
      *(float2*)(g_qkvg + (size_t)row0 * 512 + col)       = make_float2(acc[i][j][0], acc[i][j][1]);
      *(float2*)(g_qkvg + (size_t)(row0 + 8) * 512 + col) = make_float2(acc[i][j][2], acc[i][j][3]);
    }
  }
}

// ---------------- K3: attention on mma tf32 (per b, h, 64-row q-tile) -----------
// grid (5, 4, 320) = (qtile, h, b); 256 threads (8 warps).
#define QS_P 36
#define KT_P 328
#define VS_P 40
#define PS_P 332
// smem floats: Qs 64*36 + Kt 32*328 + Vs 320*40 + Ps 64*332 + bias 320
#define K3_QS   0
#define K3_KT   (64*QS_P)
#define K3_VS   (K3_KT + 32*KT_P)
#define K3_PS   (K3_VS + 320*VS_P)
#define K3_BIAS (K3_PS + 64*PS_P)
#define K3_FLOATS (K3_BIAS + 320)

__global__ __launch_bounds__(256) void k3_attn(const float* __restrict__ mask) {
  extern __shared__ uint32_t sm3[];
  uint32_t* Qs = sm3 + K3_QS;
  uint32_t* Kt = sm3 + K3_KT;
  uint32_t* Vs = sm3 + K3_VS;
  uint32_t* Ps = sm3 + K3_PS;      // fp32 S, then tf32 P
  float*    Psf = (float*)Ps;
  float*    bias_s = (float*)(sm3 + K3_BIAS);

  int qt = blockIdx.x, h = blockIdx.y, b = blockIdx.z;
  int q0 = qt * 64;
  int tid = threadIdx.x, wid = tid >> 5, lane = tid & 31;
  int qr = lane >> 2, qc = lane & 3;

  // ---- stage Q (tf32), K^T (tf32), V (tf32), bias ----
  #pragma unroll
  for (int i = 0; i < 8; i++) {
    int e = tid + i * 256;
    int row = e >> 5, c = e & 31;
    Qs[row * QS_P + c] = f2tf32(g_qkvg[(size_t)(b * 320 + q0 + row) * 512 + h * 32 + c]);
  }
  #pragma unroll 4
  for (int i = 0; i < 40; i++) {
    int e = tid + i * 256;
    int key = e >> 5, c = e & 31;
    size_t rb = (size_t)(b * 320 + key) * 512 + h * 32;
    Kt[c * KT_P + key] = f2tf32(g_qkvg[rb + 128 + c]);
    Vs[key * VS_P + c] = f2tf32(g_qkvg[rb + 256 + c]);
  }
  for (int e = tid; e < 320; e += 256) bias_s[e] = 1e9f * (mask[b * 320 + e] - 1.f);
  __syncthreads();

  // ---- QK^T: warp (wm 0..1) x (wn 0..3); warp tile 32 rows x 80 cols ----
  {
    int wm = wid >> 2, wn = wid & 3;
    float acc[2][10][4];
    #pragma unroll
    for (int i = 0; i < 2; i++)
      #pragma unroll
      for (int j = 0; j < 10; j++)
        #pragma unroll
        for (int e = 0; e < 4; e++) acc[i][j][e] = 0.f;

    #pragma unroll
    for (int cs = 0; cs < 4; cs++) {
      int c0 = cs * 8;
      uint32_t af[2][4], bf[10][2];
      #pragma unroll
      for (int i = 0; i < 2; i++) {
        int row = wm * 32 + i * 16 + qr;
        af[i][0] = Qs[row * QS_P + c0 + qc];
        af[i][1] = Qs[(row + 8) * QS_P + c0 + qc];
        af[i][2] = Qs[row * QS_P + c0 + qc + 4];
        af[i][3] = Qs[(row + 8) * QS_P + c0 + qc + 4];
      }
      #pragma unroll
      for (int j = 0; j < 10; j++) {
        int col = wn * 80 + j * 8 + qr;
        bf[j][0] = Kt[(c0 + qc) * KT_P + col];
        bf[j][1] = Kt[(c0 + qc + 4) * KT_P + col];
      }
      #pragma unroll
      for (int i = 0; i < 2; i++)
        #pragma unroll
        for (int j = 0; j < 10; j++)
          mma_tf32(acc[i][j], af[i], bf[j]);
    }
    // store S (fp32) to Ps
    #pragma unroll
    for (int i = 0; i < 2; i++) {
      int row = wm * 32 + i * 16 + qr;
      #pragma unroll
      for (int j = 0; j < 10; j++) {
        int col = wn * 80 + j * 8 + qc * 2;
        *(float2*)(Psf + row * PS_P + col)       = make_float2(acc[i][j][0], acc[i][j][1]);
        *(float2*)(Psf + (row + 8) * PS_P + col) = make_float2(acc[i][j][2], acc[i][j][3]);
      }
    }
  }
  __syncthreads();

  // ---- softmax: warp per 8 rows; scl*S + bias + nb; write tf32 P ----
  {
    const float scl = 0.17677669529663687f;
    #pragma unroll
    for (int rr = 0; rr < 8; rr++) {
      int r = wid * 8 + rr;
      const float* nbrow = g_nb + (size_t)h * NN + (size_t)(q0 + r) * 320;
      float v[10];
      float mx = -3.0e38f;
      #pragma unroll
      for (int t = 0; t < 10; t++) {
        int k = lane + 32 * t;
        v[t] = Psf[r * PS_P + k] * scl + bias_s[k] + __ldg(nbrow + k);
        mx = fmaxf(mx, v[t]);
      }
      #pragma unroll
      for (int o = 16; o; o >>= 1) mx = fmaxf(mx, __shfl_xor_sync(~0u, mx, o));
      float ssum = 0.f;
      #pragma unroll
      for (int t = 0; t < 10; t++) { v[t] = __expf(v[t] - mx); ssum += v[t]; }
      #pragma unroll
      for (int o = 16; o; o >>= 1) ssum += __shfl_xor_sync(~0u, ssum, o);
      float inv = 1.f / ssum;
      #pragma unroll
      for (int t = 0; t < 10; t++) Ps[r * PS_P + lane + 32 * t] = f2tf32(v[t] * inv);
    }
  }
  __syncthreads();

  // ---- AV: warp (wm2 0..3) x (wn2 0..1); warp tile 16 rows x 16 cols ----
  {
    int wm2 = wid >> 1, wn2 = wid & 1;
    float acc[2][4];
    #pragma unroll
    for (int j = 0; j < 2; j++)
      #pragma unroll
      for (int e = 0; e < 4; e++) acc[j][e] = 0.f;

    #pragma unroll 4
    for (int ks = 0; ks < 40; ks++) {
      int k0 = ks * 8;
      uint32_t af[4], bf[2][2];
      int row = wm2 * 16 + qr;
      af[0] = Ps[row * PS_P + k0 + qc];
      af[1] = Ps[(row + 8) * PS_P + k0 + qc];
      af[2] = Ps[row * PS_P + k0 + qc + 4];
      af[3] = Ps[(row + 8) * PS_P + k0 + qc + 4];
      #pragma unroll
      for (int j = 0; j < 2; j++) {
        int col = wn2 * 16 + j * 8 + qr;
        bf[j][0] = Vs[(k0 + qc) * VS_P + col];
        bf[j][1] = Vs[(k0 + qc + 4) * VS_P + col];
      }
      mma_tf32(acc[0], af, bf[0]);
      mma_tf32(acc[1], af, bf[1]);
    }
    #pragma unroll
    for (int j = 0; j < 2; j++) {
      int row = q0 + wm2 * 16 + qr;
      int col = h * 32 + wn2 * 16 + j * 8 + qc * 2;
      *(float2*)(g_wa + (size_t)(b * 320 + row) * 128 + col)     = make_float2(acc[j][0], acc[j][1]);
      *(float2*)(g_wa + (size_t)(b * 320 + row + 8) * 128 + col) = make_float2(acc[j][2], acc[j][3]);
    }
  }
}

// ---------------- K4: gate*sigmoid fused + output proj (mma tf32) ---------------
// grid 1600, 128 threads, 64-row tiles, 2 CTAs/SM.
__global__ __launch_bounds__(128) void k4_mma(const float* __restrict__ ow, float* __restrict__ out) {
  extern __shared__ uint32_t sm4[];
  uint32_t* As = sm4;               // [64][LDA]
  uint32_t* Bs = sm4 + 64 * LDA;    // [128][LDA]

  int tid = threadIdx.x, wid = tid >> 5, lane = tid & 31;
  int wn = wid;
  int qr = lane >> 2, qc = lane & 3;
  int rowBase = blockIdx.x * 64;

  #pragma unroll
  for (int i = 0; i < 16; i++) {
    int idx = tid + i * 128;
    int r = idx >> 5, f = idx & 31;
    int row = rowBase + r;
    float4 a  = ((const float4*)(g_wa + (size_t)row * CZ))[f];
    float4 gt = ((const float4*)(g_qkvg + (size_t)row * 512 + 384))[f];
    a.x *= 1.f / (1.f + __expf(-gt.x));
    a.y *= 1.f / (1.f + __expf(-gt.y));
    a.z *= 1.f / (1.f + __expf(-gt.z));
    a.w *= 1.f / (1.f + __expf(-gt.w));
    uint32_t* d = As + r * LDA + f * 4;
    d[0] = f2tf32(a.x); d[1] = f2tf32(a.y); d[2] = f2tf32(a.z); d[3] = f2tf32(a.w);
  }
  #pragma unroll
  for (int i = 0; i < 32; i++) {
    int idx = tid + i * 128;
    int k = idx >> 5, f = idx & 31;
    float4 v = ((const float4*)(ow + (size_t)k * 128))[f];
    uint32_t* d = Bs + k * LDA + f * 4;
    d[0] = f2tf32(v.x); d[1] = f2tf32(v.y); d[2] = f2tf32(v.z); d[3] = f2tf32(v.w);
  }
  __syncthreads();

  float acc[4][4][4];
  #pragma unroll
  for (int i = 0; i < 4; i++)
    #pragma unroll
    for (int j = 0; j < 4; j++)
      #pragma unroll
      for (int e = 0; e < 4; e++) acc[i][j][e] = 0.f;

  #pragma unroll 2
  for (int kk = 0; kk < 16; kk++) {
    int k0 = kk * 8;
    uint32_t af[4][4], bf[4][2];
    #pragma unroll
    for (int i = 0; i < 4; i++) {
      int row = i * 16 + qr;
      af[i][0] = As[row * LDA + k0 + qc];
      af[i][1] = As[(row + 8) * LDA + k0 + qc];
      af[i][2] = As[row * LDA + k0 + qc + 4];
      af[i][3] = As[(row + 8) * LDA + k0 + qc + 4];
    }
    #pragma unroll
    for (int j = 0; j < 4; j++) {
      int col = wn * 32 + j * 8 + qr;
      bf[j][0] = Bs[(k0 + qc) * LDA + col];
      bf[j][1] = Bs[(k0 + qc + 4) * LDA + col];
    }
    #pragma unroll
    for (int i = 0; i < 4; i++)
      #pragma unroll
      for (int j = 0; j < 4; j++)
        mma_tf32(acc[i][j], af[i], bf[j]);
  }

  #pragma unroll
  for (int i = 0; i < 4; i++) {
    int row0 = rowBase + i * 16 + qr;
    #pragma unroll
    for (int j = 0; j < 4; j++) {
      int col = wn * 32 + j * 8 + qc * 2;
      *(float2*)(out + (size_t)row0 * CZ + col)       = make_float2(acc[i][j][0], acc[i][j][1]);
      *(float2*)(out + (size_t)(row0 + 8) * CZ + col) = make_float2(acc[i][j][2], acc[i][j][3]);
    }
  }
}

// ---------------- launch --------------------------------------------------------
extern "C" void kernel_launch(void* const* d_in, const int* in_sizes, int n_in,
                              void* d_out, int out_size) {
  const float* pair    = (const float*)d_in[0];
  const float* affine  = (const float*)d_in[1];
  const float* mask    = (const float*)d_in[2];
  const float* pls     = (const float*)d_in[3];
  const float* plo     = (const float*)d_in[4];
  const float* als     = (const float*)d_in[5];
  const float* alo     = (const float*)d_in[6];
  const float* f2d     = (const float*)d_in[7];
  const float* qw      = (const float*)d_in[8];
  const float* kw      = (const float*)d_in[9];
  const float* vw      = (const float*)d_in[10];
  const float* gw      = (const float*)d_in[11];
  const float* ow      = (const float*)d_in[12];
  float* out = (float*)d_out;

  const int gemm_smem = (64 + 128) * LDA * 4;   // 101376 B -> 2 CTAs/SM
  const int k3_smem = K3_FLOATS * 4;            // 188672 B
  cudaFuncSetAttribute(k2_mma, cudaFuncAttributeMaxDynamicSharedMemorySize, gemm_smem);
  cudaFuncSetAttribute(k4_mma, cudaFuncAttributeMaxDynamicSharedMemorySize, gemm_smem);
  cudaFuncSetAttribute(k3_attn, cudaFuncAttributeMaxDynamicSharedMemorySize, k3_smem);

  k1_nb<<<NN, 128>>>(affine, als, alo, f2d);
  k2_mma<<<dim3(4, NN / 64), 128, gemm_smem>>>(pair, pls, plo, qw, kw, vw, gw);
  k3_attn<<<dim3(5, NH, N_RES), 256, k3_smem>>>(mask);
  k4_mma<<<NN / 64, 128, gemm_smem>>>(ow, out);
}

// round 6
// speedup vs baseline: 2.2450x; 1.3630x over previous
#include <cuda_runtime.h>
#include <cstdint>
#include <math.h>

#define N_RES 320
#define CZ 128
#define NH 4
#define HD 32
#define NN (N_RES*N_RES)   /* 102400 */

// ---------------- scratch (static device globals; no allocation) ----------------
__device__ float g_qkvg[(size_t)NN*512];     // 209.7 MB : [row][kind*128 + h*32 + d]
__device__ float g_nb[(size_t)NH*NN];        // 1.6 MB   : [h][q*320+k]
__device__ float g_wa[(size_t)NN*CZ];        // 52.4 MB  : weighted_avg [row][h*32+d]

__device__ __forceinline__ uint32_t f2tf32(float x) {
  uint32_t r; asm("cvt.rna.tf32.f32 %0, %1;" : "=r"(r) : "f"(x)); return r;
}
__device__ __forceinline__ void mma_tf32(float* c, const uint32_t* a, const uint32_t* b) {
  asm volatile("mma.sync.aligned.m16n8k8.row.col.f32.tf32.tf32.f32 "
               "{%0,%1,%2,%3}, {%4,%5,%6,%7}, {%8,%9}, {%0,%1,%2,%3};"
               : "+f"(c[0]), "+f"(c[1]), "+f"(c[2]), "+f"(c[3])
               : "r"(a[0]), "r"(a[1]), "r"(a[2]), "r"(a[3]), "r"(b[0]), "r"(b[1]));
}

#define LDA 132   /* padded stride (floats) for 128-wide smem tiles */

// ---------------- K1: LayerNorm(affine) + nonbatched bias only ------------------
__global__ void k1_nb(const float* __restrict__ affine,
                      const float* __restrict__ als, const float* __restrict__ alo,
                      const float* __restrict__ f2d) {
  int row = blockIdx.x;
  int t = threadIdx.x, w = t >> 5, l = t & 31;
  __shared__ float sh[16];
  size_t base = (size_t)row * CZ + t;

  float a = affine[base];
  float s = a, s2 = a * a;
  #pragma unroll
  for (int o = 16; o; o >>= 1) { s += __shfl_xor_sync(~0u, s, o); s2 += __shfl_xor_sync(~0u, s2, o); }
  if (l == 0) { sh[w] = s; sh[4 + w] = s2; }
  __syncthreads();
  float sum  = sh[0] + sh[1] + sh[2] + sh[3];
  float sum2 = sh[4] + sh[5] + sh[6] + sh[7];
  float mean = sum * (1.f / CZ);
  float var  = sum2 * (1.f / CZ) - mean * mean;
  float aln = (a - mean) * rsqrtf(var + 1e-5f) * als[t] + alo[t];

  float p0 = aln * f2d[t * 4 + 0];
  float p1 = aln * f2d[t * 4 + 1];
  float p2 = aln * f2d[t * 4 + 2];
  float p3 = aln * f2d[t * 4 + 3];
  #pragma unroll
  for (int o = 16; o; o >>= 1) {
    p0 += __shfl_xor_sync(~0u, p0, o);
    p1 += __shfl_xor_sync(~0u, p1, o);
    p2 += __shfl_xor_sync(~0u, p2, o);
    p3 += __shfl_xor_sync(~0u, p3, o);
  }
  __syncthreads();
  if (l == 0) { sh[w*4+0] = p0; sh[w*4+1] = p1; sh[w*4+2] = p2; sh[w*4+3] = p3; }
  __syncthreads();
  if (t < 4) {
    g_nb[(size_t)t * NN + row] = sh[0*4+t] + sh[1*4+t] + sh[2*4+t] + sh[3*4+t];
  }
}

// ---------------- K2: fused pair-LN + QKVG projection (mma tf32) ----------------
// grid (4, 1600): x = kind, y = 64-row tile. 256 threads (8 warps), 2 CTAs/SM.
__global__ __launch_bounds__(256) void k2_mma(const float* __restrict__ pair,
                                              const float* __restrict__ pls, const float* __restrict__ plo,
                                              const float* __restrict__ qw, const float* __restrict__ kw,
                                              const float* __restrict__ vw, const float* __restrict__ gw) {
  extern __shared__ uint32_t sm2[];
  uint32_t* As = sm2;               // [64][LDA]  (fp32 staged, then tf32 in place)
  uint32_t* Bs = sm2 + 64 * LDA;    // [128][LDA]
  float* Asf = (float*)As;

  int tid = threadIdx.x, wid = tid >> 5, lane = tid & 31;
  int wm = wid >> 2, wn = wid & 3;            // warp grid 2x4
  int qr = lane >> 2, qc = lane & 3;
  int rowBase = blockIdx.y * 64;
  const float* W = (blockIdx.x == 0) ? qw : (blockIdx.x == 1) ? kw : (blockIdx.x == 2) ? vw : gw;

  // stage A rows as fp32 (coalesced)
  #pragma unroll
  for (int i = 0; i < 8; i++) {
    int idx = tid + i * 256;                  // 2048 float4
    int r = idx >> 5, f = idx & 31;
    float4 v = ((const float4*)(pair + (size_t)(rowBase + r) * CZ))[f];
    float* d = Asf + r * LDA + f * 4;
    d[0] = v.x; d[1] = v.y; d[2] = v.z; d[3] = v.w;
  }
  // B load + tf32
  #pragma unroll
  for (int i = 0; i < 16; i++) {
    int idx = tid + i * 256;                  // 4096 float4
    int k = idx >> 5, f = idx & 31;
    float4 v = ((const float4*)(W + (size_t)k * 128))[f];
    uint32_t* d = Bs + k * LDA + f * 4;
    d[0] = f2tf32(v.x); d[1] = f2tf32(v.y); d[2] = f2tf32(v.z); d[3] = f2tf32(v.w);
  }
  __syncthreads();

  // in-place LayerNorm per row (warp-per-row), write tf32 bits
  float plsv[4], plov[4];
  #pragma unroll
  for (int m = 0; m < 4; m++) { plsv[m] = pls[lane + 32 * m]; plov[m] = plo[lane + 32 * m]; }
  for (int r = wid; r < 64; r += 8) {
    float x[4];
    float s = 0.f, s2 = 0.f;
    #pragma unroll
    for (int m = 0; m < 4; m++) {
      x[m] = Asf[r * LDA + lane + 32 * m];
      s += x[m]; s2 += x[m] * x[m];
    }
    #pragma unroll
    for (int o = 16; o; o >>= 1) { s += __shfl_xor_sync(~0u, s, o); s2 += __shfl_xor_sync(~0u, s2, o); }
    float mean = s * (1.f / CZ);
    float var  = s2 * (1.f / CZ) - mean * mean;
    float rstd = rsqrtf(var + 1e-5f);
    #pragma unroll
    for (int m = 0; m < 4; m++)
      As[r * LDA + lane + 32 * m] = f2tf32((x[m] - mean) * rstd * plsv[m] + plov[m]);
  }
  __syncthreads();

  float acc[2][4][4];
  #pragma unroll
  for (int i = 0; i < 2; i++)
    #pragma unroll
    for (int j = 0; j < 4; j++)
      #pragma unroll
      for (int e = 0; e < 4; e++) acc[i][j][e] = 0.f;

  #pragma unroll 4
  for (int kk = 0; kk < 16; kk++) {
    int k0 = kk * 8;
    uint32_t af[2][4], bf[4][2];
    #pragma unroll
    for (int i = 0; i < 2; i++) {
      int row = wm * 32 + i * 16 + qr;
      af[i][0] = As[row * LDA + k0 + qc];
      af[i][1] = As[(row + 8) * LDA + k0 + qc];
      af[i][2] = As[row * LDA + k0 + qc + 4];
      af[i][3] = As[(row + 8) * LDA + k0 + qc + 4];
    }
    #pragma unroll
    for (int j = 0; j < 4; j++) {
      int col = wn * 32 + j * 8 + qr;
      bf[j][0] = Bs[(k0 + qc) * LDA + col];
      bf[j][1] = Bs[(k0 + qc + 4) * LDA + col];
    }
    #pragma unroll
    for (int i = 0; i < 2; i++)
      #pragma unroll
      for (int j = 0; j < 4; j++)
        mma_tf32(acc[i][j], af[i], bf[j]);
  }

  int colBase = blockIdx.x * 128;
  #pragma unroll
  for (int i = 0; i < 2; i++) {
    int row0 = rowBase + wm * 32 + i * 16 + qr;
    #pragma unroll
    for (int j = 0; j < 4; j++) {
      int col = colBase + wn * 32 + j * 8 + qc * 2;
      *(float2*)(g_qkvg + (size_t)row0 * 512 + col)       = make_float2(acc[i][j][0], acc[i][j][1]);
      *(float2*)(g_qkvg + (size_t)(row0 + 8) * 512 + col) = make_float2(acc[i][j][2], acc[i][j][3]);
    }
  }
}

// ---------------- K3: attention on mma tf32 (per h, b; qtile loop inside) -------
// grid (4, 320) = (h, b); 512 threads (16 warps). K/V staged once, reused 5x.
#define QS_P 36
#define KT_P 328
#define VS_P 40
#define PS_P 332
#define K3_QS   0
#define K3_KT   (64*QS_P)
#define K3_VS   (K3_KT + 32*KT_P)
#define K3_PS   (K3_VS + 320*VS_P)
#define K3_BIAS (K3_PS + 64*PS_P)
#define K3_FLOATS (K3_BIAS + 320)

__global__ __launch_bounds__(512) void k3_attn(const float* __restrict__ mask) {
  extern __shared__ uint32_t sm3[];
  uint32_t* Qs = sm3 + K3_QS;
  uint32_t* Kt = sm3 + K3_KT;
  uint32_t* Vs = sm3 + K3_VS;
  uint32_t* Ps = sm3 + K3_PS;      // fp32 S, then tf32 P
  float*    Psf = (float*)Ps;
  float*    bias_s = (float*)(sm3 + K3_BIAS);

  int h = blockIdx.x, b = blockIdx.y;
  int tid = threadIdx.x, wid = tid >> 5, lane = tid & 31;
  int qr = lane >> 2, qc = lane & 3;

  // ---- stage K^T, V (tf32), bias: once per block ----
  #pragma unroll 4
  for (int i = 0; i < 20; i++) {
    int e = tid + i * 512;
    int key = e >> 5, c = e & 31;
    size_t rb = (size_t)(b * 320 + key) * 512 + h * 32;
    Kt[c * KT_P + key] = f2tf32(g_qkvg[rb + 128 + c]);
    Vs[key * VS_P + c] = f2tf32(g_qkvg[rb + 256 + c]);
  }
  for (int e = tid; e < 320; e += 512) bias_s[e] = 1e9f * (mask[b * 320 + e] - 1.f);
  __syncthreads();

  const float scl = 0.17677669529663687f;

  for (int qt = 0; qt < 5; qt++) {
    int q0 = qt * 64;

    // ---- Q tile (tf32) ----
    #pragma unroll
    for (int i = 0; i < 4; i++) {
      int e = tid + i * 512;
      int row = e >> 5, c = e & 31;
      Qs[row * QS_P + c] = f2tf32(g_qkvg[(size_t)(b * 320 + q0 + row) * 512 + h * 32 + c]);
    }
    __syncthreads();

    // ---- QK^T: warp grid 2x8; warp tile 32 rows x 40 cols ----
    {
      int wm = wid >> 3, wn = wid & 7;
      float acc[2][5][4];
      #pragma unroll
      for (int i = 0; i < 2; i++)
        #pragma unroll
        for (int j = 0; j < 5; j++)
          #pragma unroll
          for (int e = 0; e < 4; e++) acc[i][j][e] = 0.f;

      #pragma unroll
      for (int cs = 0; cs < 4; cs++) {
        int c0 = cs * 8;
        uint32_t af[2][4], bf[5][2];
        #pragma unroll
        for (int i = 0; i < 2; i++) {
          int row = wm * 32 + i * 16 + qr;
          af[i][0] = Qs[row * QS_P + c0 + qc];
          af[i][1] = Qs[(row + 8) * QS_P + c0 + qc];
          af[i][2] = Qs[row * QS_P + c0 + qc + 4];
          af[i][3] = Qs[(row + 8) * QS_P + c0 + qc + 4];
        }
        #pragma unroll
        for (int j = 0; j < 5; j++) {
          int col = wn * 40 + j * 8 + qr;
          bf[j][0] = Kt[(c0 + qc) * KT_P + col];
          bf[j][1] = Kt[(c0 + qc + 4) * KT_P + col];
        }
        #pragma unroll
        for (int i = 0; i < 2; i++)
          #pragma unroll
          for (int j = 0; j < 5; j++)
            mma_tf32(acc[i][j], af[i], bf[j]);
      }
      #pragma unroll
      for (int i = 0; i < 2; i++) {
        int row = wm * 32 + i * 16 + qr;
        #pragma unroll
        for (int j = 0; j < 5; j++) {
          int col = wn * 40 + j * 8 + qc * 2;
          *(float2*)(Psf + row * PS_P + col)       = make_float2(acc[i][j][0], acc[i][j][1]);
          *(float2*)(Psf + (row + 8) * PS_P + col) = make_float2(acc[i][j][2], acc[i][j][3]);
        }
      }
    }
    __syncthreads();

    // ---- softmax: warp per 4 rows ----
    #pragma unroll
    for (int rr = 0; rr < 4; rr++) {
      int r = wid * 4 + rr;
      const float* nbrow = g_nb + (size_t)h * NN + (size_t)(q0 + r) * 320;
      float v[10];
      float mx = -3.0e38f;
      #pragma unroll
      for (int t = 0; t < 10; t++) {
        int k = lane + 32 * t;
        v[t] = Psf[r * PS_P + k] * scl + bias_s[k] + __ldg(nbrow + k);
        mx = fmaxf(mx, v[t]);
      }
      #pragma unroll
      for (int o = 16; o; o >>= 1) mx = fmaxf(mx, __shfl_xor_sync(~0u, mx, o));
      float ssum = 0.f;
      #pragma unroll
      for (int t = 0; t < 10; t++) { v[t] = __expf(v[t] - mx); ssum += v[t]; }
      #pragma unroll
      for (int o = 16; o; o >>= 1) ssum += __shfl_xor_sync(~0u, ssum, o);
      float inv = 1.f / ssum;
      #pragma unroll
      for (int t = 0; t < 10; t++) Ps[r * PS_P + lane + 32 * t] = f2tf32(v[t] * inv);
    }
    __syncthreads();

    // ---- AV: warp grid 4x4; warp tile 16 rows x 8 cols ----
    {
      int wm2 = wid >> 2, wn2 = wid & 3;
      float acc[4] = {0.f, 0.f, 0.f, 0.f};
      #pragma unroll 8
      for (int ks = 0; ks < 40; ks++) {
        int k0 = ks * 8;
        uint32_t af[4], bf[2];
        int row = wm2 * 16 + qr;
        af[0] = Ps[row * PS_P + k0 + qc];
        af[1] = Ps[(row + 8) * PS_P + k0 + qc];
        af[2] = Ps[row * PS_P + k0 + qc + 4];
        af[3] = Ps[(row + 8) * PS_P + k0 + qc + 4];
        int col = wn2 * 8 + qr;
        bf[0] = Vs[(k0 + qc) * VS_P + col];
        bf[1] = Vs[(k0 + qc + 4) * VS_P + col];
        mma_tf32(acc, af, bf);
      }
      int row = b * 320 + q0 + wm2 * 16 + qr;
      int col = h * 32 + wn2 * 8 + qc * 2;
      *(float2*)(g_wa + (size_t)row * 128 + col)       = make_float2(acc[0], acc[1]);
      *(float2*)(g_wa + (size_t)(row + 8) * 128 + col) = make_float2(acc[2], acc[3]);
    }
    __syncthreads();
  }
}

// ---------------- K4: gate*sigmoid fused + output proj (mma tf32) ---------------
// grid 1600, 256 threads, 64-row tiles, 2 CTAs/SM.
__global__ __launch_bounds__(256) void k4_mma(const float* __restrict__ ow, float* __restrict__ out) {
  extern __shared__ uint32_t sm4[];
  uint32_t* As = sm4;               // [64][LDA]
  uint32_t* Bs = sm4 + 64 * LDA;    // [128][LDA]

  int tid = threadIdx.x, wid = tid >> 5, lane = tid & 31;
  int wm = wid >> 2, wn = wid & 3;
  int qr = lane >> 2, qc = lane & 3;
  int rowBase = blockIdx.x * 64;

  #pragma unroll
  for (int i = 0; i < 8; i++) {
    int idx = tid + i * 256;
    int r = idx >> 5, f = idx & 31;
    int row = rowBase + r;
    float4 a  = ((const float4*)(g_wa + (size_t)row * CZ))[f];
    float4 gt = ((const float4*)(g_qkvg + (size_t)row * 512 + 384))[f];
    a.x *= 1.f / (1.f + __expf(-gt.x));
    a.y *= 1.f / (1.f + __expf(-gt.y));
    a.z *= 1.f / (1.f + __expf(-gt.z));
    a.w *= 1.f / (1.f + __expf(-gt.w));
    uint32_t* d = As + r * LDA + f * 4;
    d[0] = f2tf32(a.x); d[1] = f2tf32(a.y); d[2] = f2tf32(a.z); d[3] = f2tf32(a.w);
  }
  #pragma unroll
  for (int i = 0; i < 16; i++) {
    int idx = tid + i * 256;
    int k = idx >> 5, f = idx & 31;
    float4 v = ((const float4*)(ow + (size_t)k * 128))[f];
    uint32_t* d = Bs + k * LDA + f * 4;
    d[0] = f2tf32(v.x); d[1] = f2tf32(v.y); d[2] = f2tf32(v.z); d[3] = f2tf32(v.w);
  }
  __syncthreads();

  float acc[2][4][4];
  #pragma unroll
  for (int i = 0; i < 2; i++)
    #pragma unroll
    for (int j = 0; j < 4; j++)
      #pragma unroll
      for (int e = 0; e < 4; e++) acc[i][j][e] = 0.f;

  #pragma unroll 4
  for (int kk = 0; kk < 16; kk++) {
    int k0 = kk * 8;
    uint32_t af[2][4], bf[4][2];
    #pragma unroll
    for (int i = 0; i < 2; i++) {
      int row = wm * 32 + i * 16 + qr;
      af[i][0] = As[row * LDA + k0 + qc];
      af[i][1] = As[(row + 8) * LDA + k0 + qc];
      af[i][2] = As[row * LDA + k0 + qc + 4];
      af[i][3] = As[(row + 8) * LDA + k0 + qc + 4];
    }
    #pragma unroll
    for (int j = 0; j < 4; j++) {
      int col = wn * 32 + j * 8 + qr;
      bf[j][0] = Bs[(k0 + qc) * LDA + col];
      bf[j][1] = Bs[(k0 + qc + 4) * LDA + col];
    }
    #pragma unroll
    for (int i = 0; i < 2; i++)
      #pragma unroll
      for (int j = 0; j < 4; j++)
        mma_tf32(acc[i][j], af[i], bf[j]);
  }

  #pragma unroll
  for (int i = 0; i < 2; i++) {
    int row0 = rowBase + wm * 32 + i * 16 + qr;
    #pragma unroll
    for (int j = 0; j < 4; j++) {
      int col = wn * 32 + j * 8 + qc * 2;
      *(float2*)(out + (size_t)row0 * CZ + col)       = make_float2(acc[i][j][0], acc[i][j][1]);
      *(float2*)(out + (size_t)(row0 + 8) * CZ + col) = make_float2(acc[i][j][2], acc[i][j][3]);
    }
  }
}

// ---------------- launch --------------------------------------------------------
extern "C" void kernel_launch(void* const* d_in, const int* in_sizes, int n_in,
                              void* d_out, int out_size) {
  const float* pair    = (const float*)d_in[0];
  const float* affine  = (const float*)d_in[1];
  const float* mask    = (const float*)d_in[2];
  const float* pls     = (const float*)d_in[3];
  const float* plo     = (const float*)d_in[4];
  const float* als     = (const float*)d_in[5];
  const float* alo     = (const float*)d_in[6];
  const float* f2d     = (const float*)d_in[7];
  const float* qw      = (const float*)d_in[8];
  const float* kw      = (const float*)d_in[9];
  const float* vw      = (const float*)d_in[10];
  const float* gw      = (const float*)d_in[11];
  const float* ow      = (const float*)d_in[12];
  float* out = (float*)d_out;

  const int gemm_smem = (64 + 128) * LDA * 4;   // 101376 B -> 2 CTAs/SM
  const int k3_smem = K3_FLOATS * 4;            // 188672 B
  cudaFuncSetAttribute(k2_mma, cudaFuncAttributeMaxDynamicSharedMemorySize, gemm_smem);
  cudaFuncSetAttribute(k4_mma, cudaFuncAttributeMaxDynamicSharedMemorySize, gemm_smem);
  cudaFuncSetAttribute(k3_attn, cudaFuncAttributeMaxDynamicSharedMemorySize, k3_smem);

  k1_nb<<<NN, 128>>>(affine, als, alo, f2d);
  k2_mma<<<dim3(4, NN / 64), 256, gemm_smem>>>(pair, pls, plo, qw, kw, vw, gw);
  k3_attn<<<dim3(NH, N_RES), 512, k3_smem>>>(mask);
  k4_mma<<<NN / 64, 256, gemm_smem>>>(ow, out);
}

// round 7
// speedup vs baseline: 2.6419x; 1.1768x over previous
#include <cuda_runtime.h>
#include <cstdint>
#include <math.h>

#define N_RES 320
#define CZ 128
#define NH 4
#define HD 32
#define NN (N_RES*N_RES)   /* 102400 */

// ---------------- scratch (static device globals; no allocation) ----------------
__device__ float g_qkvg[(size_t)NN*512];     // 209.7 MB : [row][kind*128 + h*32 + d]
__device__ float g_nb[(size_t)NH*NN];        // 1.6 MB   : [h][q*320+k]
__device__ float g_wa[(size_t)NN*CZ];        // 52.4 MB  : weighted_avg [row][h*32+d]
// fragment-ordered tf32 weights: [kind(5)][kk(16)][wn(4)][j(4)][lane(32)] float2
__device__ float2 g_bf[5][16][4][4][32];     // 320 KB, L2-resident

__device__ __forceinline__ uint32_t f2tf32(float x) {
  uint32_t r; asm("cvt.rna.tf32.f32 %0, %1;" : "=r"(r) : "f"(x)); return r;
}
__device__ __forceinline__ void mma_tf32(float* c, const uint32_t* a, const uint32_t* b) {
  asm volatile("mma.sync.aligned.m16n8k8.row.col.f32.tf32.tf32.f32 "
               "{%0,%1,%2,%3}, {%4,%5,%6,%7}, {%8,%9}, {%0,%1,%2,%3};"
               : "+f"(c[0]), "+f"(c[1]), "+f"(c[2]), "+f"(c[3])
               : "r"(a[0]), "r"(a[1]), "r"(a[2]), "r"(a[3]), "r"(b[0]), "r"(b[1]));
}

#define LDA 132   /* padded stride (floats) for 128-wide smem tiles */

// ---------------- K0: weight -> fragment-order tf32 prep (runs once per call) ---
// grid 80 = 5 kinds x 16 kk; 512 threads = wn(4) x j(4) x lane(32)
__global__ void k0_prep(const float* __restrict__ qw, const float* __restrict__ kw,
                        const float* __restrict__ vw, const float* __restrict__ gw,
                        const float* __restrict__ ow) {
  int kind = blockIdx.x >> 4, kk = blockIdx.x & 15;
  const float* W = (kind == 0) ? qw : (kind == 1) ? kw : (kind == 2) ? vw : (kind == 3) ? gw : ow;
  int t = threadIdx.x;
  int wn = t >> 7, j = (t >> 5) & 3, lane = t & 31;
  int qr = lane >> 2, qc = lane & 3;
  int col = wn * 32 + j * 8 + qr;
  int k0 = kk * 8;
  float2 v;
  v.x = __uint_as_float(f2tf32(W[(k0 + qc) * 128 + col]));
  v.y = __uint_as_float(f2tf32(W[(k0 + qc + 4) * 128 + col]));
  g_bf[kind][kk][wn][j][lane] = v;
}

// ---------------- K1: LayerNorm(affine) + nonbatched bias ------------------------
__global__ void k1_nb(const float* __restrict__ affine,
                      const float* __restrict__ als, const float* __restrict__ alo,
                      const float* __restrict__ f2d) {
  int row = blockIdx.x;
  int t = threadIdx.x, w = t >> 5, l = t & 31;
  __shared__ float sh[16];
  size_t base = (size_t)row * CZ + t;

  float a = affine[base];
  float s = a, s2 = a * a;
  #pragma unroll
  for (int o = 16; o; o >>= 1) { s += __shfl_xor_sync(~0u, s, o); s2 += __shfl_xor_sync(~0u, s2, o); }
  if (l == 0) { sh[w] = s; sh[4 + w] = s2; }
  __syncthreads();
  float sum  = sh[0] + sh[1] + sh[2] + sh[3];
  float sum2 = sh[4] + sh[5] + sh[6] + sh[7];
  float mean = sum * (1.f / CZ);
  float var  = sum2 * (1.f / CZ) - mean * mean;
  float aln = (a - mean) * rsqrtf(var + 1e-5f) * als[t] + alo[t];

  float p0 = aln * f2d[t * 4 + 0];
  float p1 = aln * f2d[t * 4 + 1];
  float p2 = aln * f2d[t * 4 + 2];
  float p3 = aln * f2d[t * 4 + 3];
  #pragma unroll
  for (int o = 16; o; o >>= 1) {
    p0 += __shfl_xor_sync(~0u, p0, o);
    p1 += __shfl_xor_sync(~0u, p1, o);
    p2 += __shfl_xor_sync(~0u, p2, o);
    p3 += __shfl_xor_sync(~0u, p3, o);
  }
  __syncthreads();
  if (l == 0) { sh[w*4+0] = p0; sh[w*4+1] = p1; sh[w*4+2] = p2; sh[w*4+3] = p3; }
  __syncthreads();
  if (t < 4) {
    g_nb[(size_t)t * NN + row] = sh[0*4+t] + sh[1*4+t] + sh[2*4+t] + sh[3*4+t];
  }
}

// ---------------- K2: fused pair-LN + all-4-kind QKVG projection ----------------
// grid 1600 (64-row tiles); 256 threads; smem = A only (33.8KB) -> 4 CTAs/SM.
__global__ __launch_bounds__(256) void k2_mma(const float* __restrict__ pair,
                                              const float* __restrict__ pls,
                                              const float* __restrict__ plo) {
  extern __shared__ uint32_t sm2[];
  uint32_t* As = sm2;               // [64][LDA]
  float* Asf = (float*)As;

  int tid = threadIdx.x, wid = tid >> 5, lane = tid & 31;
  int wm = wid >> 2, wn = wid & 3;            // warp grid 2x4
  int qr = lane >> 2, qc = lane & 3;
  int rowBase = blockIdx.x * 64;

  // stage A rows as fp32 (coalesced)
  #pragma unroll
  for (int i = 0; i < 8; i++) {
    int idx = tid + i * 256;                  // 2048 float4
    int r = idx >> 5, f = idx & 31;
    float4 v = ((const float4*)(pair + (size_t)(rowBase + r) * CZ))[f];
    float* d = Asf + r * LDA + f * 4;
    d[0] = v.x; d[1] = v.y; d[2] = v.z; d[3] = v.w;
  }
  __syncthreads();

  // in-place LayerNorm per row (warp-per-row), write tf32 bits
  float plsv[4], plov[4];
  #pragma unroll
  for (int m = 0; m < 4; m++) { plsv[m] = pls[lane + 32 * m]; plov[m] = plo[lane + 32 * m]; }
  for (int r = wid; r < 64; r += 8) {
    float x[4];
    float s = 0.f, s2 = 0.f;
    #pragma unroll
    for (int m = 0; m < 4; m++) {
      x[m] = Asf[r * LDA + lane + 32 * m];
      s += x[m]; s2 += x[m] * x[m];
    }
    #pragma unroll
    for (int o = 16; o; o >>= 1) { s += __shfl_xor_sync(~0u, s, o); s2 += __shfl_xor_sync(~0u, s2, o); }
    float mean = s * (1.f / CZ);
    float var  = s2 * (1.f / CZ) - mean * mean;
    float rstd = rsqrtf(var + 1e-5f);
    #pragma unroll
    for (int m = 0; m < 4; m++)
      As[r * LDA + lane + 32 * m] = f2tf32((x[m] - mean) * rstd * plsv[m] + plov[m]);
  }
  __syncthreads();

  // loop over the 4 weight kinds; B fragments straight from L2
  for (int kind = 0; kind < 4; kind++) {
    float acc[2][4][4];
    #pragma unroll
    for (int i = 0; i < 2; i++)
      #pragma unroll
      for (int j = 0; j < 4; j++)
        #pragma unroll
        for (int e = 0; e < 4; e++) acc[i][j][e] = 0.f;

    #pragma unroll 4
    for (int kk = 0; kk < 16; kk++) {
      int k0 = kk * 8;
      uint32_t af[2][4];
      #pragma unroll
      for (int i = 0; i < 2; i++) {
        int row = wm * 32 + i * 16 + qr;
        af[i][0] = As[row * LDA + k0 + qc];
        af[i][1] = As[(row + 8) * LDA + k0 + qc];
        af[i][2] = As[row * LDA + k0 + qc + 4];
        af[i][3] = As[(row + 8) * LDA + k0 + qc + 4];
      }
      #pragma unroll
      for (int j = 0; j < 4; j++) {
        float2 b2 = g_bf[kind][kk][wn][j][lane];
        uint32_t bf[2] = { __float_as_uint(b2.x), __float_as_uint(b2.y) };
        #pragma unroll
        for (int i = 0; i < 2; i++)
          mma_tf32(acc[i][j], af[i], bf);
      }
    }

    int colBase = kind * 128;
    #pragma unroll
    for (int i = 0; i < 2; i++) {
      int row0 = rowBase + wm * 32 + i * 16 + qr;
      #pragma unroll
      for (int j = 0; j < 4; j++) {
        int col = colBase + wn * 32 + j * 8 + qc * 2;
        *(float2*)(g_qkvg + (size_t)row0 * 512 + col)       = make_float2(acc[i][j][0], acc[i][j][1]);
        *(float2*)(g_qkvg + (size_t)(row0 + 8) * 512 + col) = make_float2(acc[i][j][2], acc[i][j][3]);
      }
    }
  }
}

// ---------------- K3: attention on mma tf32 (per h, b; qtile loop inside) -------
// grid (4, 320) = (h, b); 512 threads (16 warps). K/V staged once, reused 5x.
#define QS_P 36
#define KT_P 328
#define VS_P 40
#define PS_P 332
#define K3_QS   0
#define K3_KT   (64*QS_P)
#define K3_VS   (K3_KT + 32*KT_P)
#define K3_PS   (K3_VS + 320*VS_P)
#define K3_BIAS (K3_PS + 64*PS_P)
#define K3_FLOATS (K3_BIAS + 320)

__global__ __launch_bounds__(512) void k3_attn(const float* __restrict__ mask) {
  extern __shared__ uint32_t sm3[];
  uint32_t* Qs = sm3 + K3_QS;
  uint32_t* Kt = sm3 + K3_KT;
  uint32_t* Vs = sm3 + K3_VS;
  uint32_t* Ps = sm3 + K3_PS;      // fp32 S, then tf32 P
  float*    Psf = (float*)Ps;
  float*    bias_s = (float*)(sm3 + K3_BIAS);

  int h = blockIdx.x, b = blockIdx.y;
  int tid = threadIdx.x, wid = tid >> 5, lane = tid & 31;
  int qr = lane >> 2, qc = lane & 3;

  // ---- stage K^T, V (tf32), bias: once per block ----
  #pragma unroll 4
  for (int i = 0; i < 20; i++) {
    int e = tid + i * 512;
    int key = e >> 5, c = e & 31;
    size_t rb = (size_t)(b * 320 + key) * 512 + h * 32;
    Kt[c * KT_P + key] = f2tf32(g_qkvg[rb + 128 + c]);
    Vs[key * VS_P + c] = f2tf32(g_qkvg[rb + 256 + c]);
  }
  for (int e = tid; e < 320; e += 512) bias_s[e] = 1e9f * (mask[b * 320 + e] - 1.f);
  __syncthreads();

  const float scl = 0.17677669529663687f;

  for (int qt = 0; qt < 5; qt++) {
    int q0 = qt * 64;

    // ---- Q tile (tf32) ----
    #pragma unroll
    for (int i = 0; i < 4; i++) {
      int e = tid + i * 512;
      int row = e >> 5, c = e & 31;
      Qs[row * QS_P + c] = f2tf32(g_qkvg[(size_t)(b * 320 + q0 + row) * 512 + h * 32 + c]);
    }
    __syncthreads();

    // ---- QK^T: warp grid 2x8; warp tile 32 rows x 40 cols ----
    {
      int wm = wid >> 3, wn = wid & 7;
      float acc[2][5][4];
      #pragma unroll
      for (int i = 0; i < 2; i++)
        #pragma unroll
        for (int j = 0; j < 5; j++)
          #pragma unroll
          for (int e = 0; e < 4; e++) acc[i][j][e] = 0.f;

      #pragma unroll
      for (int cs = 0; cs < 4; cs++) {
        int c0 = cs * 8;
        uint32_t af[2][4], bf[5][2];
        #pragma unroll
        for (int i = 0; i < 2; i++) {
          int row = wm * 32 + i * 16 + qr;
          af[i][0] = Qs[row * QS_P + c0 + qc];
          af[i][1] = Qs[(row + 8) * QS_P + c0 + qc];
          af[i][2] = Qs[row * QS_P + c0 + qc + 4];
          af[i][3] = Qs[(row + 8) * QS_P + c0 + qc + 4];
        }
        #pragma unroll
        for (int j = 0; j < 5; j++) {
          int col = wn * 40 + j * 8 + qr;
          bf[j][0] = Kt[(c0 + qc) * KT_P + col];
          bf[j][1] = Kt[(c0 + qc + 4) * KT_P + col];
        }
        #pragma unroll
        for (int i = 0; i < 2; i++)
          #pragma unroll
          for (int j = 0; j < 5; j++)
            mma_tf32(acc[i][j], af[i], bf[j]);
      }
      #pragma unroll
      for (int i = 0; i < 2; i++) {
        int row = wm * 32 + i * 16 + qr;
        #pragma unroll
        for (int j = 0; j < 5; j++) {
          int col = wn * 40 + j * 8 + qc * 2;
          *(float2*)(Psf + row * PS_P + col)       = make_float2(acc[i][j][0], acc[i][j][1]);
          *(float2*)(Psf + (row + 8) * PS_P + col) = make_float2(acc[i][j][2], acc[i][j][3]);
        }
      }
    }
    __syncthreads();

    // ---- softmax: warp per 4 rows ----
    #pragma unroll
    for (int rr = 0; rr < 4; rr++) {
      int r = wid * 4 + rr;
      const float* nbrow = g_nb + (size_t)h * NN + (size_t)(q0 + r) * 320;
      float v[10];
      float mx = -3.0e38f;
      #pragma unroll
      for (int t = 0; t < 10; t++) {
        int k = lane + 32 * t;
        v[t] = Psf[r * PS_P + k] * scl + bias_s[k] + __ldg(nbrow + k);
        mx = fmaxf(mx, v[t]);
      }
      #pragma unroll
      for (int o = 16; o; o >>= 1) mx = fmaxf(mx, __shfl_xor_sync(~0u, mx, o));
      float ssum = 0.f;
      #pragma unroll
      for (int t = 0; t < 10; t++) { v[t] = __expf(v[t] - mx); ssum += v[t]; }
      #pragma unroll
      for (int o = 16; o; o >>= 1) ssum += __shfl_xor_sync(~0u, ssum, o);
      float inv = 1.f / ssum;
      #pragma unroll
      for (int t = 0; t < 10; t++) Ps[r * PS_P + lane + 32 * t] = f2tf32(v[t] * inv);
    }
    __syncthreads();

    // ---- AV: warp grid 4x4; warp tile 16 rows x 8 cols ----
    {
      int wm2 = wid >> 2, wn2 = wid & 3;
      float acc[4] = {0.f, 0.f, 0.f, 0.f};
      #pragma unroll 8
      for (int ks = 0; ks < 40; ks++) {
        int k0 = ks * 8;
        uint32_t af[4], bf[2];
        int row = wm2 * 16 + qr;
        af[0] = Ps[row * PS_P + k0 + qc];
        af[1] = Ps[(row + 8) * PS_P + k0 + qc];
        af[2] = Ps[row * PS_P + k0 + qc + 4];
        af[3] = Ps[(row + 8) * PS_P + k0 + qc + 4];
        int col = wn2 * 8 + qr;
        bf[0] = Vs[(k0 + qc) * VS_P + col];
        bf[1] = Vs[(k0 + qc + 4) * VS_P + col];
        mma_tf32(acc, af, bf);
      }
      int row = b * 320 + q0 + wm2 * 16 + qr;
      int col = h * 32 + wn2 * 8 + qc * 2;
      *(float2*)(g_wa + (size_t)row * 128 + col)       = make_float2(acc[0], acc[1]);
      *(float2*)(g_wa + (size_t)(row + 8) * 128 + col) = make_float2(acc[2], acc[3]);
    }
    __syncthreads();
  }
}

// ---------------- K4: gate*sigmoid fused + output proj (B frags from L2) --------
// grid 1600, 256 threads, 64-row tiles, smem = A only -> 4 CTAs/SM.
__global__ __launch_bounds__(256) void k4_mma(float* __restrict__ out) {
  extern __shared__ uint32_t sm4[];
  uint32_t* As = sm4;               // [64][LDA]

  int tid = threadIdx.x, wid = tid >> 5, lane = tid & 31;
  int wm = wid >> 2, wn = wid & 3;
  int qr = lane >> 2, qc = lane & 3;
  int rowBase = blockIdx.x * 64;

  #pragma unroll
  for (int i = 0; i < 8; i++) {
    int idx = tid + i * 256;
    int r = idx >> 5, f = idx & 31;
    int row = rowBase + r;
    float4 a  = ((const float4*)(g_wa + (size_t)row * CZ))[f];
    float4 gt = ((const float4*)(g_qkvg + (size_t)row * 512 + 384))[f];
    a.x *= 1.f / (1.f + __expf(-gt.x));
    a.y *= 1.f / (1.f + __expf(-gt.y));
    a.z *= 1.f / (1.f + __expf(-gt.z));
    a.w *= 1.f / (1.f + __expf(-gt.w));
    uint32_t* d = As + r * LDA + f * 4;
    d[0] = f2tf32(a.x); d[1] = f2tf32(a.y); d[2] = f2tf32(a.z); d[3] = f2tf32(a.w);
  }
  __syncthreads();

  float acc[2][4][4];
  #pragma unroll
  for (int i = 0; i < 2; i++)
    #pragma unroll
    for (int j = 0; j < 4; j++)
      #pragma unroll
      for (int e = 0; e < 4; e++) acc[i][j][e] = 0.f;

  #pragma unroll 4
  for (int kk = 0; kk < 16; kk++) {
    int k0 = kk * 8;
    uint32_t af[2][4];
    #pragma unroll
    for (int i = 0; i < 2; i++) {
      int row = wm * 32 + i * 16 + qr;
      af[i][0] = As[row * LDA + k0 + qc];
      af[i][1] = As[(row + 8) * LDA + k0 + qc];
      af[i][2] = As[row * LDA + k0 + qc + 4];
      af[i][3] = As[(row + 8) * LDA + k0 + qc + 4];
    }
    #pragma unroll
    for (int j = 0; j < 4; j++) {
      float2 b2 = g_bf[4][kk][wn][j][lane];
      uint32_t bf[2] = { __float_as_uint(b2.x), __float_as_uint(b2.y) };
      #pragma unroll
      for (int i = 0; i < 2; i++)
        mma_tf32(acc[i][j], af[i], bf);
    }
  }

  #pragma unroll
  for (int i = 0; i < 2; i++) {
    int row0 = rowBase + wm * 32 + i * 16 + qr;
    #pragma unroll
    for (int j = 0; j < 4; j++) {
      int col = wn * 32 + j * 8 + qc * 2;
      *(float2*)(out + (size_t)row0 * CZ + col)       = make_float2(acc[i][j][0], acc[i][j][1]);
      *(float2*)(out + (size_t)(row0 + 8) * CZ + col) = make_float2(acc[i][j][2], acc[i][j][3]);
    }
  }
}

// ---------------- launch --------------------------------------------------------
extern "C" void kernel_launch(void* const* d_in, const int* in_sizes, int n_in,
                              void* d_out, int out_size) {
  const float* pair    = (const float*)d_in[0];
  const float* affine  = (const float*)d_in[1];
  const float* mask    = (const float*)d_in[2];
  const float* pls     = (const float*)d_in[3];
  const float* plo     = (const float*)d_in[4];
  const float* als     = (const float*)d_in[5];
  const float* alo     = (const float*)d_in[6];
  const float* f2d     = (const float*)d_in[7];
  const float* qw      = (const float*)d_in[8];
  const float* kw      = (const float*)d_in[9];
  const float* vw      = (const float*)d_in[10];
  const float* gw      = (const float*)d_in[11];
  const float* ow      = (const float*)d_in[12];
  float* out = (float*)d_out;

  const int a_smem  = 64 * LDA * 4;             // 33792 B -> 4 CTAs/SM
  const int k3_smem = K3_FLOATS * 4;            // 188672 B
  cudaFuncSetAttribute(k2_mma, cudaFuncAttributeMaxDynamicSharedMemorySize, a_smem);
  cudaFuncSetAttribute(k4_mma, cudaFuncAttributeMaxDynamicSharedMemorySize, a_smem);
  cudaFuncSetAttribute(k3_attn, cudaFuncAttributeMaxDynamicSharedMemorySize, k3_smem);

  k0_prep<<<80, 512>>>(qw, kw, vw, gw, ow);
  k1_nb<<<NN, 128>>>(affine, als, alo, f2d);
  k2_mma<<<NN / 64, 256, a_smem>>>(pair, pls, plo);
  k3_attn<<<dim3(NH, N_RES), 512, k3_smem>>>(mask);
  k4_mma<<<NN / 64, 256, a_smem>>>(out);
}

// round 8
// speedup vs baseline: 2.8381x; 1.0743x over previous
#include <cuda_runtime.h>
#include <cstdint>
#include <math.h>

#define N_RES 320
#define CZ 128
#define NH 4
#define HD 32
#define NN (N_RES*N_RES)   /* 102400 */

// ---------------- scratch (static device globals; no allocation) ----------------
__device__ float g_qkvg[(size_t)NN*512];     // 209.7 MB : [row][kind*128 + h*32 + d]
__device__ float g_nb[(size_t)NH*NN];        // 1.6 MB   : [h][q*320+k]
__device__ float g_wa[(size_t)NN*CZ];        // 52.4 MB  : weighted_avg [row][h*32+d]
// fragment-ordered tf32 weights: [kind(5)][kk(16)][wn(4)][j(4)][lane(32)] float2
__device__ float2 g_bf[5][16][4][4][32];     // 320 KB, L2-resident

__device__ __forceinline__ uint32_t f2tf32(float x) {
  uint32_t r; asm("cvt.rna.tf32.f32 %0, %1;" : "=r"(r) : "f"(x)); return r;
}
__device__ __forceinline__ void mma_tf32(float* c, const uint32_t* a, const uint32_t* b) {
  asm volatile("mma.sync.aligned.m16n8k8.row.col.f32.tf32.tf32.f32 "
               "{%0,%1,%2,%3}, {%4,%5,%6,%7}, {%8,%9}, {%0,%1,%2,%3};"
               : "+f"(c[0]), "+f"(c[1]), "+f"(c[2]), "+f"(c[3])
               : "r"(a[0]), "r"(a[1]), "r"(a[2]), "r"(a[3]), "r"(b[0]), "r"(b[1]));
}

#define LDA 132   /* padded stride (floats) for 128-wide smem tiles */

// ---------------- K0: weight -> fragment-order tf32 prep ------------------------
__global__ void k0_prep(const float* __restrict__ qw, const float* __restrict__ kw,
                        const float* __restrict__ vw, const float* __restrict__ gw,
                        const float* __restrict__ ow) {
  int kind = blockIdx.x >> 4, kk = blockIdx.x & 15;
  const float* W = (kind == 0) ? qw : (kind == 1) ? kw : (kind == 2) ? vw : (kind == 3) ? gw : ow;
  int t = threadIdx.x;
  int wn = t >> 7, j = (t >> 5) & 3, lane = t & 31;
  int qr = lane >> 2, qc = lane & 3;
  int col = wn * 32 + j * 8 + qr;
  int k0 = kk * 8;
  float2 v;
  v.x = __uint_as_float(f2tf32(W[(k0 + qc) * 128 + col]));
  v.y = __uint_as_float(f2tf32(W[(k0 + qc + 4) * 128 + col]));
  g_bf[kind][kk][wn][j][lane] = v;
}

// ---------------- K1: LayerNorm(affine) + nonbatched bias ------------------------
__global__ void k1_nb(const float* __restrict__ affine,
                      const float* __restrict__ als, const float* __restrict__ alo,
                      const float* __restrict__ f2d) {
  int row = blockIdx.x;
  int t = threadIdx.x, w = t >> 5, l = t & 31;
  __shared__ float sh[16];
  size_t base = (size_t)row * CZ + t;

  float a = affine[base];
  float s = a, s2 = a * a;
  #pragma unroll
  for (int o = 16; o; o >>= 1) { s += __shfl_xor_sync(~0u, s, o); s2 += __shfl_xor_sync(~0u, s2, o); }
  if (l == 0) { sh[w] = s; sh[4 + w] = s2; }
  __syncthreads();
  float sum  = sh[0] + sh[1] + sh[2] + sh[3];
  float sum2 = sh[4] + sh[5] + sh[6] + sh[7];
  float mean = sum * (1.f / CZ);
  float var  = sum2 * (1.f / CZ) - mean * mean;
  float aln = (a - mean) * rsqrtf(var + 1e-5f) * als[t] + alo[t];

  float p0 = aln * f2d[t * 4 + 0];
  float p1 = aln * f2d[t * 4 + 1];
  float p2 = aln * f2d[t * 4 + 2];
  float p3 = aln * f2d[t * 4 + 3];
  #pragma unroll
  for (int o = 16; o; o >>= 1) {
    p0 += __shfl_xor_sync(~0u, p0, o);
    p1 += __shfl_xor_sync(~0u, p1, o);
    p2 += __shfl_xor_sync(~0u, p2, o);
    p3 += __shfl_xor_sync(~0u, p3, o);
  }
  __syncthreads();
  if (l == 0) { sh[w*4+0] = p0; sh[w*4+1] = p1; sh[w*4+2] = p2; sh[w*4+3] = p3; }
  __syncthreads();
  if (t < 4) {
    g_nb[(size_t)t * NN + row] = sh[0*4+t] + sh[1*4+t] + sh[2*4+t] + sh[3*4+t];
  }
}

// ---------------- K2: fused pair-LN + all-4-kind QKVG projection ----------------
__global__ __launch_bounds__(256) void k2_mma(const float* __restrict__ pair,
                                              const float* __restrict__ pls,
                                              const float* __restrict__ plo) {
  extern __shared__ uint32_t sm2[];
  uint32_t* As = sm2;               // [64][LDA]
  float* Asf = (float*)As;

  int tid = threadIdx.x, wid = tid >> 5, lane = tid & 31;
  int wm = wid >> 2, wn = wid & 3;            // warp grid 2x4
  int qr = lane >> 2, qc = lane & 3;
  int rowBase = blockIdx.x * 64;

  #pragma unroll
  for (int i = 0; i < 8; i++) {
    int idx = tid + i * 256;
    int r = idx >> 5, f = idx & 31;
    float4 v = ((const float4*)(pair + (size_t)(rowBase + r) * CZ))[f];
    float* d = Asf + r * LDA + f * 4;
    d[0] = v.x; d[1] = v.y; d[2] = v.z; d[3] = v.w;
  }
  __syncthreads();

  float plsv[4], plov[4];
  #pragma unroll
  for (int m = 0; m < 4; m++) { plsv[m] = pls[lane + 32 * m]; plov[m] = plo[lane + 32 * m]; }
  for (int r = wid; r < 64; r += 8) {
    float x[4];
    float s = 0.f, s2 = 0.f;
    #pragma unroll
    for (int m = 0; m < 4; m++) {
      x[m] = Asf[r * LDA + lane + 32 * m];
      s += x[m]; s2 += x[m] * x[m];
    }
    #pragma unroll
    for (int o = 16; o; o >>= 1) { s += __shfl_xor_sync(~0u, s, o); s2 += __shfl_xor_sync(~0u, s2, o); }
    float mean = s * (1.f / CZ);
    float var  = s2 * (1.f / CZ) - mean * mean;
    float rstd = rsqrtf(var + 1e-5f);
    #pragma unroll
    for (int m = 0; m < 4; m++)
      As[r * LDA + lane + 32 * m] = f2tf32((x[m] - mean) * rstd * plsv[m] + plov[m]);
  }
  __syncthreads();

  for (int kind = 0; kind < 4; kind++) {
    float acc[2][4][4];
    #pragma unroll
    for (int i = 0; i < 2; i++)
      #pragma unroll
      for (int j = 0; j < 4; j++)
        #pragma unroll
        for (int e = 0; e < 4; e++) acc[i][j][e] = 0.f;

    #pragma unroll 4
    for (int kk = 0; kk < 16; kk++) {
      int k0 = kk * 8;
      uint32_t af[2][4];
      #pragma unroll
      for (int i = 0; i < 2; i++) {
        int row = wm * 32 + i * 16 + qr;
        af[i][0] = As[row * LDA + k0 + qc];
        af[i][1] = As[(row + 8) * LDA + k0 + qc];
        af[i][2] = As[row * LDA + k0 + qc + 4];
        af[i][3] = As[(row + 8) * LDA + k0 + qc + 4];
      }
      #pragma unroll
      for (int j = 0; j < 4; j++) {
        float2 b2 = g_bf[kind][kk][wn][j][lane];
        uint32_t bf[2] = { __float_as_uint(b2.x), __float_as_uint(b2.y) };
        #pragma unroll
        for (int i = 0; i < 2; i++)
          mma_tf32(acc[i][j], af[i], bf);
      }
    }

    int colBase = kind * 128;
    #pragma unroll
    for (int i = 0; i < 2; i++) {
      int row0 = rowBase + wm * 32 + i * 16 + qr;
      #pragma unroll
      for (int j = 0; j < 4; j++) {
        int col = colBase + wn * 32 + j * 8 + qc * 2;
        *(float2*)(g_qkvg + (size_t)row0 * 512 + col)       = make_float2(acc[i][j][0], acc[i][j][1]);
        *(float2*)(g_qkvg + (size_t)(row0 + 8) * 512 + col) = make_float2(acc[i][j][2], acc[i][j][3]);
      }
    }
  }
}

// ---------------- K3: attention, 1024 threads (32 warps), per (h,b) -------------
#define QS_P 36
#define KT_P 328
#define VS_P 40
#define PS_P 332
#define K3_QS   0
#define K3_KT   (64*QS_P)
#define K3_VS   (K3_KT + 32*KT_P)
#define K3_PS   (K3_VS + 320*VS_P)
#define K3_BIAS (K3_PS + 64*PS_P)
#define K3_FLOATS (K3_BIAS + 320)

__global__ __launch_bounds__(1024) void k3_attn(const float* __restrict__ mask) {
  extern __shared__ uint32_t sm3[];
  uint32_t* Qs = sm3 + K3_QS;
  uint32_t* Kt = sm3 + K3_KT;
  uint32_t* Vs = sm3 + K3_VS;
  uint32_t* Ps = sm3 + K3_PS;      // fp32 S, then tf32 P
  float*    Psf = (float*)Ps;
  float*    bias_s = (float*)(sm3 + K3_BIAS);

  int h = blockIdx.x, b = blockIdx.y;
  int tid = threadIdx.x, wid = tid >> 5, lane = tid & 31;
  int qr = lane >> 2, qc = lane & 3;

  // ---- stage K^T, V (tf32), bias: once per block ----
  #pragma unroll 2
  for (int i = 0; i < 10; i++) {
    int e = tid + i * 1024;
    int key = e >> 5, c = e & 31;
    size_t rb = (size_t)(b * 320 + key) * 512 + h * 32;
    Kt[c * KT_P + key] = f2tf32(g_qkvg[rb + 128 + c]);
    Vs[key * VS_P + c] = f2tf32(g_qkvg[rb + 256 + c]);
  }
  if (tid < 320) bias_s[tid] = 1e9f * (mask[b * 320 + tid] - 1.f);
  __syncthreads();

  const float scl = 0.17677669529663687f;

  for (int qt = 0; qt < 5; qt++) {
    int q0 = qt * 64;

    // ---- Q tile (tf32) ----
    #pragma unroll
    for (int i = 0; i < 2; i++) {
      int e = tid + i * 1024;
      int row = e >> 5, c = e & 31;
      Qs[row * QS_P + c] = f2tf32(g_qkvg[(size_t)(b * 320 + q0 + row) * 512 + h * 32 + c]);
    }
    __syncthreads();

    // ---- QK^T: warp grid 4x8; warp tile 16 rows x 40 cols ----
    {
      int wm = wid >> 3, wn = wid & 7;
      float acc[5][4];
      #pragma unroll
      for (int j = 0; j < 5; j++)
        #pragma unroll
        for (int e = 0; e < 4; e++) acc[j][e] = 0.f;

      #pragma unroll
      for (int cs = 0; cs < 4; cs++) {
        int c0 = cs * 8;
        uint32_t af[4], bf[5][2];
        int row = wm * 16 + qr;
        af[0] = Qs[row * QS_P + c0 + qc];
        af[1] = Qs[(row + 8) * QS_P + c0 + qc];
        af[2] = Qs[row * QS_P + c0 + qc + 4];
        af[3] = Qs[(row + 8) * QS_P + c0 + qc + 4];
        #pragma unroll
        for (int j = 0; j < 5; j++) {
          int col = wn * 40 + j * 8 + qr;
          bf[j][0] = Kt[(c0 + qc) * KT_P + col];
          bf[j][1] = Kt[(c0 + qc + 4) * KT_P + col];
        }
        #pragma unroll
        for (int j = 0; j < 5; j++)
          mma_tf32(acc[j], af, bf[j]);
      }
      int row = wm * 16 + qr;
      #pragma unroll
      for (int j = 0; j < 5; j++) {
        int col = wn * 40 + j * 8 + qc * 2;
        *(float2*)(Psf + row * PS_P + col)       = make_float2(acc[j][0], acc[j][1]);
        *(float2*)(Psf + (row + 8) * PS_P + col) = make_float2(acc[j][2], acc[j][3]);
      }
    }
    __syncthreads();

    // ---- softmax: 2 rows per warp ----
    #pragma unroll
    for (int rr = 0; rr < 2; rr++) {
      int r = wid * 2 + rr;
      const float* nbrow = g_nb + (size_t)h * NN + (size_t)(q0 + r) * 320;
      float v[10];
      float mx = -3.0e38f;
      #pragma unroll
      for (int t = 0; t < 10; t++) {
        int k = lane + 32 * t;
        v[t] = Psf[r * PS_P + k] * scl + bias_s[k] + __ldg(nbrow + k);
        mx = fmaxf(mx, v[t]);
      }
      #pragma unroll
      for (int o = 16; o; o >>= 1) mx = fmaxf(mx, __shfl_xor_sync(~0u, mx, o));
      float ssum = 0.f;
      #pragma unroll
      for (int t = 0; t < 10; t++) { v[t] = __expf(v[t] - mx); ssum += v[t]; }
      #pragma unroll
      for (int o = 16; o; o >>= 1) ssum += __shfl_xor_sync(~0u, ssum, o);
      float inv = 1.f / ssum;
      #pragma unroll
      for (int t = 0; t < 10; t++) Ps[r * PS_P + lane + 32 * t] = f2tf32(v[t] * inv);
    }
    __syncthreads();

    // ---- AV: 8 warps; warp grid 4x2; warp tile 16 rows x 16 cols, full k ----
    if (wid < 8) {
      int wm2 = wid >> 1, wn2 = wid & 1;
      float acc[2][4];
      #pragma unroll
      for (int j = 0; j < 2; j++)
        #pragma unroll
        for (int e = 0; e < 4; e++) acc[j][e] = 0.f;

      #pragma unroll 8
      for (int ks = 0; ks < 40; ks++) {
        int k0 = ks * 8;
        uint32_t af[4], bf[2][2];
        int row = wm2 * 16 + qr;
        af[0] = Ps[row * PS_P + k0 + qc];
        af[1] = Ps[(row + 8) * PS_P + k0 + qc];
        af[2] = Ps[row * PS_P + k0 + qc + 4];
        af[3] = Ps[(row + 8) * PS_P + k0 + qc + 4];
        #pragma unroll
        for (int j = 0; j < 2; j++) {
          int col = wn2 * 16 + j * 8 + qr;
          bf[j][0] = Vs[(k0 + qc) * VS_P + col];
          bf[j][1] = Vs[(k0 + qc + 4) * VS_P + col];
        }
        mma_tf32(acc[0], af, bf[0]);
        mma_tf32(acc[1], af, bf[1]);
      }
      int row = b * 320 + q0 + wm2 * 16 + qr;
      #pragma unroll
      for (int j = 0; j < 2; j++) {
        int col = h * 32 + wn2 * 16 + j * 8 + qc * 2;
        *(float2*)(g_wa + (size_t)row * 128 + col)       = make_float2(acc[j][0], acc[j][1]);
        *(float2*)(g_wa + (size_t)(row + 8) * 128 + col) = make_float2(acc[j][2], acc[j][3]);
      }
    }
    __syncthreads();
  }
}

// ---------------- K4: gate*sigmoid fused + output proj (B frags from L2) --------
__global__ __launch_bounds__(256) void k4_mma(float* __restrict__ out) {
  extern __shared__ uint32_t sm4[];
  uint32_t* As = sm4;               // [64][LDA]

  int tid = threadIdx.x, wid = tid >> 5, lane = tid & 31;
  int wm = wid >> 2, wn = wid & 3;
  int qr = lane >> 2, qc = lane & 3;
  int rowBase = blockIdx.x * 64;

  #pragma unroll
  for (int i = 0; i < 8; i++) {
    int idx = tid + i * 256;
    int r = idx >> 5, f = idx & 31;
    int row = rowBase + r;
    float4 a  = ((const float4*)(g_wa + (size_t)row * CZ))[f];
    float4 gt = ((const float4*)(g_qkvg + (size_t)row * 512 + 384))[f];
    a.x *= 1.f / (1.f + __expf(-gt.x));
    a.y *= 1.f / (1.f + __expf(-gt.y));
    a.z *= 1.f / (1.f + __expf(-gt.z));
    a.w *= 1.f / (1.f + __expf(-gt.w));
    uint32_t* d = As + r * LDA + f * 4;
    d[0] = f2tf32(a.x); d[1] = f2tf32(a.y); d[2] = f2tf32(a.z); d[3] = f2tf32(a.w);
  }
  __syncthreads();

  float acc[2][4][4];
  #pragma unroll
  for (int i = 0; i < 2; i++)
    #pragma unroll
    for (int j = 0; j < 4; j++)
      #pragma unroll
      for (int e = 0; e < 4; e++) acc[i][j][e] = 0.f;

  #pragma unroll 4
  for (int kk = 0; kk < 16; kk++) {
    int k0 = kk * 8;
    uint32_t af[2][4];
    #pragma unroll
    for (int i = 0; i < 2; i++) {
      int row = wm * 32 + i * 16 + qr;
      af[i][0] = As[row * LDA + k0 + qc];
      af[i][1] = As[(row + 8) * LDA + k0 + qc];
      af[i][2] = As[row * LDA + k0 + qc + 4];
      af[i][3] = As[(row + 8) * LDA + k0 + qc + 4];
    }
    #pragma unroll
    for (int j = 0; j < 4; j++) {
      float2 b2 = g_bf[4][kk][wn][j][lane];
      uint32_t bf[2] = { __float_as_uint(b2.x), __float_as_uint(b2.y) };
      #pragma unroll
      for (int i = 0; i < 2; i++)
        mma_tf32(acc[i][j], af[i], bf);
    }
  }

  #pragma unroll
  for (int i = 0; i < 2; i++) {
    int row0 = rowBase + wm * 32 + i * 16 + qr;
    #pragma unroll
    for (int j = 0; j < 4; j++) {
      int col = wn * 32 + j * 8 + qc * 2;
      *(float2*)(out + (size_t)row0 * CZ + col)       = make_float2(acc[i][j][0], acc[i][j][1]);
      *(float2*)(out + (size_t)(row0 + 8) * CZ + col) = make_float2(acc[i][j][2], acc[i][j][3]);
    }
  }
}

// ---------------- launch --------------------------------------------------------
extern "C" void kernel_launch(void* const* d_in, const int* in_sizes, int n_in,
                              void* d_out, int out_size) {
  const float* pair    = (const float*)d_in[0];
  const float* affine  = (const float*)d_in[1];
  const float* mask    = (const float*)d_in[2];
  const float* pls     = (const float*)d_in[3];
  const float* plo     = (const float*)d_in[4];
  const float* als     = (const float*)d_in[5];
  const float* alo     = (const float*)d_in[6];
  const float* f2d     = (const float*)d_in[7];
  const float* qw      = (const float*)d_in[8];
  const float* kw      = (const float*)d_in[9];
  const float* vw      = (const float*)d_in[10];
  const float* gw      = (const float*)d_in[11];
  const float* ow      = (const float*)d_in[12];
  float* out = (float*)d_out;

  const int a_smem  = 64 * LDA * 4;             // 33792 B -> 4 CTAs/SM
  const int k3_smem = K3_FLOATS * 4;            // 188672 B
  cudaFuncSetAttribute(k2_mma, cudaFuncAttributeMaxDynamicSharedMemorySize, a_smem);
  cudaFuncSetAttribute(k4_mma, cudaFuncAttributeMaxDynamicSharedMemorySize, a_smem);
  cudaFuncSetAttribute(k3_attn, cudaFuncAttributeMaxDynamicSharedMemorySize, k3_smem);

  k0_prep<<<80, 512>>>(qw, kw, vw, gw, ow);
  k1_nb<<<NN, 128>>>(affine, als, alo, f2d);
  k2_mma<<<NN / 64, 256, a_smem>>>(pair, pls, plo);
  k3_attn<<<dim3(NH, N_RES), 1024, k3_smem>>>(mask);
  k4_mma<<<NN / 64, 256, a_smem>>>(out);
}

// round 9
// speedup vs baseline: 3.3030x; 1.1638x over previous
#include <cuda_runtime.h>
#include <cstdint>
#include <math.h>

#define N_RES 320
#define CZ 128
#define NH 4
#define HD 32
#define NN (N_RES*N_RES)   /* 102400 */

// ---------------- scratch (static device globals; no allocation) ----------------
__device__ float g_qkvg[(size_t)NN*512];     // 209.7 MB : [row][kind*128 + h*32 + d]
__device__ float g_nb[(size_t)NH*NN];        // 1.6 MB   : [h][q*320+k]
__device__ float g_wa[(size_t)NN*CZ];        // 52.4 MB  : weighted_avg [row][h*32+d]
// fragment-ordered tf32 weights: [kind(5)][kk(16)][wn(4)][j(4)][lane(32)] float2
__device__ float2 g_bf[5][16][4][4][32];     // 320 KB, L2-resident

__device__ __forceinline__ uint32_t f2tf32(float x) {
  uint32_t r; asm("cvt.rna.tf32.f32 %0, %1;" : "=r"(r) : "f"(x)); return r;
}
__device__ __forceinline__ void mma_tf32(float* c, const uint32_t* a, const uint32_t* b) {
  asm volatile("mma.sync.aligned.m16n8k8.row.col.f32.tf32.tf32.f32 "
               "{%0,%1,%2,%3}, {%4,%5,%6,%7}, {%8,%9}, {%0,%1,%2,%3};"
               : "+f"(c[0]), "+f"(c[1]), "+f"(c[2]), "+f"(c[3])
               : "r"(a[0]), "r"(a[1]), "r"(a[2]), "r"(a[3]), "r"(b[0]), "r"(b[1]));
}

#define LDA 132   /* padded stride (floats) for 128-wide smem tiles */

// ---------------- K0: weight -> fragment-order tf32 prep ------------------------
__global__ void k0_prep(const float* __restrict__ qw, const float* __restrict__ kw,
                        const float* __restrict__ vw, const float* __restrict__ gw,
                        const float* __restrict__ ow) {
  int kind = blockIdx.x >> 4, kk = blockIdx.x & 15;
  const float* W = (kind == 0) ? qw : (kind == 1) ? kw : (kind == 2) ? vw : (kind == 3) ? gw : ow;
  int t = threadIdx.x;
  int wn = t >> 7, j = (t >> 5) & 3, lane = t & 31;
  int qr = lane >> 2, qc = lane & 3;
  int col = wn * 32 + j * 8 + qr;
  int k0 = kk * 8;
  float2 v;
  v.x = __uint_as_float(f2tf32(W[(k0 + qc) * 128 + col]));
  v.y = __uint_as_float(f2tf32(W[(k0 + qc + 4) * 128 + col]));
  g_bf[kind][kk][wn][j][lane] = v;
}

// ---------------- K1: LayerNorm(affine) + nonbatched bias ------------------------
__global__ void k1_nb(const float* __restrict__ affine,
                      const float* __restrict__ als, const float* __restrict__ alo,
                      const float* __restrict__ f2d) {
  int row = blockIdx.x;
  int t = threadIdx.x, w = t >> 5, l = t & 31;
  __shared__ float sh[16];
  size_t base = (size_t)row * CZ + t;

  float a = affine[base];
  float s = a, s2 = a * a;
  #pragma unroll
  for (int o = 16; o; o >>= 1) { s += __shfl_xor_sync(~0u, s, o); s2 += __shfl_xor_sync(~0u, s2, o); }
  if (l == 0) { sh[w] = s; sh[4 + w] = s2; }
  __syncthreads();
  float sum  = sh[0] + sh[1] + sh[2] + sh[3];
  float sum2 = sh[4] + sh[5] + sh[6] + sh[7];
  float mean = sum * (1.f / CZ);
  float var  = sum2 * (1.f / CZ) - mean * mean;
  float aln = (a - mean) * rsqrtf(var + 1e-5f) * als[t] + alo[t];

  float p0 = aln * f2d[t * 4 + 0];
  float p1 = aln * f2d[t * 4 + 1];
  float p2 = aln * f2d[t * 4 + 2];
  float p3 = aln * f2d[t * 4 + 3];
  #pragma unroll
  for (int o = 16; o; o >>= 1) {
    p0 += __shfl_xor_sync(~0u, p0, o);
    p1 += __shfl_xor_sync(~0u, p1, o);
    p2 += __shfl_xor_sync(~0u, p2, o);
    p3 += __shfl_xor_sync(~0u, p3, o);
  }
  __syncthreads();
  if (l == 0) { sh[w*4+0] = p0; sh[w*4+1] = p1; sh[w*4+2] = p2; sh[w*4+3] = p3; }
  __syncthreads();
  if (t < 4) {
    g_nb[(size_t)t * NN + row] = sh[0*4+t] + sh[1*4+t] + sh[2*4+t] + sh[3*4+t];
  }
}

// ---------------- K2: fused pair-LN + all-4-kind QKVG projection ----------------
__global__ __launch_bounds__(256) void k2_mma(const float* __restrict__ pair,
                                              const float* __restrict__ pls,
                                              const float* __restrict__ plo) {
  extern __shared__ uint32_t sm2[];
  uint32_t* As = sm2;               // [64][LDA]
  float* Asf = (float*)As;

  int tid = threadIdx.x, wid = tid >> 5, lane = tid & 31;
  int wm = wid >> 2, wn = wid & 3;            // warp grid 2x4
  int qr = lane >> 2, qc = lane & 3;
  int rowBase = blockIdx.x * 64;

  #pragma unroll
  for (int i = 0; i < 8; i++) {
    int idx = tid + i * 256;
    int r = idx >> 5, f = idx & 31;
    float4 v = ((const float4*)(pair + (size_t)(rowBase + r) * CZ))[f];
    float* d = Asf + r * LDA + f * 4;
    d[0] = v.x; d[1] = v.y; d[2] = v.z; d[3] = v.w;
  }
  __syncthreads();

  float plsv[4], plov[4];
  #pragma unroll
  for (int m = 0; m < 4; m++) { plsv[m] = pls[lane + 32 * m]; plov[m] = plo[lane + 32 * m]; }
  for (int r = wid; r < 64; r += 8) {
    float x[4];
    float s = 0.f, s2 = 0.f;
    #pragma unroll
    for (int m = 0; m < 4; m++) {
      x[m] = Asf[r * LDA + lane + 32 * m];
      s += x[m]; s2 += x[m] * x[m];
    }
    #pragma unroll
    for (int o = 16; o; o >>= 1) { s += __shfl_xor_sync(~0u, s, o); s2 += __shfl_xor_sync(~0u, s2, o); }
    float mean = s * (1.f / CZ);
    float var  = s2 * (1.f / CZ) - mean * mean;
    float rstd = rsqrtf(var + 1e-5f);
    #pragma unroll
    for (int m = 0; m < 4; m++)
      As[r * LDA + lane + 32 * m] = f2tf32((x[m] - mean) * rstd * plsv[m] + plov[m]);
  }
  __syncthreads();

  for (int kind = 0; kind < 4; kind++) {
    float acc[2][4][4];
    #pragma unroll
    for (int i = 0; i < 2; i++)
      #pragma unroll
      for (int j = 0; j < 4; j++)
        #pragma unroll
        for (int e = 0; e < 4; e++) acc[i][j][e] = 0.f;

    #pragma unroll 4
    for (int kk = 0; kk < 16; kk++) {
      int k0 = kk * 8;
      uint32_t af[2][4];
      #pragma unroll
      for (int i = 0; i < 2; i++) {
        int row = wm * 32 + i * 16 + qr;
        af[i][0] = As[row * LDA + k0 + qc];
        af[i][1] = As[(row + 8) * LDA + k0 + qc];
        af[i][2] = As[row * LDA + k0 + qc + 4];
        af[i][3] = As[(row + 8) * LDA + k0 + qc + 4];
      }
      #pragma unroll
      for (int j = 0; j < 4; j++) {
        float2 b2 = g_bf[kind][kk][wn][j][lane];
        uint32_t bf[2] = { __float_as_uint(b2.x), __float_as_uint(b2.y) };
        #pragma unroll
        for (int i = 0; i < 2; i++)
          mma_tf32(acc[i][j], af[i], bf);
      }
    }

    int colBase = kind * 128;
    #pragma unroll
    for (int i = 0; i < 2; i++) {
      int row0 = rowBase + wm * 32 + i * 16 + qr;
      #pragma unroll
      for (int j = 0; j < 4; j++) {
        int col = colBase + wn * 32 + j * 8 + qc * 2;
        *(float2*)(g_qkvg + (size_t)row0 * 512 + col)       = make_float2(acc[i][j][0], acc[i][j][1]);
        *(float2*)(g_qkvg + (size_t)(row0 + 8) * 512 + col) = make_float2(acc[i][j][2], acc[i][j][3]);
      }
    }
  }
}

// ---------------- K3: register-flash attention, 640 threads per (h,b) -----------
// 20 warps x 16 q-rows = 320 rows. S and P never touch smem.
#define KT_P 328
#define VS_P 40
#define K3_KT   0
#define K3_VS   (32*KT_P)
#define K3_BIAS (K3_VS + 320*VS_P)
#define K3_FLOATS (K3_BIAS + 320)

__global__ __launch_bounds__(640, 1) void k3_attn(const float* __restrict__ mask) {
  extern __shared__ uint32_t sm3[];
  uint32_t* Kt = sm3 + K3_KT;          // [32 headdim][328]: tf32 K^T
  uint32_t* Vs = sm3 + K3_VS;          // [320 k][40]: tf32 V
  float*    bias_s = (float*)(sm3 + K3_BIAS);

  int h = blockIdx.x, b = blockIdx.y;
  int tid = threadIdx.x, wid = tid >> 5, lane = tid & 31;
  int qr = lane >> 2, qc = lane & 3;

  // ---- stage K^T, V (tf32), bias ----
  #pragma unroll 2
  for (int i = 0; i < 16; i++) {
    int e = tid + i * 640;
    int key = e >> 5, c = e & 31;
    size_t rb = (size_t)(b * 320 + key) * 512 + h * 32;
    Kt[c * KT_P + key] = f2tf32(g_qkvg[rb + 128 + c]);
    Vs[key * VS_P + c] = f2tf32(g_qkvg[rb + 256 + c]);
  }
  if (tid < 320) bias_s[tid] = 1e9f * (mask[b * 320 + tid] - 1.f);
  __syncthreads();

  const float scl = 0.17677669529663687f;
  int q0w = wid * 16;                                // this warp's 16 q-rows
  size_t rA = (size_t)(b * 320 + q0w + qr) * 512 + h * 32;
  const float* nbr0 = g_nb + (size_t)h * NN + (size_t)(q0w + qr) * 320;
  const float* nbr1 = nbr0 + 8 * 320;

  // ---- Q fragments (registers, once) ----
  uint32_t qf[4][4];
  #pragma unroll
  for (int cs = 0; cs < 4; cs++) {
    qf[cs][0] = f2tf32(g_qkvg[rA + cs * 8 + qc]);
    qf[cs][1] = f2tf32(g_qkvg[rA + 8 * 512 + cs * 8 + qc]);
    qf[cs][2] = f2tf32(g_qkvg[rA + cs * 8 + qc + 4]);
    qf[cs][3] = f2tf32(g_qkvg[rA + 8 * 512 + cs * 8 + qc + 4]);
  }

  float o[4][4];
  #pragma unroll
  for (int jo = 0; jo < 4; jo++)
    #pragma unroll
    for (int e = 0; e < 4; e++) o[jo][e] = 0.f;
  float m0 = -3.0e38f, m1 = -3.0e38f, l0 = 0.f, l1 = 0.f;

  int sbase = lane & ~3;                 // quad base lane (= qr*4)
  int srcA = sbase + (qc >> 1), srcB = srcA + 2;

  for (int ch = 0; ch < 5; ch++) {
    int kbase = ch * 64;

    // ---- S chunk = Q @ K^T (16 x 64), 8 n-tiles ----
    float s[8][4];
    #pragma unroll
    for (int j = 0; j < 8; j++)
      #pragma unroll
      for (int e = 0; e < 4; e++) s[j][e] = 0.f;

    #pragma unroll
    for (int cs = 0; cs < 4; cs++) {
      int c0 = cs * 8;
      #pragma unroll
      for (int j = 0; j < 8; j++) {
        int col = kbase + j * 8 + qr;
        uint32_t bf[2] = { Kt[(c0 + qc) * KT_P + col], Kt[(c0 + qc + 4) * KT_P + col] };
        mma_tf32(s[j], qf[cs], bf);
      }
    }

    // ---- scale + bias + nb; chunk max ----
    float cmax0 = -3.0e38f, cmax1 = -3.0e38f;
    #pragma unroll
    for (int j = 0; j < 8; j++) {
      int kk = kbase + j * 8 + qc * 2;
      float2 n0 = *(const float2*)(nbr0 + kk);
      float2 n1 = *(const float2*)(nbr1 + kk);
      float b0 = bias_s[kk], b1 = bias_s[kk + 1];
      s[j][0] = s[j][0] * scl + b0 + n0.x;
      s[j][1] = s[j][1] * scl + b1 + n0.y;
      s[j][2] = s[j][2] * scl + b0 + n1.x;
      s[j][3] = s[j][3] * scl + b1 + n1.y;
      cmax0 = fmaxf(cmax0, fmaxf(s[j][0], s[j][1]));
      cmax1 = fmaxf(cmax1, fmaxf(s[j][2], s[j][3]));
    }
    cmax0 = fmaxf(cmax0, __shfl_xor_sync(~0u, cmax0, 1));
    cmax0 = fmaxf(cmax0, __shfl_xor_sync(~0u, cmax0, 2));
    cmax1 = fmaxf(cmax1, __shfl_xor_sync(~0u, cmax1, 1));
    cmax1 = fmaxf(cmax1, __shfl_xor_sync(~0u, cmax1, 2));

    // ---- online softmax update ----
    float mn0 = fmaxf(m0, cmax0), mn1 = fmaxf(m1, cmax1);
    float sc0 = __expf(m0 - mn0), sc1 = __expf(m1 - mn1);
    m0 = mn0; m1 = mn1;
    float ps0 = 0.f, ps1 = 0.f;
    #pragma unroll
    for (int j = 0; j < 8; j++) {
      s[j][0] = __expf(s[j][0] - mn0);
      s[j][1] = __expf(s[j][1] - mn0);
      s[j][2] = __expf(s[j][2] - mn1);
      s[j][3] = __expf(s[j][3] - mn1);
      ps0 += s[j][0] + s[j][1];
      ps1 += s[j][2] + s[j][3];
    }
    ps0 += __shfl_xor_sync(~0u, ps0, 1); ps0 += __shfl_xor_sync(~0u, ps0, 2);
    ps1 += __shfl_xor_sync(~0u, ps1, 1); ps1 += __shfl_xor_sync(~0u, ps1, 2);
    l0 = l0 * sc0 + ps0;
    l1 = l1 * sc1 + ps1;
    #pragma unroll
    for (int jo = 0; jo < 4; jo++) {
      o[jo][0] *= sc0; o[jo][1] *= sc0;
      o[jo][2] *= sc1; o[jo][3] *= sc1;
    }

    // ---- P transpose (C-layout -> A-layout via quad shuffles) + AV ----
    #pragma unroll
    for (int j = 0; j < 8; j++) {
      uint32_t p0 = f2tf32(s[j][0]), p1 = f2tf32(s[j][1]);
      uint32_t p2 = f2tf32(s[j][2]), p3 = f2tf32(s[j][3]);
      uint32_t xa0 = __shfl_sync(~0u, p0, srcA), xa1 = __shfl_sync(~0u, p1, srcA);
      uint32_t ya0 = __shfl_sync(~0u, p2, srcA), ya1 = __shfl_sync(~0u, p3, srcA);
      uint32_t xb0 = __shfl_sync(~0u, p0, srcB), xb1 = __shfl_sync(~0u, p1, srcB);
      uint32_t yb0 = __shfl_sync(~0u, p2, srcB), yb1 = __shfl_sync(~0u, p3, srcB);
      uint32_t af[4];
      af[0] = (qc & 1) ? xa1 : xa0;   // (row qr,   k=qc)
      af[1] = (qc & 1) ? ya1 : ya0;   // (row qr+8, k=qc)
      af[2] = (qc & 1) ? xb1 : xb0;   // (row qr,   k=qc+4)
      af[3] = (qc & 1) ? yb1 : yb0;   // (row qr+8, k=qc+4)

      int kv = kbase + j * 8;
      #pragma unroll
      for (int jo = 0; jo < 4; jo++) {
        int col = jo * 8 + qr;
        uint32_t bf[2] = { Vs[(kv + qc) * VS_P + col], Vs[(kv + qc + 4) * VS_P + col] };
        mma_tf32(o[jo], af, bf);
      }
    }
  }

  // ---- normalize + store ----
  float inv0 = 1.f / l0, inv1 = 1.f / l1;
  size_t row = (size_t)(b * 320 + q0w + qr);
  #pragma unroll
  for (int jo = 0; jo < 4; jo++) {
    int col = h * 32 + jo * 8 + qc * 2;
    *(float2*)(g_wa + row * 128 + col)       = make_float2(o[jo][0] * inv0, o[jo][1] * inv0);
    *(float2*)(g_wa + (row + 8) * 128 + col) = make_float2(o[jo][2] * inv1, o[jo][3] * inv1);
  }
}

// ---------------- K4: gate*sigmoid fused + output proj (B frags from L2) --------
__global__ __launch_bounds__(256) void k4_mma(float* __restrict__ out) {
  extern __shared__ uint32_t sm4[];
  uint32_t* As = sm4;               // [64][LDA]

  int tid = threadIdx.x, wid = tid >> 5, lane = tid & 31;
  int wm = wid >> 2, wn = wid & 3;
  int qr = lane >> 2, qc = lane & 3;
  int rowBase = blockIdx.x * 64;

  #pragma unroll
  for (int i = 0; i < 8; i++) {
    int idx = tid + i * 256;
    int r = idx >> 5, f = idx & 31;
    int row = rowBase + r;
    float4 a  = ((const float4*)(g_wa + (size_t)row * CZ))[f];
    float4 gt = ((const float4*)(g_qkvg + (size_t)row * 512 + 384))[f];
    a.x *= 1.f / (1.f + __expf(-gt.x));
    a.y *= 1.f / (1.f + __expf(-gt.y));
    a.z *= 1.f / (1.f + __expf(-gt.z));
    a.w *= 1.f / (1.f + __expf(-gt.w));
    uint32_t* d = As + r * LDA + f * 4;
    d[0] = f2tf32(a.x); d[1] = f2tf32(a.y); d[2] = f2tf32(a.z); d[3] = f2tf32(a.w);
  }
  __syncthreads();

  float acc[2][4][4];
  #pragma unroll
  for (int i = 0; i < 2; i++)
    #pragma unroll
    for (int j = 0; j < 4; j++)
      #pragma unroll
      for (int e = 0; e < 4; e++) acc[i][j][e] = 0.f;

  #pragma unroll 4
  for (int kk = 0; kk < 16; kk++) {
    int k0 = kk * 8;
    uint32_t af[2][4];
    #pragma unroll
    for (int i = 0; i < 2; i++) {
      int row = wm * 32 + i * 16 + qr;
      af[i][0] = As[row * LDA + k0 + qc];
      af[i][1] = As[(row + 8) * LDA + k0 + qc];
      af[i][2] = As[row * LDA + k0 + qc + 4];
      af[i][3] = As[(row + 8) * LDA + k0 + qc + 4];
    }
    #pragma unroll
    for (int j = 0; j < 4; j++) {
      float2 b2 = g_bf[4][kk][wn][j][lane];
      uint32_t bf[2] = { __float_as_uint(b2.x), __float_as_uint(b2.y) };
      #pragma unroll
      for (int i = 0; i < 2; i++)
        mma_tf32(acc[i][j], af[i], bf);
    }
  }

  #pragma unroll
  for (int i = 0; i < 2; i++) {
    int row0 = rowBase + wm * 32 + i * 16 + qr;
    #pragma unroll
    for (int j = 0; j < 4; j++) {
      int col = wn * 32 + j * 8 + qc * 2;
      *(float2*)(out + (size_t)row0 * CZ + col)       = make_float2(acc[i][j][0], acc[i][j][1]);
      *(float2*)(out + (size_t)(row0 + 8) * CZ + col) = make_float2(acc[i][j][2], acc[i][j][3]);
    }
  }
}

// ---------------- launch --------------------------------------------------------
extern "C" void kernel_launch(void* const* d_in, const int* in_sizes, int n_in,
                              void* d_out, int out_size) {
  const float* pair    = (const float*)d_in[0];
  const float* affine  = (const float*)d_in[1];
  const float* mask    = (const float*)d_in[2];
  const float* pls     = (const float*)d_in[3];
  const float* plo     = (const float*)d_in[4];
  const float* als     = (const float*)d_in[5];
  const float* alo     = (const float*)d_in[6];
  const float* f2d     = (const float*)d_in[7];
  const float* qw      = (const float*)d_in[8];
  const float* kw      = (const float*)d_in[9];
  const float* vw      = (const float*)d_in[10];
  const float* gw      = (const float*)d_in[11];
  const float* ow      = (const float*)d_in[12];
  float* out = (float*)d_out;

  const int a_smem  = 64 * LDA * 4;             // 33792 B -> 4 CTAs/SM
  const int k3_smem = K3_FLOATS * 4;            // 95744 B
  cudaFuncSetAttribute(k2_mma, cudaFuncAttributeMaxDynamicSharedMemorySize, a_smem);
  cudaFuncSetAttribute(k4_mma, cudaFuncAttributeMaxDynamicSharedMemorySize, a_smem);
  cudaFuncSetAttribute(k3_attn, cudaFuncAttributeMaxDynamicSharedMemorySize, k3_smem);

  k0_prep<<<80, 512>>>(qw, kw, vw, gw, ow);
  k1_nb<<<NN, 128>>>(affine, als, alo, f2d);
  k2_mma<<<NN / 64, 256, a_smem>>>(pair, pls, plo);
  k3_attn<<<dim3(NH, N_RES), 640, k3_smem>>>(mask);
  k4_mma<<<NN / 64, 256, a_smem>>>(out);
}

// round 11
// speedup vs baseline: 3.5530x; 1.0757x over previous
#include <cuda_runtime.h>
#include <cuda_fp16.h>
#include <cstdint>
#include <math.h>

#define N_RES 320
#define CZ 128
#define NH 4
#define HD 32
#define NN (N_RES*N_RES)   /* 102400 */

// ---------------- scratch (static device globals; no allocation) ----------------
__device__ float g_qkvg[(size_t)NN*512];     // 209.7 MB : [row][kind*128 + h*32 + d]
__device__ float g_nb[(size_t)NH*NN];        // 1.6 MB   : [h][q*320+k]
__device__ float g_wa[(size_t)NN*CZ];        // 52.4 MB  : weighted_avg [row][h*32+d]
// fragment-ordered tf32 weights: [kind(5)][kk(16)][wn(4)][j(4)][lane(32)] float2
__device__ float2 g_bf[5][16][4][4][32];     // 320 KB, L2-resident

__device__ __forceinline__ uint32_t f2tf32(float x) {
  uint32_t r; asm("cvt.rna.tf32.f32 %0, %1;" : "=r"(r) : "f"(x)); return r;
}
__device__ __forceinline__ uint32_t packh2(float lo, float hi) {
  __half2 h = __floats2half2_rn(lo, hi);
  return *reinterpret_cast<uint32_t*>(&h);
}
__device__ __forceinline__ void mma_tf32(float* c, const uint32_t* a, const uint32_t* b) {
  asm volatile("mma.sync.aligned.m16n8k8.row.col.f32.tf32.tf32.f32 "
               "{%0,%1,%2,%3}, {%4,%5,%6,%7}, {%8,%9}, {%0,%1,%2,%3};"
               : "+f"(c[0]), "+f"(c[1]), "+f"(c[2]), "+f"(c[3])
               : "r"(a[0]), "r"(a[1]), "r"(a[2]), "r"(a[3]), "r"(b[0]), "r"(b[1]));
}
__device__ __forceinline__ void mma_f16(float* c, const uint32_t* a, const uint32_t* b) {
  asm volatile("mma.sync.aligned.m16n8k16.row.col.f32.f16.f16.f32 "
               "{%0,%1,%2,%3}, {%4,%5,%6,%7}, {%8,%9}, {%0,%1,%2,%3};"
               : "+f"(c[0]), "+f"(c[1]), "+f"(c[2]), "+f"(c[3])
               : "r"(a[0]), "r"(a[1]), "r"(a[2]), "r"(a[3]), "r"(b[0]), "r"(b[1]));
}

#define LDA 132   /* padded stride (floats) for 128-wide smem tiles */

// ---------------- K0: weight -> fragment-order tf32 prep ------------------------
__global__ void k0_prep(const float* __restrict__ qw, const float* __restrict__ kw,
                        const float* __restrict__ vw, const float* __restrict__ gw,
                        const float* __restrict__ ow) {
  int kind = blockIdx.x >> 4, kk = blockIdx.x & 15;
  const float* W = (kind == 0) ? qw : (kind == 1) ? kw : (kind == 2) ? vw : (kind == 3) ? gw : ow;
  int t = threadIdx.x;
  int wn = t >> 7, j = (t >> 5) & 3, lane = t & 31;
  int qr = lane >> 2, qc = lane & 3;
  int col = wn * 32 + j * 8 + qr;
  int k0 = kk * 8;
  float2 v;
  v.x = __uint_as_float(f2tf32(W[(k0 + qc) * 128 + col]));
  v.y = __uint_as_float(f2tf32(W[(k0 + qc + 4) * 128 + col]));
  g_bf[kind][kk][wn][j][lane] = v;
}

// ---------------- K1: LayerNorm(affine) + nonbatched bias ------------------------
__global__ void k1_nb(const float* __restrict__ affine,
                      const float* __restrict__ als, const float* __restrict__ alo,
                      const float* __restrict__ f2d) {
  int row = blockIdx.x;
  int t = threadIdx.x, w = t >> 5, l = t & 31;
  __shared__ float sh[16];
  size_t base = (size_t)row * CZ + t;

  float a = affine[base];
  float s = a, s2 = a * a;
  #pragma unroll
  for (int o = 16; o; o >>= 1) { s += __shfl_xor_sync(~0u, s, o); s2 += __shfl_xor_sync(~0u, s2, o); }
  if (l == 0) { sh[w] = s; sh[4 + w] = s2; }
  __syncthreads();
  float sum  = sh[0] + sh[1] + sh[2] + sh[3];
  float sum2 = sh[4] + sh[5] + sh[6] + sh[7];
  float mean = sum * (1.f / CZ);
  float var  = sum2 * (1.f / CZ) - mean * mean;
  float aln = (a - mean) * rsqrtf(var + 1e-5f) * als[t] + alo[t];

  float p0 = aln * f2d[t * 4 + 0];
  float p1 = aln * f2d[t * 4 + 1];
  float p2 = aln * f2d[t * 4 + 2];
  float p3 = aln * f2d[t * 4 + 3];
  #pragma unroll
  for (int o = 16; o; o >>= 1) {
    p0 += __shfl_xor_sync(~0u, p0, o);
    p1 += __shfl_xor_sync(~0u, p1, o);
    p2 += __shfl_xor_sync(~0u, p2, o);
    p3 += __shfl_xor_sync(~0u, p3, o);
  }
  __syncthreads();
  if (l == 0) { sh[w*4+0] = p0; sh[w*4+1] = p1; sh[w*4+2] = p2; sh[w*4+3] = p3; }
  __syncthreads();
  if (t < 4) {
    g_nb[(size_t)t * NN + row] = sh[0*4+t] + sh[1*4+t] + sh[2*4+t] + sh[3*4+t];
  }
}

// ---------------- K2: fused pair-LN + all-4-kind QKVG projection ----------------
__global__ __launch_bounds__(256) void k2_mma(const float* __restrict__ pair,
                                              const float* __restrict__ pls,
                                              const float* __restrict__ plo) {
  extern __shared__ uint32_t sm2[];
  uint32_t* As = sm2;               // [64][LDA]
  float* Asf = (float*)As;

  int tid = threadIdx.x, wid = tid >> 5, lane = tid & 31;
  int wm = wid >> 2, wn = wid & 3;            // warp grid 2x4
  int qr = lane >> 2, qc = lane & 3;
  int rowBase = blockIdx.x * 64;

  #pragma unroll
  for (int i = 0; i < 8; i++) {
    int idx = tid + i * 256;
    int r = idx >> 5, f = idx & 31;
    float4 v = ((const float4*)(pair + (size_t)(rowBase + r) * CZ))[f];
    float* d = Asf + r * LDA + f * 4;
    d[0] = v.x; d[1] = v.y; d[2] = v.z; d[3] = v.w;
  }
  __syncthreads();

  float plsv[4], plov[4];
  #pragma unroll
  for (int m = 0; m < 4; m++) { plsv[m] = pls[lane + 32 * m]; plov[m] = plo[lane + 32 * m]; }
  for (int r = wid; r < 64; r += 8) {
    float x[4];
    float s = 0.f, s2 = 0.f;
    #pragma unroll
    for (int m = 0; m < 4; m++) {
      x[m] = Asf[r * LDA + lane + 32 * m];
      s += x[m]; s2 += x[m] * x[m];
    }
    #pragma unroll
    for (int o = 16; o; o >>= 1) { s += __shfl_xor_sync(~0u, s, o); s2 += __shfl_xor_sync(~0u, s2, o); }
    float mean = s * (1.f / CZ);
    float var  = s2 * (1.f / CZ) - mean * mean;
    float rstd = rsqrtf(var + 1e-5f);
    #pragma unroll
    for (int m = 0; m < 4; m++)
      As[r * LDA + lane + 32 * m] = f2tf32((x[m] - mean) * rstd * plsv[m] + plov[m]);
  }
  __syncthreads();

  for (int kind = 0; kind < 4; kind++) {
    float acc[2][4][4];
    #pragma unroll
    for (int i = 0; i < 2; i++)
      #pragma unroll
      for (int j = 0; j < 4; j++)
        #pragma unroll
        for (int e = 0; e < 4; e++) acc[i][j][e] = 0.f;

    #pragma unroll 4
    for (int kk = 0; kk < 16; kk++) {
      int k0 = kk * 8;
      uint32_t af[2][4];
      #pragma unroll
      for (int i = 0; i < 2; i++) {
        int row = wm * 32 + i * 16 + qr;
        af[i][0] = As[row * LDA + k0 + qc];
        af[i][1] = As[(row + 8) * LDA + k0 + qc];
        af[i][2] = As[row * LDA + k0 + qc + 4];
        af[i][3] = As[(row + 8) * LDA + k0 + qc + 4];
      }
      #pragma unroll
      for (int j = 0; j < 4; j++) {
        float2 b2 = g_bf[kind][kk][wn][j][lane];
        uint32_t bf[2] = { __float_as_uint(b2.x), __float_as_uint(b2.y) };
        #pragma unroll
        for (int i = 0; i < 2; i++)
          mma_tf32(acc[i][j], af[i], bf);
      }
    }

    int colBase = kind * 128;
    #pragma unroll
    for (int i = 0; i < 2; i++) {
      int row0 = rowBase + wm * 32 + i * 16 + qr;
      #pragma unroll
      for (int j = 0; j < 4; j++) {
        int col = colBase + wn * 32 + j * 8 + qc * 2;
        *(float2*)(g_qkvg + (size_t)row0 * 512 + col)       = make_float2(acc[i][j][0], acc[i][j][1]);
        *(float2*)(g_qkvg + (size_t)(row0 + 8) * 512 + col) = make_float2(acc[i][j][2], acc[i][j][3]);
      }
    }
  }
}

// ---------------- K3: register-flash attention, fp16 AV, 640 thr per (h,b) ------
// QK in tf32 (precision), P+V in fp16 m16n8k16 (A-layout == packed C-layout: no
// shuffles; AV B bytes halved). S/P never touch smem.
#define KT_P 328
#define VS2_P 40
#define K3_KT   0
#define K3_VS2  (32*KT_P)                 /* 10496 */
#define K3_BIAS (K3_VS2 + 160*VS2_P)      /* +6400 = 16896 */
#define K3_FLOATS (K3_BIAS + 320)         /* 17216 floats = 68864 B */

__global__ __launch_bounds__(640, 1) void k3_attn(const float* __restrict__ mask) {
  extern __shared__ uint32_t sm3[];
  uint32_t* Kt  = sm3 + K3_KT;         // [32 headdim][328]: tf32 K^T
  uint32_t* Vs2 = sm3 + K3_VS2;        // [160 key-pairs][40]: half2(V[2kp], V[2kp+1])
  float*    bias_s = (float*)(sm3 + K3_BIAS);

  int h = blockIdx.x, b = blockIdx.y;
  int tid = threadIdx.x, wid = tid >> 5, lane = tid & 31;
  int qr = lane >> 2, qc = lane & 3;

  // ---- stage K^T (tf32), V (half2 pairs), bias ----
  #pragma unroll 2
  for (int i = 0; i < 16; i++) {
    int e = tid + i * 640;
    int key = e >> 5, c = e & 31;
    Kt[c * KT_P + key] = f2tf32(g_qkvg[(size_t)(b * 320 + key) * 512 + h * 32 + 128 + c]);
  }
  #pragma unroll 2
  for (int i = 0; i < 8; i++) {
    int e = tid + i * 640;
    int kp = e >> 5, c = e & 31;
    size_t rb = (size_t)(b * 320 + 2 * kp) * 512 + h * 32 + 256 + c;
    Vs2[kp * VS2_P + c] = packh2(g_qkvg[rb], g_qkvg[rb + 512]);
  }
  if (tid < 320) bias_s[tid] = 1e9f * (mask[b * 320 + tid] - 1.f);
  __syncthreads();

  const float scl = 0.17677669529663687f;
  int q0w = wid * 16;                                // this warp's 16 q-rows
  size_t rA = (size_t)(b * 320 + q0w + qr) * 512 + h * 32;
  const float* nbr0 = g_nb + (size_t)h * NN + (size_t)(q0w + qr) * 320;
  const float* nbr1 = nbr0 + 8 * 320;

  // ---- Q fragments (registers, once) ----
  uint32_t qf[4][4];
  #pragma unroll
  for (int cs = 0; cs < 4; cs++) {
    qf[cs][0] = f2tf32(g_qkvg[rA + cs * 8 + qc]);
    qf[cs][1] = f2tf32(g_qkvg[rA + 8 * 512 + cs * 8 + qc]);
    qf[cs][2] = f2tf32(g_qkvg[rA + cs * 8 + qc + 4]);
    qf[cs][3] = f2tf32(g_qkvg[rA + 8 * 512 + cs * 8 + qc + 4]);
  }

  float o[4][4];
  #pragma unroll
  for (int jo = 0; jo < 4; jo++)
    #pragma unroll
    for (int e = 0; e < 4; e++) o[jo][e] = 0.f;
  float m0 = -3.0e38f, m1 = -3.0e38f, l0 = 0.f, l1 = 0.f;

  for (int ch = 0; ch < 5; ch++) {
    int kbase = ch * 64;

    // ---- S chunk = Q @ K^T (16 x 64), 8 n-tiles, tf32 ----
    float s[8][4];
    #pragma unroll
    for (int j = 0; j < 8; j++)
      #pragma unroll
      for (int e = 0; e < 4; e++) s[j][e] = 0.f;

    #pragma unroll
    for (int cs = 0; cs < 4; cs++) {
      int c0 = cs * 8;
      #pragma unroll
      for (int j = 0; j < 8; j++) {
        int col = kbase + j * 8 + qr;
        uint32_t bf[2] = { Kt[(c0 + qc) * KT_P + col], Kt[(c0 + qc + 4) * KT_P + col] };
        mma_tf32(s[j], qf[cs], bf);
      }
    }

    // ---- scale + bias + nb; chunk max ----
    float cmax0 = -3.0e38f, cmax1 = -3.0e38f;
    #pragma unroll
    for (int j = 0; j < 8; j++) {
      int kk = kbase + j * 8 + qc * 2;
      float2 n0 = *(const float2*)(nbr0 + kk);
      float2 n1 = *(const float2*)(nbr1 + kk);
      float b0 = bias_s[kk], b1 = bias_s[kk + 1];
      s[j][0] = s[j][0] * scl + b0 + n0.x;
      s[j][1] = s[j][1] * scl + b1 + n0.y;
      s[j][2] = s[j][2] * scl + b0 + n1.x;
      s[j][3] = s[j][3] * scl + b1 + n1.y;
      cmax0 = fmaxf(cmax0, fmaxf(s[j][0], s[j][1]));
      cmax1 = fmaxf(cmax1, fmaxf(s[j][2], s[j][3]));
    }
    cmax0 = fmaxf(cmax0, __shfl_xor_sync(~0u, cmax0, 1));
    cmax0 = fmaxf(cmax0, __shfl_xor_sync(~0u, cmax0, 2));
    cmax1 = fmaxf(cmax1, __shfl_xor_sync(~0u, cmax1, 1));
    cmax1 = fmaxf(cmax1, __shfl_xor_sync(~0u, cmax1, 2));

    // ---- online softmax update ----
    float mn0 = fmaxf(m0, cmax0), mn1 = fmaxf(m1, cmax1);
    float sc0 = __expf(m0 - mn0), sc1 = __expf(m1 - mn1);
    m0 = mn0; m1 = mn1;
    float ps0 = 0.f, ps1 = 0.f;
    #pragma unroll
    for (int j = 0; j < 8; j++) {
      s[j][0] = __expf(s[j][0] - mn0);
      s[j][1] = __expf(s[j][1] - mn0);
      s[j][2] = __expf(s[j][2] - mn1);
      s[j][3] = __expf(s[j][3] - mn1);
      ps0 += s[j][0] + s[j][1];
      ps1 += s[j][2] + s[j][3];
    }
    ps0 += __shfl_xor_sync(~0u, ps0, 1); ps0 += __shfl_xor_sync(~0u, ps0, 2);
    ps1 += __shfl_xor_sync(~0u, ps1, 1); ps1 += __shfl_xor_sync(~0u, ps1, 2);
    l0 = l0 * sc0 + ps0;
    l1 = l1 * sc1 + ps1;
    #pragma unroll
    for (int jo = 0; jo < 4; jo++) {
      o[jo][0] *= sc0; o[jo][1] *= sc0;
      o[jo][2] *= sc1; o[jo][3] *= sc1;
    }

    // ---- pack P to fp16 (A-layout == C-layout pairs: NO shuffles) + AV ----
    uint32_t ph[8][2];
    #pragma unroll
    for (int j = 0; j < 8; j++) {
      ph[j][0] = packh2(s[j][0], s[j][1]);   // (row qr,   k=2qc,2qc+1)
      ph[j][1] = packh2(s[j][2], s[j][3]);   // (row qr+8, k=2qc,2qc+1)
    }
    #pragma unroll
    for (int ks = 0; ks < 4; ks++) {
      uint32_t af[4] = { ph[2*ks][0], ph[2*ks][1], ph[2*ks+1][0], ph[2*ks+1][1] };
      int kvp = (kbase >> 1) + ks * 8;       // half2-row base for these 16 keys
      #pragma unroll
      for (int jo = 0; jo < 4; jo++) {
        int col = jo * 8 + qr;
        uint32_t bf[2] = { Vs2[(kvp + qc) * VS2_P + col],
                           Vs2[(kvp + qc + 4) * VS2_P + col] };
        mma_f16(o[jo], af, bf);
      }
    }
  }

  // ---- normalize + store ----
  float inv0 = 1.f / l0, inv1 = 1.f / l1;
  size_t row = (size_t)(b * 320 + q0w + qr);
  #pragma unroll
  for (int jo = 0; jo < 4; jo++) {
    int col = h * 32 + jo * 8 + qc * 2;
    *(float2*)(g_wa + row * 128 + col)       = make_float2(o[jo][0] * inv0, o[jo][1] * inv0);
    *(float2*)(g_wa + (row + 8) * 128 + col) = make_float2(o[jo][2] * inv1, o[jo][3] * inv1);
  }
}

// ---------------- K4: gate*sigmoid fused + output proj (B frags from L2) --------
__global__ __launch_bounds__(256) void k4_mma(float* __restrict__ out) {
  extern __shared__ uint32_t sm4[];
  uint32_t* As = sm4;               // [64][LDA]

  int tid = threadIdx.x, wid = tid >> 5, lane = tid & 31;
  int wm = wid >> 2, wn = wid & 3;
  int qr = lane >> 2, qc = lane & 3;
  int rowBase = blockIdx.x * 64;

  #pragma unroll
  for (int i = 0; i < 8; i++) {
    int idx = tid + i * 256;
    int r = idx >> 5, f = idx & 31;
    int row = rowBase + r;
    float4 a  = ((const float4*)(g_wa + (size_t)row * CZ))[f];
    float4 gt = ((const float4*)(g_qkvg + (size_t)row * 512 + 384))[f];
    a.x *= 1.f / (1.f + __expf(-gt.x));
    a.y *= 1.f / (1.f + __expf(-gt.y));
    a.z *= 1.f / (1.f + __expf(-gt.z));
    a.w *= 1.f / (1.f + __expf(-gt.w));
    uint32_t* d = As + r * LDA + f * 4;
    d[0] = f2tf32(a.x); d[1] = f2tf32(a.y); d[2] = f2tf32(a.z); d[3] = f2tf32(a.w);
  }
  __syncthreads();

  float acc[2][4][4];
  #pragma unroll
  for (int i = 0; i < 2; i++)
    #pragma unroll
    for (int j = 0; j < 4; j++)
      #pragma unroll
      for (int e = 0; e < 4; e++) acc[i][j][e] = 0.f;

  #pragma unroll 4
  for (int kk = 0; kk < 16; kk++) {
    int k0 = kk * 8;
    uint32_t af[2][4];
    #pragma unroll
    for (int i = 0; i < 2; i++) {
      int row = wm * 32 + i * 16 + qr;
      af[i][0] = As[row * LDA + k0 + qc];
      af[i][1] = As[(row + 8) * LDA + k0 + qc];
      af[i][2] = As[row * LDA + k0 + qc + 4];
      af[i][3] = As[(row + 8) * LDA + k0 + qc + 4];
    }
    #pragma unroll
    for (int j = 0; j < 4; j++) {
      float2 b2 = g_bf[4][kk][wn][j][lane];
      uint32_t bf[2] = { __float_as_uint(b2.x), __float_as_uint(b2.y) };
      #pragma unroll
      for (int i = 0; i < 2; i++)
        mma_tf32(acc[i][j], af[i], bf);
    }
  }

  #pragma unroll
  for (int i = 0; i < 2; i++) {
    int row0 = rowBase + wm * 32 + i * 16 + qr;
    #pragma unroll
    for (int j = 0; j < 4; j++) {
      int col = wn * 32 + j * 8 + qc * 2;
      *(float2*)(out + (size_t)row0 * CZ + col)       = make_float2(acc[i][j][0], acc[i][j][1]);
      *(float2*)(out + (size_t)(row0 + 8) * CZ + col) = make_float2(acc[i][j][2], acc[i][j][3]);
    }
  }
}

// ---------------- launch --------------------------------------------------------
extern "C" void kernel_launch(void* const* d_in, const int* in_sizes, int n_in,
                              void* d_out, int out_size) {
  const float* pair    = (const float*)d_in[0];
  const float* affine  = (const float*)d_in[1];
  const float* mask    = (const float*)d_in[2];
  const float* pls     = (const float*)d_in[3];
  const float* plo     = (const float*)d_in[4];
  const float* als     = (const float*)d_in[5];
  const float* alo     = (const float*)d_in[6];
  const float* f2d     = (const float*)d_in[7];
  const float* qw      = (const float*)d_in[8];
  const float* kw      = (const float*)d_in[9];
  const float* vw      = (const float*)d_in[10];
  const float* gw      = (const float*)d_in[11];
  const float* ow      = (const float*)d_in[12];
  float* out = (float*)d_out;

  const int a_smem  = 64 * LDA * 4;             // 33792 B -> 4 CTAs/SM
  const int k3_smem = K3_FLOATS * 4;            // 68864 B
  cudaFuncSetAttribute(k2_mma, cudaFuncAttributeMaxDynamicSharedMemorySize, a_smem);
  cudaFuncSetAttribute(k4_mma, cudaFuncAttributeMaxDynamicSharedMemorySize, a_smem);
  cudaFuncSetAttribute(k3_attn, cudaFuncAttributeMaxDynamicSharedMemorySize, k3_smem);

  k0_prep<<<80, 512>>>(qw, kw, vw, gw, ow);
  k1_nb<<<NN, 128>>>(affine, als, alo, f2d);
  k2_mma<<<NN / 64, 256, a_smem>>>(pair, pls, plo);
  k3_attn<<<dim3(NH, N_RES), 640, k3_smem>>>(mask);
  k4_mma<<<NN / 64, 256, a_smem>>>(out);
}

// round 12
// speedup vs baseline: 4.0451x; 1.1385x over previous
#include <cuda_runtime.h>
#include <cuda_fp16.h>
#include <cstdint>
#include <math.h>

#define N_RES 320
#define CZ 128
#define NH 4
#define HD 32
#define NN (N_RES*N_RES)   /* 102400 */

// ---------------- scratch (static device globals; no allocation) ----------------
__device__ __half g_qkvg[(size_t)NN*512];    // 104.9 MB : [row][kind*128 + h*32 + d], fp16
__device__ float  g_nb[(size_t)NH*NN];       // 1.6 MB   : [h][q*320+k]
__device__ __half g_wa[(size_t)NN*CZ];       // 26.2 MB  : weighted_avg, fp16
// fragment-ordered tf32 weights: [kind(5)][kk(16)][wn(4)][j(4)][lane(32)] float2
__device__ float2 g_bf[5][16][4][4][32];     // 320 KB, L2-resident

__device__ __forceinline__ uint32_t f2tf32(float x) {
  uint32_t r; asm("cvt.rna.tf32.f32 %0, %1;" : "=r"(r) : "f"(x)); return r;
}
__device__ __forceinline__ uint32_t packh2(float lo, float hi) {
  __half2 h = __floats2half2_rn(lo, hi);
  return *reinterpret_cast<uint32_t*>(&h);
}
__device__ __forceinline__ void mma_tf32(float* c, const uint32_t* a, const uint32_t* b) {
  asm volatile("mma.sync.aligned.m16n8k8.row.col.f32.tf32.tf32.f32 "
               "{%0,%1,%2,%3}, {%4,%5,%6,%7}, {%8,%9}, {%0,%1,%2,%3};"
               : "+f"(c[0]), "+f"(c[1]), "+f"(c[2]), "+f"(c[3])
               : "r"(a[0]), "r"(a[1]), "r"(a[2]), "r"(a[3]), "r"(b[0]), "r"(b[1]));
}
__device__ __forceinline__ void mma_f16(float* c, const uint32_t* a, const uint32_t* b) {
  asm volatile("mma.sync.aligned.m16n8k16.row.col.f32.f16.f16.f32 "
               "{%0,%1,%2,%3}, {%4,%5,%6,%7}, {%8,%9}, {%0,%1,%2,%3};"
               : "+f"(c[0]), "+f"(c[1]), "+f"(c[2]), "+f"(c[3])
               : "r"(a[0]), "r"(a[1]), "r"(a[2]), "r"(a[3]), "r"(b[0]), "r"(b[1]));
}

#define LDA 132   /* padded stride (floats) for 128-wide smem tiles */

// ---------------- K0: weight -> fragment-order tf32 prep ------------------------
__global__ void k0_prep(const float* __restrict__ qw, const float* __restrict__ kw,
                        const float* __restrict__ vw, const float* __restrict__ gw,
                        const float* __restrict__ ow) {
  int kind = blockIdx.x >> 4, kk = blockIdx.x & 15;
  const float* W = (kind == 0) ? qw : (kind == 1) ? kw : (kind == 2) ? vw : (kind == 3) ? gw : ow;
  int t = threadIdx.x;
  int wn = t >> 7, j = (t >> 5) & 3, lane = t & 31;
  int qr = lane >> 2, qc = lane & 3;
  int col = wn * 32 + j * 8 + qr;
  int k0 = kk * 8;
  float2 v;
  v.x = __uint_as_float(f2tf32(W[(k0 + qc) * 128 + col]));
  v.y = __uint_as_float(f2tf32(W[(k0 + qc + 4) * 128 + col]));
  g_bf[kind][kk][wn][j][lane] = v;
}

// ---------------- K1: LayerNorm(affine) + nonbatched bias ------------------------
__global__ void k1_nb(const float* __restrict__ affine,
                      const float* __restrict__ als, const float* __restrict__ alo,
                      const float* __restrict__ f2d) {
  int row = blockIdx.x;
  int t = threadIdx.x, w = t >> 5, l = t & 31;
  __shared__ float sh[16];
  size_t base = (size_t)row * CZ + t;

  float a = affine[base];
  float s = a, s2 = a * a;
  #pragma unroll
  for (int o = 16; o; o >>= 1) { s += __shfl_xor_sync(~0u, s, o); s2 += __shfl_xor_sync(~0u, s2, o); }
  if (l == 0) { sh[w] = s; sh[4 + w] = s2; }
  __syncthreads();
  float sum  = sh[0] + sh[1] + sh[2] + sh[3];
  float sum2 = sh[4] + sh[5] + sh[6] + sh[7];
  float mean = sum * (1.f / CZ);
  float var  = sum2 * (1.f / CZ) - mean * mean;
  float aln = (a - mean) * rsqrtf(var + 1e-5f) * als[t] + alo[t];

  float p0 = aln * f2d[t * 4 + 0];
  float p1 = aln * f2d[t * 4 + 1];
  float p2 = aln * f2d[t * 4 + 2];
  float p3 = aln * f2d[t * 4 + 3];
  #pragma unroll
  for (int o = 16; o; o >>= 1) {
    p0 += __shfl_xor_sync(~0u, p0, o);
    p1 += __shfl_xor_sync(~0u, p1, o);
    p2 += __shfl_xor_sync(~0u, p2, o);
    p3 += __shfl_xor_sync(~0u, p3, o);
  }
  __syncthreads();
  if (l == 0) { sh[w*4+0] = p0; sh[w*4+1] = p1; sh[w*4+2] = p2; sh[w*4+3] = p3; }
  __syncthreads();
  if (t < 4) {
    g_nb[(size_t)t * NN + row] = sh[0*4+t] + sh[1*4+t] + sh[2*4+t] + sh[3*4+t];
  }
}

// ---------------- K2: fused pair-LN + all-4-kind QKVG projection ----------------
// mainloop tf32 (unchanged); epilogue packs fp16.
__global__ __launch_bounds__(256) void k2_mma(const float* __restrict__ pair,
                                              const float* __restrict__ pls,
                                              const float* __restrict__ plo) {
  extern __shared__ uint32_t sm2[];
  uint32_t* As = sm2;               // [64][LDA]
  float* Asf = (float*)As;

  int tid = threadIdx.x, wid = tid >> 5, lane = tid & 31;
  int wm = wid >> 2, wn = wid & 3;            // warp grid 2x4
  int qr = lane >> 2, qc = lane & 3;
  int rowBase = blockIdx.x * 64;

  #pragma unroll
  for (int i = 0; i < 8; i++) {
    int idx = tid + i * 256;
    int r = idx >> 5, f = idx & 31;
    float4 v = ((const float4*)(pair + (size_t)(rowBase + r) * CZ))[f];
    float* d = Asf + r * LDA + f * 4;
    d[0] = v.x; d[1] = v.y; d[2] = v.z; d[3] = v.w;
  }
  __syncthreads();

  float plsv[4], plov[4];
  #pragma unroll
  for (int m = 0; m < 4; m++) { plsv[m] = pls[lane + 32 * m]; plov[m] = plo[lane + 32 * m]; }
  for (int r = wid; r < 64; r += 8) {
    float x[4];
    float s = 0.f, s2 = 0.f;
    #pragma unroll
    for (int m = 0; m < 4; m++) {
      x[m] = Asf[r * LDA + lane + 32 * m];
      s += x[m]; s2 += x[m] * x[m];
    }
    #pragma unroll
    for (int o = 16; o; o >>= 1) { s += __shfl_xor_sync(~0u, s, o); s2 += __shfl_xor_sync(~0u, s2, o); }
    float mean = s * (1.f / CZ);
    float var  = s2 * (1.f / CZ) - mean * mean;
    float rstd = rsqrtf(var + 1e-5f);
    #pragma unroll
    for (int m = 0; m < 4; m++)
      As[r * LDA + lane + 32 * m] = f2tf32((x[m] - mean) * rstd * plsv[m] + plov[m]);
  }
  __syncthreads();

  for (int kind = 0; kind < 4; kind++) {
    float acc[2][4][4];
    #pragma unroll
    for (int i = 0; i < 2; i++)
      #pragma unroll
      for (int j = 0; j < 4; j++)
        #pragma unroll
        for (int e = 0; e < 4; e++) acc[i][j][e] = 0.f;

    #pragma unroll 4
    for (int kk = 0; kk < 16; kk++) {
      int k0 = kk * 8;
      uint32_t af[2][4];
      #pragma unroll
      for (int i = 0; i < 2; i++) {
        int row = wm * 32 + i * 16 + qr;
        af[i][0] = As[row * LDA + k0 + qc];
        af[i][1] = As[(row + 8) * LDA + k0 + qc];
        af[i][2] = As[row * LDA + k0 + qc + 4];
        af[i][3] = As[(row + 8) * LDA + k0 + qc + 4];
      }
      #pragma unroll
      for (int j = 0; j < 4; j++) {
        float2 b2 = g_bf[kind][kk][wn][j][lane];
        uint32_t bf[2] = { __float_as_uint(b2.x), __float_as_uint(b2.y) };
        #pragma unroll
        for (int i = 0; i < 2; i++)
          mma_tf32(acc[i][j], af[i], bf);
      }
    }

    int colBase = kind * 128;
    #pragma unroll
    for (int i = 0; i < 2; i++) {
      int row0 = rowBase + wm * 32 + i * 16 + qr;
      #pragma unroll
      for (int j = 0; j < 4; j++) {
        int col = colBase + wn * 32 + j * 8 + qc * 2;
        *(__half2*)(g_qkvg + (size_t)row0 * 512 + col)       = __floats2half2_rn(acc[i][j][0], acc[i][j][1]);
        *(__half2*)(g_qkvg + (size_t)(row0 + 8) * 512 + col) = __floats2half2_rn(acc[i][j][2], acc[i][j][3]);
      }
    }
  }
}

// ---------------- K3: register-flash attention, full fp16 MMA, 640 thr ----------
// QK and AV both m16n8k16 fp16 (10-bit mantissa == tf32; fp32 accum + fp32
// softmax stats). S/P never touch smem.
#define KT2_P 328
#define VS2_P 40
#define K3_KT2  0
#define K3_VS2  (16*KT2_P)                /* 5248 */
#define K3_BIAS (K3_VS2 + 160*VS2_P)      /* +6400 = 11648 */
#define K3_FLOATS (K3_BIAS + 320)         /* 11968 words = 47872 B */

__global__ __launch_bounds__(640, 1) void k3_attn(const float* __restrict__ mask) {
  extern __shared__ uint32_t sm3[];
  uint32_t* Kh2 = sm3 + K3_KT2;        // [16 c-pairs][328]: half2(K[key][2cp],K[key][2cp+1])
  uint32_t* Vs2 = sm3 + K3_VS2;        // [160 key-pairs][40]: half2(V[2kp][c], V[2kp+1][c])
  float*    bias_s = (float*)(sm3 + K3_BIAS);

  int h = blockIdx.x, b = blockIdx.y;
  int tid = threadIdx.x, wid = tid >> 5, lane = tid & 31;
  int qr = lane >> 2, qc = lane & 3;

  // ---- stage K (contiguous half2 pairs along c), V (pairs across keys), bias ----
  #pragma unroll 2
  for (int i = 0; i < 8; i++) {
    int e = tid + i * 640;               // 5120 = 320 keys x 16 c-pairs
    int cp = e & 15, key = e >> 4;
    Kh2[cp * KT2_P + key] =
      *(const uint32_t*)(g_qkvg + (size_t)(b * 320 + key) * 512 + h * 32 + 128 + 2 * cp);
  }
  #pragma unroll 2
  for (int i = 0; i < 8; i++) {
    int e = tid + i * 640;               // 5120 = 160 key-pairs x 32 c
    int kp = e >> 5, c = e & 31;
    size_t rb = (size_t)(b * 320 + 2 * kp) * 512 + h * 32 + 256 + c;
    Vs2[kp * VS2_P + c] = packh2(__half2float(g_qkvg[rb]), __half2float(g_qkvg[rb + 512]));
  }
  if (tid < 320) bias_s[tid] = 1e9f * (mask[b * 320 + tid] - 1.f);
  __syncthreads();

  const float scl = 0.17677669529663687f;
  int q0w = wid * 16;                                // this warp's 16 q-rows
  size_t rA = (size_t)(b * 320 + q0w + qr) * 512 + h * 32;
  const float* nbr0 = g_nb + (size_t)h * NN + (size_t)(q0w + qr) * 320;
  const float* nbr1 = nbr0 + 8 * 320;

  // ---- Q fragments (fp16 A-layout, straight uint32 loads of half pairs) ----
  uint32_t qf[2][4];
  #pragma unroll
  for (int cs = 0; cs < 2; cs++) {
    int c0 = cs * 16;
    qf[cs][0] = *(const uint32_t*)(g_qkvg + rA + c0 + 2 * qc);
    qf[cs][1] = *(const uint32_t*)(g_qkvg + rA + 8 * 512 + c0 + 2 * qc);
    qf[cs][2] = *(const uint32_t*)(g_qkvg + rA + c0 + 8 + 2 * qc);
    qf[cs][3] = *(const uint32_t*)(g_qkvg + rA + 8 * 512 + c0 + 8 + 2 * qc);
  }

  float o[4][4];
  #pragma unroll
  for (int jo = 0; jo < 4; jo++)
    #pragma unroll
    for (int e = 0; e < 4; e++) o[jo][e] = 0.f;
  float m0 = -3.0e38f, m1 = -3.0e38f, l0 = 0.f, l1 = 0.f;

  for (int ch = 0; ch < 5; ch++) {
    int kbase = ch * 64;

    // ---- S chunk = Q @ K^T (16 x 64), 8 n-tiles, fp16 k16 ----
    float s[8][4];
    #pragma unroll
    for (int j = 0; j < 8; j++)
      #pragma unroll
      for (int e = 0; e < 4; e++) s[j][e] = 0.f;

    #pragma unroll
    for (int cs = 0; cs < 2; cs++) {
      #pragma unroll
      for (int j = 0; j < 8; j++) {
        int col = kbase + j * 8 + qr;
        uint32_t bf[2] = { Kh2[(cs * 8 + qc) * KT2_P + col],
                           Kh2[(cs * 8 + qc + 4) * KT2_P + col] };
        mma_f16(s[j], qf[cs], bf);
      }
    }

    // ---- scale + bias + nb; chunk max ----
    float cmax0 = -3.0e38f, cmax1 = -3.0e38f;
    #pragma unroll
    for (int j = 0; j < 8; j++) {
      int kk = kbase + j * 8 + qc * 2;
      float2 n0 = *(const float2*)(nbr0 + kk);
      float2 n1 = *(const float2*)(nbr1 + kk);
      float b0 = bias_s[kk], b1 = bias_s[kk + 1];
      s[j][0] = s[j][0] * scl + b0 + n0.x;
      s[j][1] = s[j][1] * scl + b1 + n0.y;
      s[j][2] = s[j][2] * scl + b0 + n1.x;
      s[j][3] = s[j][3] * scl + b1 + n1.y;
      cmax0 = fmaxf(cmax0, fmaxf(s[j][0], s[j][1]));
      cmax1 = fmaxf(cmax1, fmaxf(s[j][2], s[j][3]));
    }
    cmax0 = fmaxf(cmax0, __shfl_xor_sync(~0u, cmax0, 1));
    cmax0 = fmaxf(cmax0, __shfl_xor_sync(~0u, cmax0, 2));
    cmax1 = fmaxf(cmax1, __shfl_xor_sync(~0u, cmax1, 1));
    cmax1 = fmaxf(cmax1, __shfl_xor_sync(~0u, cmax1, 2));

    // ---- online softmax update ----
    float mn0 = fmaxf(m0, cmax0), mn1 = fmaxf(m1, cmax1);
    float sc0 = __expf(m0 - mn0), sc1 = __expf(m1 - mn1);
    m0 = mn0; m1 = mn1;
    float ps0 = 0.f, ps1 = 0.f;
    #pragma unroll
    for (int j = 0; j < 8; j++) {
      s[j][0] = __expf(s[j][0] - mn0);
      s[j][1] = __expf(s[j][1] - mn0);
      s[j][2] = __expf(s[j][2] - mn1);
      s[j][3] = __expf(s[j][3] - mn1);
      ps0 += s[j][0] + s[j][1];
      ps1 += s[j][2] + s[j][3];
    }
    ps0 += __shfl_xor_sync(~0u, ps0, 1); ps0 += __shfl_xor_sync(~0u, ps0, 2);
    ps1 += __shfl_xor_sync(~0u, ps1, 1); ps1 += __shfl_xor_sync(~0u, ps1, 2);
    l0 = l0 * sc0 + ps0;
    l1 = l1 * sc1 + ps1;
    #pragma unroll
    for (int jo = 0; jo < 4; jo++) {
      o[jo][0] *= sc0; o[jo][1] *= sc0;
      o[jo][2] *= sc1; o[jo][3] *= sc1;
    }

    // ---- pack P to fp16 (A-layout == C-layout pairs) + AV fp16 k16 ----
    uint32_t ph[8][2];
    #pragma unroll
    for (int j = 0; j < 8; j++) {
      ph[j][0] = packh2(s[j][0], s[j][1]);
      ph[j][1] = packh2(s[j][2], s[j][3]);
    }
    #pragma unroll
    for (int ks = 0; ks < 4; ks++) {
      uint32_t af[4] = { ph[2*ks][0], ph[2*ks][1], ph[2*ks+1][0], ph[2*ks+1][1] };
      int kvp = (kbase >> 1) + ks * 8;
      #pragma unroll
      for (int jo = 0; jo < 4; jo++) {
        int col = jo * 8 + qr;
        uint32_t bf[2] = { Vs2[(kvp + qc) * VS2_P + col],
                           Vs2[(kvp + qc + 4) * VS2_P + col] };
        mma_f16(o[jo], af, bf);
      }
    }
  }

  // ---- normalize + store fp16 ----
  float inv0 = 1.f / l0, inv1 = 1.f / l1;
  size_t row = (size_t)(b * 320 + q0w + qr);
  #pragma unroll
  for (int jo = 0; jo < 4; jo++) {
    int col = h * 32 + jo * 8 + qc * 2;
    *(__half2*)(g_wa + row * 128 + col)       = __floats2half2_rn(o[jo][0] * inv0, o[jo][1] * inv0);
    *(__half2*)(g_wa + (row + 8) * 128 + col) = __floats2half2_rn(o[jo][2] * inv1, o[jo][3] * inv1);
  }
}

// ---------------- K4: gate*sigmoid fused + output proj (B frags from L2) --------
__global__ __launch_bounds__(256) void k4_mma(float* __restrict__ out) {
  extern __shared__ uint32_t sm4[];
  uint32_t* As = sm4;               // [64][LDA]

  int tid = threadIdx.x, wid = tid >> 5, lane = tid & 31;
  int wm = wid >> 2, wn = wid & 3;
  int qr = lane >> 2, qc = lane & 3;
  int rowBase = blockIdx.x * 64;

  #pragma unroll
  for (int i = 0; i < 4; i++) {
    int idx = tid + i * 256;                  // 1024 uint4 (8 halves each)
    int r = idx >> 4, f = idx & 15;
    int row = rowBase + r;
    uint4 av = *(const uint4*)(g_wa + (size_t)row * CZ + f * 8);
    uint4 gv = *(const uint4*)(g_qkvg + (size_t)row * 512 + 384 + f * 8);
    const __half2* ah = (const __half2*)&av;
    const __half2* gh = (const __half2*)&gv;
    uint32_t* d = As + r * LDA + f * 8;
    #pragma unroll
    for (int m = 0; m < 4; m++) {
      float2 a = __half22float2(ah[m]);
      float2 g = __half22float2(gh[m]);
      d[2*m]   = f2tf32(a.x * (1.f / (1.f + __expf(-g.x))));
      d[2*m+1] = f2tf32(a.y * (1.f / (1.f + __expf(-g.y))));
    }
  }
  __syncthreads();

  float acc[2][4][4];
  #pragma unroll
  for (int i = 0; i < 2; i++)
    #pragma unroll
    for (int j = 0; j < 4; j++)
      #pragma unroll
      for (int e = 0; e < 4; e++) acc[i][j][e] = 0.f;

  #pragma unroll 4
  for (int kk = 0; kk < 16; kk++) {
    int k0 = kk * 8;
    uint32_t af[2][4];
    #pragma unroll
    for (int i = 0; i < 2; i++) {
      int row = wm * 32 + i * 16 + qr;
      af[i][0] = As[row * LDA + k0 + qc];
      af[i][1] = As[(row + 8) * LDA + k0 + qc];
      af[i][2] = As[row * LDA + k0 + qc + 4];
      af[i][3] = As[(row + 8) * LDA + k0 + qc + 4];
    }
    #pragma unroll
    for (int j = 0; j < 4; j++) {
      float2 b2 = g_bf[4][kk][wn][j][lane];
      uint32_t bf[2] = { __float_as_uint(b2.x), __float_as_uint(b2.y) };
      #pragma unroll
      for (int i = 0; i < 2; i++)
        mma_tf32(acc[i][j], af[i], bf);
    }
  }

  #pragma unroll
  for (int i = 0; i < 2; i++) {
    int row0 = rowBase + wm * 32 + i * 16 + qr;
    #pragma unroll
    for (int j = 0; j < 4; j++) {
      int col = wn * 32 + j * 8 + qc * 2;
      *(float2*)(out + (size_t)row0 * CZ + col)       = make_float2(acc[i][j][0], acc[i][j][1]);
      *(float2*)(out + (size_t)(row0 + 8) * CZ + col) = make_float2(acc[i][j][2], acc[i][j][3]);
    }
  }
}

// ---------------- launch --------------------------------------------------------
extern "C" void kernel_launch(void* const* d_in, const int* in_sizes, int n_in,
                              void* d_out, int out_size) {
  const float* pair    = (const float*)d_in[0];
  const float* affine  = (const float*)d_in[1];
  const float* mask    = (const float*)d_in[2];
  const float* pls     = (const float*)d_in[3];
  const float* plo     = (const float*)d_in[4];
  const float* als     = (const float*)d_in[5];
  const float* alo     = (const float*)d_in[6];
  const float* f2d     = (const float*)d_in[7];
  const float* qw      = (const float*)d_in[8];
  const float* kw      = (const float*)d_in[9];
  const float* vw      = (const float*)d_in[10];
  const float* gw      = (const float*)d_in[11];
  const float* ow      = (const float*)d_in[12];
  float* out = (float*)d_out;

  const int a_smem  = 64 * LDA * 4;             // 33792 B -> 4 CTAs/SM
  const int k3_smem = K3_FLOATS * 4;            // 47872 B
  cudaFuncSetAttribute(k2_mma, cudaFuncAttributeMaxDynamicSharedMemorySize, a_smem);
  cudaFuncSetAttribute(k4_mma, cudaFuncAttributeMaxDynamicSharedMemorySize, a_smem);
  cudaFuncSetAttribute(k3_attn, cudaFuncAttributeMaxDynamicSharedMemorySize, k3_smem);

  k0_prep<<<80, 512>>>(qw, kw, vw, gw, ow);
  k1_nb<<<NN, 128>>>(affine, als, alo, f2d);
  k2_mma<<<NN / 64, 256, a_smem>>>(pair, pls, plo);
  k3_attn<<<dim3(NH, N_RES), 640, k3_smem>>>(mask);
  k4_mma<<<NN / 64, 256, a_smem>>>(out);
}

// round 13
// speedup vs baseline: 5.0026x; 1.2367x over previous
#include <cuda_runtime.h>
#include <cuda_fp16.h>
#include <cstdint>
#include <math.h>

#define N_RES 320
#define CZ 128
#define NH 4
#define HD 32
#define NN (N_RES*N_RES)   /* 102400 */
#define LOG2E 1.4426950408889634f

// ---------------- scratch (static device globals; no allocation) ----------------
__device__ __half g_qkvg[(size_t)NN*512];    // 104.9 MB : [row][kind*128 + h*32 + d], fp16
__device__ float  g_nb[(size_t)NH*NN];       // 1.6 MB   : [h][q*320+k], pre-scaled by log2(e)
__device__ __half g_wa[(size_t)NN*CZ];       // 26.2 MB  : weighted_avg, fp16
// fp16 fragment-ordered weights: [kind(5)][ks(8)][wn(4)][j(4)][lane(32)] uint2 (m16n8k16 B)
__device__ uint2 g_bh[5][8][4][4][32];       // 160 KB, L2-resident

__device__ __forceinline__ uint32_t packh2(float lo, float hi) {
  __half2 h = __floats2half2_rn(lo, hi);
  return *reinterpret_cast<uint32_t*>(&h);
}
__device__ __forceinline__ float fexp2(float x) {
  float r; asm("ex2.approx.f32 %0, %1;" : "=f"(r) : "f"(x)); return r;
}
__device__ __forceinline__ void mma_f16(float* c, const uint32_t* a, const uint32_t* b) {
  asm volatile("mma.sync.aligned.m16n8k16.row.col.f32.f16.f16.f32 "
               "{%0,%1,%2,%3}, {%4,%5,%6,%7}, {%8,%9}, {%0,%1,%2,%3};"
               : "+f"(c[0]), "+f"(c[1]), "+f"(c[2]), "+f"(c[3])
               : "r"(a[0]), "r"(a[1]), "r"(a[2]), "r"(a[3]), "r"(b[0]), "r"(b[1]));
}

#define LDH 68   /* half2-word stride for [64][64-pair] smem A tiles (bank-clean) */

// ---------------- K0: weight -> fp16 m16n8k16 B-fragment prep -------------------
// grid 40 = 5 kinds x 8 ksteps; 512 threads = wn(4) x j(4) x lane(32)
__global__ void k0_prep(const float* __restrict__ qw, const float* __restrict__ kw,
                        const float* __restrict__ vw, const float* __restrict__ gw,
                        const float* __restrict__ ow) {
  int kind = blockIdx.x >> 3, ks = blockIdx.x & 7;
  const float* W = (kind == 0) ? qw : (kind == 1) ? kw : (kind == 2) ? vw : (kind == 3) ? gw : ow;
  int t = threadIdx.x;
  int wn = t >> 7, j = (t >> 5) & 3, lane = t & 31;
  int qr = lane >> 2, qc = lane & 3;
  int col = wn * 32 + j * 8 + qr;
  int k0 = ks * 16;
  uint2 v;
  v.x = packh2(W[(k0 + 2 * qc) * 128 + col], W[(k0 + 2 * qc + 1) * 128 + col]);
  v.y = packh2(W[(k0 + 2 * qc + 8) * 128 + col], W[(k0 + 2 * qc + 9) * 128 + col]);
  g_bh[kind][ks][wn][j][lane] = v;
}

// ---------------- K1: LayerNorm(affine) + nonbatched bias (warp-per-row) --------
// grid 12800 x 256 threads; no smem, no block barriers. nb pre-scaled by log2(e).
__global__ __launch_bounds__(256) void k1_nb(const float* __restrict__ affine,
                                             const float* __restrict__ als,
                                             const float* __restrict__ alo,
                                             const float* __restrict__ f2d) {
  int w = threadIdx.x >> 5, l = threadIdx.x & 31;
  int row = blockIdx.x * 8 + w;
  const float* ar = affine + (size_t)row * CZ;

  float x[4];
  float s = 0.f, s2 = 0.f;
  #pragma unroll
  for (int m = 0; m < 4; m++) {
    x[m] = ar[l + 32 * m];
    s += x[m]; s2 += x[m] * x[m];
  }
  #pragma unroll
  for (int o = 16; o; o >>= 1) { s += __shfl_xor_sync(~0u, s, o); s2 += __shfl_xor_sync(~0u, s2, o); }
  float mean = s * (1.f / CZ);
  float var  = s2 * (1.f / CZ) - mean * mean;
  float rstd = rsqrtf(var + 1e-5f);

  float p0 = 0.f, p1 = 0.f, p2 = 0.f, p3 = 0.f;
  #pragma unroll
  for (int m = 0; m < 4; m++) {
    int c = l + 32 * m;
    float aln = (x[m] - mean) * rstd * als[c] + alo[c];
    p0 += aln * f2d[c * 4 + 0];
    p1 += aln * f2d[c * 4 + 1];
    p2 += aln * f2d[c * 4 + 2];
    p3 += aln * f2d[c * 4 + 3];
  }
  #pragma unroll
  for (int o = 16; o; o >>= 1) {
    p0 += __shfl_xor_sync(~0u, p0, o);
    p1 += __shfl_xor_sync(~0u, p1, o);
    p2 += __shfl_xor_sync(~0u, p2, o);
    p3 += __shfl_xor_sync(~0u, p3, o);
  }
  if (l == 0) {
    g_nb[(size_t)0 * NN + row] = p0 * LOG2E;
    g_nb[(size_t)1 * NN + row] = p1 * LOG2E;
    g_nb[(size_t)2 * NN + row] = p2 * LOG2E;
    g_nb[(size_t)3 * NN + row] = p3 * LOG2E;
  }
}

// ---------------- K2: fused pair-LN + all-4-kind QKVG projection (fp16 k16) -----
// grid 1600 (64-row tiles); 256 threads; smem = fp16 A tile only (17.4 KB).
__global__ __launch_bounds__(256) void k2_mma(const float* __restrict__ pair,
                                              const float* __restrict__ pls,
                                              const float* __restrict__ plo) {
  extern __shared__ uint32_t sm2[];
  uint32_t* Ash2 = sm2;             // [64][LDH] half2 words

  int tid = threadIdx.x, wid = tid >> 5, lane = tid & 31;
  int wm = wid >> 2, wn = wid & 3;            // warp grid 2x4
  int qr = lane >> 2, qc = lane & 3;
  int rowBase = blockIdx.x * 64;

  // warp-per-row LayerNorm from gmem; pack half2 via shfl_xor(1)
  float plsv[4], plov[4];
  #pragma unroll
  for (int m = 0; m < 4; m++) { plsv[m] = pls[lane + 32 * m]; plov[m] = plo[lane + 32 * m]; }
  for (int r = wid; r < 64; r += 8) {
    const float* pr = pair + (size_t)(rowBase + r) * CZ;
    float x[4];
    float s = 0.f, s2 = 0.f;
    #pragma unroll
    for (int m = 0; m < 4; m++) {
      x[m] = pr[lane + 32 * m];
      s += x[m]; s2 += x[m] * x[m];
    }
    #pragma unroll
    for (int o = 16; o; o >>= 1) { s += __shfl_xor_sync(~0u, s, o); s2 += __shfl_xor_sync(~0u, s2, o); }
    float mean = s * (1.f / CZ);
    float var  = s2 * (1.f / CZ) - mean * mean;
    float rstd = rsqrtf(var + 1e-5f);
    #pragma unroll
    for (int m = 0; m < 4; m++) {
      float y = (x[m] - mean) * rstd * plsv[m] + plov[m];
      float yp = __shfl_xor_sync(~0u, y, 1);
      if (!(lane & 1)) Ash2[r * LDH + 16 * m + (lane >> 1)] = packh2(y, yp);
    }
  }
  __syncthreads();

  for (int kind = 0; kind < 4; kind++) {
    float acc[2][4][4];
    #pragma unroll
    for (int i = 0; i < 2; i++)
      #pragma unroll
      for (int j = 0; j < 4; j++)
        #pragma unroll
        for (int e = 0; e < 4; e++) acc[i][j][e] = 0.f;

    #pragma unroll
    for (int ks = 0; ks < 8; ks++) {
      int kp0 = ks * 8;
      uint32_t af[2][4];
      #pragma unroll
      for (int i = 0; i < 2; i++) {
        int row = wm * 32 + i * 16 + qr;
        af[i][0] = Ash2[row * LDH + kp0 + qc];
        af[i][1] = Ash2[(row + 8) * LDH + kp0 + qc];
        af[i][2] = Ash2[row * LDH + kp0 + qc + 4];
        af[i][3] = Ash2[(row + 8) * LDH + kp0 + qc + 4];
      }
      #pragma unroll
      for (int j = 0; j < 4; j++) {
        uint2 b2 = g_bh[kind][ks][wn][j][lane];
        uint32_t bf[2] = { b2.x, b2.y };
        #pragma unroll
        for (int i = 0; i < 2; i++)
          mma_f16(acc[i][j], af[i], bf);
      }
    }

    int colBase = kind * 128;
    #pragma unroll
    for (int i = 0; i < 2; i++) {
      int row0 = rowBase + wm * 32 + i * 16 + qr;
      #pragma unroll
      for (int j = 0; j < 4; j++) {
        int col = colBase + wn * 32 + j * 8 + qc * 2;
        *(__half2*)(g_qkvg + (size_t)row0 * 512 + col)       = __floats2half2_rn(acc[i][j][0], acc[i][j][1]);
        *(__half2*)(g_qkvg + (size_t)(row0 + 8) * 512 + col) = __floats2half2_rn(acc[i][j][2], acc[i][j][3]);
      }
    }
  }
}

// ---------------- K3: register-flash attention, full fp16 MMA, exp2 domain ------
#define KT2_P 328
#define VS2_P 40
#define K3_KT2  0
#define K3_VS2  (16*KT2_P)                /* 5248 */
#define K3_BIAS (K3_VS2 + 160*VS2_P)      /* +6400 = 11648 */
#define K3_FLOATS (K3_BIAS + 320)         /* 11968 words = 47872 B */

__global__ __launch_bounds__(640, 1) void k3_attn(const float* __restrict__ mask) {
  extern __shared__ uint32_t sm3[];
  uint32_t* Kh2 = sm3 + K3_KT2;        // [16 c-pairs][328]
  uint32_t* Vs2 = sm3 + K3_VS2;        // [160 key-pairs][40]
  float*    bias_s = (float*)(sm3 + K3_BIAS);

  int h = blockIdx.x, b = blockIdx.y;
  int tid = threadIdx.x, wid = tid >> 5, lane = tid & 31;
  int qr = lane >> 2, qc = lane & 3;

  #pragma unroll 2
  for (int i = 0; i < 8; i++) {
    int e = tid + i * 640;
    int cp = e & 15, key = e >> 4;
    Kh2[cp * KT2_P + key] =
      *(const uint32_t*)(g_qkvg + (size_t)(b * 320 + key) * 512 + h * 32 + 128 + 2 * cp);
  }
  #pragma unroll 2
  for (int i = 0; i < 8; i++) {
    int e = tid + i * 640;
    int kp = e >> 5, c = e & 31;
    size_t rb = (size_t)(b * 320 + 2 * kp) * 512 + h * 32 + 256 + c;
    Vs2[kp * VS2_P + c] = packh2(__half2float(g_qkvg[rb]), __half2float(g_qkvg[rb + 512]));
  }
  if (tid < 320) bias_s[tid] = LOG2E * 1e9f * (mask[b * 320 + tid] - 1.f);
  __syncthreads();

  const float scl2 = 0.17677669529663687f * LOG2E;   // qk scale, log2 domain
  int q0w = wid * 16;
  size_t rA = (size_t)(b * 320 + q0w + qr) * 512 + h * 32;
  const float* nbr0 = g_nb + (size_t)h * NN + (size_t)(q0w + qr) * 320;   // pre-scaled
  const float* nbr1 = nbr0 + 8 * 320;

  uint32_t qf[2][4];
  #pragma unroll
  for (int cs = 0; cs < 2; cs++) {
    int c0 = cs * 16;
    qf[cs][0] = *(const uint32_t*)(g_qkvg + rA + c0 + 2 * qc);
    qf[cs][1] = *(const uint32_t*)(g_qkvg + rA + 8 * 512 + c0 + 2 * qc);
    qf[cs][2] = *(const uint32_t*)(g_qkvg + rA + c0 + 8 + 2 * qc);
    qf[cs][3] = *(const uint32_t*)(g_qkvg + rA + 8 * 512 + c0 + 8 + 2 * qc);
  }

  float o[4][4];
  #pragma unroll
  for (int jo = 0; jo < 4; jo++)
    #pragma unroll
    for (int e = 0; e < 4; e++) o[jo][e] = 0.f;
  float m0 = -3.0e38f, m1 = -3.0e38f, l0 = 0.f, l1 = 0.f;

  for (int ch = 0; ch < 5; ch++) {
    int kbase = ch * 64;

    float s[8][4];
    #pragma unroll
    for (int j = 0; j < 8; j++)
      #pragma unroll
      for (int e = 0; e < 4; e++) s[j][e] = 0.f;

    #pragma unroll
    for (int cs = 0; cs < 2; cs++) {
      #pragma unroll
      for (int j = 0; j < 8; j++) {
        int col = kbase + j * 8 + qr;
        uint32_t bf[2] = { Kh2[(cs * 8 + qc) * KT2_P + col],
                           Kh2[(cs * 8 + qc + 4) * KT2_P + col] };
        mma_f16(s[j], qf[cs], bf);
      }
    }

    float cmax0 = -3.0e38f, cmax1 = -3.0e38f;
    #pragma unroll
    for (int j = 0; j < 8; j++) {
      int kk = kbase + j * 8 + qc * 2;
      float2 n0 = *(const float2*)(nbr0 + kk);
      float2 n1 = *(const float2*)(nbr1 + kk);
      float b0 = bias_s[kk], b1 = bias_s[kk + 1];
      s[j][0] = s[j][0] * scl2 + b0 + n0.x;
      s[j][1] = s[j][1] * scl2 + b1 + n0.y;
      s[j][2] = s[j][2] * scl2 + b0 + n1.x;
      s[j][3] = s[j][3] * scl2 + b1 + n1.y;
      cmax0 = fmaxf(cmax0, fmaxf(s[j][0], s[j][1]));
      cmax1 = fmaxf(cmax1, fmaxf(s[j][2], s[j][3]));
    }
    cmax0 = fmaxf(cmax0, __shfl_xor_sync(~0u, cmax0, 1));
    cmax0 = fmaxf(cmax0, __shfl_xor_sync(~0u, cmax0, 2));
    cmax1 = fmaxf(cmax1, __shfl_xor_sync(~0u, cmax1, 1));
    cmax1 = fmaxf(cmax1, __shfl_xor_sync(~0u, cmax1, 2));

    float mn0 = fmaxf(m0, cmax0), mn1 = fmaxf(m1, cmax1);
    float sc0 = fexp2(m0 - mn0), sc1 = fexp2(m1 - mn1);
    m0 = mn0; m1 = mn1;
    float ps0 = 0.f, ps1 = 0.f;
    #pragma unroll
    for (int j = 0; j < 8; j++) {
      s[j][0] = fexp2(s[j][0] - mn0);
      s[j][1] = fexp2(s[j][1] - mn0);
      s[j][2] = fexp2(s[j][2] - mn1);
      s[j][3] = fexp2(s[j][3] - mn1);
      ps0 += s[j][0] + s[j][1];
      ps1 += s[j][2] + s[j][3];
    }
    ps0 += __shfl_xor_sync(~0u, ps0, 1); ps0 += __shfl_xor_sync(~0u, ps0, 2);
    ps1 += __shfl_xor_sync(~0u, ps1, 1); ps1 += __shfl_xor_sync(~0u, ps1, 2);
    l0 = l0 * sc0 + ps0;
    l1 = l1 * sc1 + ps1;
    #pragma unroll
    for (int jo = 0; jo < 4; jo++) {
      o[jo][0] *= sc0; o[jo][1] *= sc0;
      o[jo][2] *= sc1; o[jo][3] *= sc1;
    }

    uint32_t ph[8][2];
    #pragma unroll
    for (int j = 0; j < 8; j++) {
      ph[j][0] = packh2(s[j][0], s[j][1]);
      ph[j][1] = packh2(s[j][2], s[j][3]);
    }
    #pragma unroll
    for (int ks = 0; ks < 4; ks++) {
      uint32_t af[4] = { ph[2*ks][0], ph[2*ks][1], ph[2*ks+1][0], ph[2*ks+1][1] };
      int kvp = (kbase >> 1) + ks * 8;
      #pragma unroll
      for (int jo = 0; jo < 4; jo++) {
        int col = jo * 8 + qr;
        uint32_t bf[2] = { Vs2[(kvp + qc) * VS2_P + col],
                           Vs2[(kvp + qc + 4) * VS2_P + col] };
        mma_f16(o[jo], af, bf);
      }
    }
  }

  float inv0 = 1.f / l0, inv1 = 1.f / l1;
  size_t row = (size_t)(b * 320 + q0w + qr);
  #pragma unroll
  for (int jo = 0; jo < 4; jo++) {
    int col = h * 32 + jo * 8 + qc * 2;
    *(__half2*)(g_wa + row * 128 + col)       = __floats2half2_rn(o[jo][0] * inv0, o[jo][1] * inv0);
    *(__half2*)(g_wa + (row + 8) * 128 + col) = __floats2half2_rn(o[jo][2] * inv1, o[jo][3] * inv1);
  }
}

// ---------------- K4: gate*sigmoid fused + output proj (fp16 k16) ---------------
__global__ __launch_bounds__(256) void k4_mma(float* __restrict__ out) {
  extern __shared__ uint32_t sm4[];
  uint32_t* Ash2 = sm4;             // [64][LDH]

  int tid = threadIdx.x, wid = tid >> 5, lane = tid & 31;
  int wm = wid >> 2, wn = wid & 3;
  int qr = lane >> 2, qc = lane & 3;
  int rowBase = blockIdx.x * 64;

  #pragma unroll
  for (int i = 0; i < 4; i++) {
    int idx = tid + i * 256;                  // 1024 uint4 (8 halves each)
    int r = idx >> 4, f = idx & 15;
    int row = rowBase + r;
    uint4 av = *(const uint4*)(g_wa + (size_t)row * CZ + f * 8);
    uint4 gv = *(const uint4*)(g_qkvg + (size_t)row * 512 + 384 + f * 8);
    const __half2* ah = (const __half2*)&av;
    const __half2* gh = (const __half2*)&gv;
    uint32_t hw[4];
    #pragma unroll
    for (int m = 0; m < 4; m++) {
      float2 a = __half22float2(ah[m]);
      float2 g = __half22float2(gh[m]);
      hw[m] = packh2(a.x * (1.f / (1.f + __expf(-g.x))),
                     a.y * (1.f / (1.f + __expf(-g.y))));
    }
    *(uint4*)(Ash2 + r * LDH + f * 4) = *(const uint4*)hw;
  }
  __syncthreads();

  float acc[2][4][4];
  #pragma unroll
  for (int i = 0; i < 2; i++)
    #pragma unroll
    for (int j = 0; j < 4; j++)
      #pragma unroll
      for (int e = 0; e < 4; e++) acc[i][j][e] = 0.f;

  #pragma unroll
  for (int ks = 0; ks < 8; ks++) {
    int kp0 = ks * 8;
    uint32_t af[2][4];
    #pragma unroll
    for (int i = 0; i < 2; i++) {
      int row = wm * 32 + i * 16 + qr;
      af[i][0] = Ash2[row * LDH + kp0 + qc];
      af[i][1] = Ash2[(row + 8) * LDH + kp0 + qc];
      af[i][2] = Ash2[row * LDH + kp0 + qc + 4];
      af[i][3] = Ash2[(row + 8) * LDH + kp0 + qc + 4];
    }
    #pragma unroll
    for (int j = 0; j < 4; j++) {
      uint2 b2 = g_bh[4][ks][wn][j][lane];
      uint32_t bf[2] = { b2.x, b2.y };
      #pragma unroll
      for (int i = 0; i < 2; i++)
        mma_f16(acc[i][j], af[i], bf);
    }
  }

  #pragma unroll
  for (int i = 0; i < 2; i++) {
    int row0 = rowBase + wm * 32 + i * 16 + qr;
    #pragma unroll
    for (int j = 0; j < 4; j++) {
      int col = wn * 32 + j * 8 + qc * 2;
      *(float2*)(out + (size_t)row0 * CZ + col)       = make_float2(acc[i][j][0], acc[i][j][1]);
      *(float2*)(out + (size_t)(row0 + 8) * CZ + col) = make_float2(acc[i][j][2], acc[i][j][3]);
    }
  }
}

// ---------------- launch --------------------------------------------------------
extern "C" void kernel_launch(void* const* d_in, const int* in_sizes, int n_in,
                              void* d_out, int out_size) {
  const float* pair    = (const float*)d_in[0];
  const float* affine  = (const float*)d_in[1];
  const float* mask    = (const float*)d_in[2];
  const float* pls     = (const float*)d_in[3];
  const float* plo     = (const float*)d_in[4];
  const float* als     = (const float*)d_in[5];
  const float* alo     = (const float*)d_in[6];
  const float* f2d     = (const float*)d_in[7];
  const float* qw      = (const float*)d_in[8];
  const float* kw      = (const float*)d_in[9];
  const float* vw      = (const float*)d_in[10];
  const float* gw      = (const float*)d_in[11];
  const float* ow      = (const float*)d_in[12];
  float* out = (float*)d_out;

  const int a_smem  = 64 * LDH * 4;             // 17408 B
  const int k3_smem = K3_FLOATS * 4;            // 47872 B
  cudaFuncSetAttribute(k2_mma, cudaFuncAttributeMaxDynamicSharedMemorySize, a_smem);
  cudaFuncSetAttribute(k4_mma, cudaFuncAttributeMaxDynamicSharedMemorySize, a_smem);
  cudaFuncSetAttribute(k3_attn, cudaFuncAttributeMaxDynamicSharedMemorySize, k3_smem);

  k0_prep<<<40, 512>>>(qw, kw, vw, gw, ow);
  k1_nb<<<NN / 8, 256>>>(affine, als, alo, f2d);
  k2_mma<<<NN / 64, 256, a_smem>>>(pair, pls, plo);
  k3_attn<<<dim3(NH, N_RES), 640, k3_smem>>>(mask);
  k4_mma<<<NN / 64, 256, a_smem>>>(out);
}